// round 11
// baseline (speedup 1.0000x reference)
#include <cuda_runtime.h>
#include <cuda_fp16.h>

#define DIM 16
#define N_ATM 131072
#define N_BND 1048576
#define N_ANG 2097152
#define N_GRAPHS 256
#define PI_F 3.14159265358979323846f

// ---------------- scratch (device globals; zero-init; invariants restored each replay) ----
__device__ float    g_h_atm[N_ATM * DIM];
__device__ float    g_h_bnd[N_BND * DIM];
__device__ __half   g_h_ang[N_ANG * DIM];   // fp16 storage (post-LN, O(1) values)
__device__ unsigned g_accA[N_BND * DIM];    // half2(num,den); zeroed by edge_G
__device__ unsigned g_accG[N_ATM * DIM];    // half2(num,den); zeroed by node_G
__device__ unsigned g_bps[N_BND * DIM];     // bond src-proj half2(p0,p4)
__device__ __half   g_bpd[N_BND * DIM];     // bond dst-proj p1
__device__ __half   g_bp3[N_BND * DIM];     // bond self-proj p3 = x@W3 + b1
__device__ unsigned g_aps[N_ATM * DIM];     // atom src-proj half2(p0,p4)
__device__ __half   g_apd[N_ATM * DIM];     // atom dst-proj p1
__device__ __half   g_ap3[N_ATM * DIM];     // atom self-proj p3
__device__ float    g_pooled[N_GRAPHS * DIM];

// ---------------- helpers ----------------
__device__ __forceinline__ float sigmoidf_(float x) { return 1.0f / (1.0f + __expf(-x)); }
__device__ __forceinline__ float siluf_(float x)    { return x / (1.0f + __expf(-x)); }
__device__ __forceinline__ unsigned h2bits(__half2 h) { return *reinterpret_cast<unsigned*>(&h); }
__device__ __forceinline__ float2 h2f2(unsigned u) {
    return __half22float2(*reinterpret_cast<__half2*>(&u));
}

// ---- 16-lane helpers (encoders / node_G / edge_A_first) ----
__device__ __forceinline__ float ln16(float x, float g, float b) {
    float s = x, q = x * x;
    #pragma unroll
    for (int off = 8; off; off >>= 1) {
        s += __shfl_xor_sync(0xffffffffu, s, off);
        q += __shfl_xor_sync(0xffffffffu, q, off);
    }
    float mu  = s * (1.0f / 16.0f);
    float var = q * (1.0f / 16.0f) - mu * mu;
    return (x - mu) * rsqrtf(var + 1e-5f) * g + b;
}

struct Slot { int j, grp, lane, slot, stride; };
__device__ __forceinline__ Slot make_slot() {
    Slot s;
    int t = blockIdx.x * blockDim.x + threadIdx.x;
    s.lane = t & 31;
    s.j = s.lane & 15;
    s.grp = s.lane & 16;
    s.slot = ((t >> 5) << 1) + (s.grp >> 4);
    s.stride = ((gridDim.x * blockDim.x) >> 5) << 1;
    return s;
}

__device__ __forceinline__ void red_quad(unsigned* base, int node, const Slot& s,
                                         float num, float den) {
    __half2 h = __floats2half2_rn(num, den);
    unsigned v = h2bits(h);
    int b = s.lane & ~3;
    unsigned v0 = __shfl_sync(0xffffffffu, v, b);
    unsigned v1 = __shfl_sync(0xffffffffu, v, b | 1);
    unsigned v2 = __shfl_sync(0xffffffffu, v, b | 2);
    unsigned v3 = __shfl_sync(0xffffffffu, v, b | 3);
    if ((s.lane & 3) == 0) {
        unsigned* p = base + (size_t)node * 16 + s.j;
        asm volatile("red.global.add.noftz.v4.f16x2 [%0], {%1, %2, %3, %4};"
                     :: "l"(p), "r"(v0), "r"(v1), "r"(v2), "r"(v3) : "memory");
    }
}

// ---- 8-lane helpers (edge_A conv1/2, edge_G): 2 channels per lane ----
struct Slot8 { int jj, g8, slot, stride; };
__device__ __forceinline__ Slot8 make_slot8() {
    Slot8 s;
    int t = blockIdx.x * blockDim.x + threadIdx.x;
    int lane = t & 31;
    s.jj = lane & 7;
    s.g8 = lane & 24;
    s.slot = ((t >> 5) << 2) + (lane >> 3);
    s.stride = ((gridDim.x * blockDim.x) >> 5) << 2;
    return s;
}

// LayerNorm over 16 channels held as pairs across 8 lanes
__device__ __forceinline__ float2 ln8pair(float x0, float x1, float g0, float g1,
                                          float b0, float b1) {
    float s = x0 + x1, q = x0 * x0 + x1 * x1;
    #pragma unroll
    for (int off = 4; off; off >>= 1) {
        s += __shfl_xor_sync(0xffffffffu, s, off);
        q += __shfl_xor_sync(0xffffffffu, q, off);
    }
    float mu  = s * (1.0f / 16.0f);
    float var = q * (1.0f / 16.0f) - mu * mu;
    float r = rsqrtf(var + 1e-5f);
    return make_float2((x0 - mu) * r * g0 + b0, (x1 - mu) * r * g1 + b1);
}

// pair-lane vector reduction: lane owns 2 channels (2 words); even jj issues 16B RED
__device__ __forceinline__ void red_pair8(unsigned* base, int node, int jj,
                                          unsigned a0, unsigned a1) {
    unsigned b0 = __shfl_xor_sync(0xffffffffu, a0, 1);
    unsigned b1 = __shfl_xor_sync(0xffffffffu, a1, 1);
    if ((jj & 1) == 0) {
        unsigned* p = base + (size_t)node * 16 + 2 * jj;
        asm volatile("red.global.add.noftz.v4.f16x2 [%0], {%1, %2, %3, %4};"
                     :: "l"(p), "r"(a0), "r"(a1), "r"(b0), "r"(b1) : "memory");
    }
}

// 4-matvec weight pack, float4-interleaved:
// sw[(k*16+j)*4 + m] with m: 0=W0, 1=W1, 2=W4, 3=W3  (float4 per (k,j))
// sw[1024..1039] = b0, sw[1040..1055] = b1
#define WPACK 1056
__device__ __forceinline__ void load_wproj(float* sw, const float* W, const float* b) {
    for (int i = threadIdx.x; i < WPACK; i += blockDim.x) {
        if (i < 1024) {
            int kj = i >> 2, m = i & 3;
            int mm = (m == 0) ? 0 : (m == 1) ? 1 : (m == 2) ? 4 : 3;
            sw[i] = W[mm * 256 + kj];
        }
        else if (i < 1040) sw[i] = b[i - 1024];
        else               sw[i] = b[16 + (i - 1040)];
    }
    __syncthreads();
}

// 16-lane projection (encoders, node_G): one LDS.128 per k
__device__ __forceinline__ void proj_store(float v, const Slot& s, const float* sw,
                                           unsigned* dst_s, __half* dst_d, __half* dst_3,
                                           int i) {
    float p0 = sw[1024 + s.j], p1 = 0.0f, p4 = 0.0f, p3 = sw[1040 + s.j];
    #pragma unroll
    for (int k = 0; k < 16; k++) {
        float a = __shfl_sync(0xffffffffu, v, s.grp | k);
        float4 w = *(const float4*)&sw[(k * 16 + s.j) * 4];
        p0 += a * w.x;
        p1 += a * w.y;
        p4 += a * w.z;
        p3 += a * w.w;
    }
    dst_s[(size_t)i * 16 + s.j] = h2bits(__floats2half2_rn(p0, p4));
    dst_d[(size_t)i * 16 + s.j] = __float2half_rn(p1);
    dst_3[(size_t)i * 16 + s.j] = __float2half_rn(p3);
}

// 8-lane projection (edge_G): 4 LDS.128 per t
__device__ __forceinline__ void proj_store8(float v0, float v1, const Slot8& s,
                                            const float* sw, unsigned* dst_s,
                                            __half* dst_d, __half* dst_3, int i) {
    int j0 = 2 * s.jj;
    float2 bb0 = *(const float2*)&sw[1024 + j0];
    float2 bb1 = *(const float2*)&sw[1040 + j0];
    float p0a = bb0.x, p0b = bb0.y, p1a = 0.f, p1b = 0.f;
    float p4a = 0.f, p4b = 0.f, p3a = bb1.x, p3b = bb1.y;
    #pragma unroll
    for (int t = 0; t < 8; t++) {
        float e0 = __shfl_sync(0xffffffffu, v0, s.g8 | t);
        float e1 = __shfl_sync(0xffffffffu, v1, s.g8 | t);
        int k0 = 2 * t, k1 = 2 * t + 1;
        float4 wA0 = *(const float4*)&sw[(k0 * 16 + j0) * 4];
        float4 wA1 = *(const float4*)&sw[(k0 * 16 + j0 + 1) * 4];
        float4 wB0 = *(const float4*)&sw[(k1 * 16 + j0) * 4];
        float4 wB1 = *(const float4*)&sw[(k1 * 16 + j0 + 1) * 4];
        p0a += e0 * wA0.x + e1 * wB0.x;  p0b += e0 * wA1.x + e1 * wB1.x;
        p1a += e0 * wA0.y + e1 * wB0.y;  p1b += e0 * wA1.y + e1 * wB1.y;
        p4a += e0 * wA0.z + e1 * wB0.z;  p4b += e0 * wA1.z + e1 * wB1.z;
        p3a += e0 * wA0.w + e1 * wB0.w;  p3b += e0 * wA1.w + e1 * wB1.w;
    }
    uint2 ps;
    ps.x = h2bits(__floats2half2_rn(p0a, p4a));
    ps.y = h2bits(__floats2half2_rn(p0b, p4b));
    *(uint2*)(dst_s + (size_t)i * 16 + j0) = ps;
    *(unsigned*)(&dst_d[(size_t)i * 16 + j0]) = h2bits(__floats2half2_rn(p1a, p1b));
    *(unsigned*)(&dst_3[(size_t)i * 16 + j0]) = h2bits(__floats2half2_rn(p3a, p3b));
}

// build 8-lane W2 pack: sw2q[t*8+jj] = (W2[2t][2jj], W2[2t][2jj+1], W2[2t+1][2jj], W2[2t+1][2jj+1])
__device__ __forceinline__ void load_w2q(float4* sw2q, const float* W2) {
    for (int i = threadIdx.x; i < 64; i += blockDim.x) {
        int t = i >> 3, jj = i & 7;
        sw2q[i] = make_float4(W2[(2 * t) * 16 + 2 * jj],     W2[(2 * t) * 16 + 2 * jj + 1],
                              W2[(2 * t + 1) * 16 + 2 * jj], W2[(2 * t + 1) * 16 + 2 * jj + 1]);
    }
}

// 16-lane edge-A body (used only by k_edge_A_first)
__device__ __forceinline__ void edgeA_core(int ed, int si, int di, float ev,
                                           const float* w2c, float ge, float be,
                                           const Slot& s, bool write_e) {
    float2 pf = h2f2(g_bps[(size_t)si * 16 + s.j]);
    float p1 = __half2float(g_bpd[(size_t)di * 16 + s.j]);
    float z = pf.x + p1;
    #pragma unroll
    for (int k = 0; k < 16; k++)
        z += __shfl_sync(0xffffffffu, ev, s.grp | k) * w2c[k];
    float sig = sigmoidf_(z);
    red_quad(g_accA, di, s, sig * pf.y, sig);
    if (write_e)
        g_h_ang[(size_t)ed * 16 + s.j] = __float2half_rn(ev + siluf_(ln16(z, ge, be)));
}

// ---------------- encoders (fused with first-conv projections) ----------------
__global__ void __launch_bounds__(256) k_enc_atm(
        const int* __restrict__ xatm,
        const float* __restrict__ W1, const float* __restrict__ b1,
        const float* __restrict__ W2, const float* __restrict__ b2,
        const float* __restrict__ lg, const float* __restrict__ lb,
        const float* __restrict__ Wg0, const float* __restrict__ bg0) {
    __shared__ __align__(16) float sw[WPACK];
    load_wproj(sw, Wg0, bg0);
    Slot s = make_slot();
    float w2c[16];
    #pragma unroll
    for (int k = 0; k < 16; k++) w2c[k] = W2[k * 16 + s.j];
    float b1j = b1[s.j], b2j = b2[s.j], gj = lg[s.j], bj = lb[s.j];
    for (int a = s.slot; a < N_ATM; a += s.stride) {
        int sp = xatm[a];
        float h = siluf_(W1[sp * 16 + s.j] + b1j);
        float z = b2j;
        #pragma unroll
        for (int k = 0; k < 16; k++)
            z += __shfl_sync(0xffffffffu, h, s.grp | k) * w2c[k];
        float v = ln16(z, gj, bj);
        g_h_atm[a * 16 + s.j] = v;
        proj_store(v, s, sw, g_aps, g_apd, g_ap3, a);
    }
}

__global__ void __launch_bounds__(256) k_enc_bnd(
        const float* __restrict__ xb,
        const float* __restrict__ W1, const float* __restrict__ b1,
        const float* __restrict__ W2, const float* __restrict__ b2,
        const float* __restrict__ lg, const float* __restrict__ lb,
        const float* __restrict__ Wa0, const float* __restrict__ ba0) {
    __shared__ __align__(16) float sw[WPACK];
    load_wproj(sw, Wa0, ba0);
    Slot s = make_slot();
    float w1c[16], w2c[16];
    #pragma unroll
    for (int k = 0; k < 16; k++) { w1c[k] = W1[k * 16 + s.j]; w2c[k] = W2[k * 16 + s.j]; }
    float b1j = b1[s.j], b2j = b2[s.j], gj = lg[s.j], bj = lb[s.j];
    const float nrm = sqrtf(2.0f / 5.0f);
    for (int e = s.slot; e < N_BND; e += s.stride) {
        float xx = xb[e] + 1e-5f;
        float f = nrm * sinf((float)(s.j + 1) * PI_F * xx * (1.0f / 5.0f)) / xx;
        float h = b1j;
        #pragma unroll
        for (int k = 0; k < 16; k++)
            h += __shfl_sync(0xffffffffu, f, s.grp | k) * w1c[k];
        h = siluf_(h);
        float z = b2j;
        #pragma unroll
        for (int k = 0; k < 16; k++)
            z += __shfl_sync(0xffffffffu, h, s.grp | k) * w2c[k];
        float v = ln16(z, gj, bj);
        g_h_bnd[e * 16 + s.j] = v;
        proj_store(v, s, sw, g_bps, g_bpd, g_bp3, e);
    }
}

// ---------------- A-graph edge phase, conv 0: fused angle encoder (16-lane) ----
__global__ void __launch_bounds__(256) k_edge_A_first(
        const int* __restrict__ src, const int* __restrict__ dst,
        const float* __restrict__ xang, const int* __restrict__ mask,
        const float* __restrict__ W1, const float* __restrict__ b1,
        const float* __restrict__ W2, const float* __restrict__ b2,
        const float* __restrict__ lg, const float* __restrict__ lb,
        const float* __restrict__ W, const float* __restrict__ ln) {
    __shared__ float sw[1152];
    for (int i = threadIdx.x; i < 1152; i += blockDim.x) {
        if (i < 512)       sw[i] = W1[512 + i];           // sets 2,3 of W1
        else if (i < 1024) sw[i] = W2[i];                 // sets 2,3 of W2
        else {
            int idx = i - 1024, gsel = idx >> 4, j = idx & 15;
            const float* tbl[8] = { b1 + 32, b1 + 48, b2 + 32, b2 + 48,
                                    lg + 32, lg + 48, lb + 32, lb + 48 };
            sw[i] = tbl[gsel][j];
        }
    }
    __syncthreads();
    Slot s = make_slot();
    float w2c[16];
    #pragma unroll
    for (int k = 0; k < 16; k++) w2c[k] = W[2 * 256 + k * 16 + s.j];
    float ge = ln[32 + s.j], be = ln[48 + s.j];
    const float cb = (float)s.j * (PI_F / 15.0f);
    const float cd = -PI_F + (float)s.j * (2.0f * PI_F / 15.0f);
    const float* sv = sw + 1024;
    for (int ed = s.slot; ed < N_ANG; ed += s.stride) {
        int si = src[ed], di = dst[ed];
        float x = xang[ed];
        bool m = mask[ed] != 0;
        int o = m ? 256 : 0, o16 = m ? 16 : 0;
        float gam = m ? (7.5f / PI_F) : (15.0f / PI_F);
        float t = gam * (x - (m ? cd : cb));
        float f = __expf(-t * t);
        const float* w1p = sw + o;
        const float* w2p = sw + 512 + o;
        float h = sv[o16 + s.j];
        #pragma unroll
        for (int k = 0; k < 16; k++)
            h += __shfl_sync(0xffffffffu, f, s.grp | k) * w1p[k * 16 + s.j];
        h = siluf_(h);
        float z2 = sv[32 + o16 + s.j];
        #pragma unroll
        for (int k = 0; k < 16; k++)
            z2 += __shfl_sync(0xffffffffu, h, s.grp | k) * w2p[k * 16 + s.j];
        float ev = ln16(z2, sv[64 + o16 + s.j], sv[96 + o16 + s.j]);
        edgeA_core(ed, si, di, ev, w2c, ge, be, s, true);
    }
}

// ---------------- A-graph edge phase, conv 1/2 (8-lane; W2 float4 pack) ----------
__global__ void __launch_bounds__(256) k_edge_A(
        const int* __restrict__ src, const int* __restrict__ dst,
        const float* __restrict__ W, const float* __restrict__ ln, int write_e) {
    __shared__ float4 sw2q[64];
    load_w2q(sw2q, W + 512);
    __syncthreads();
    Slot8 s = make_slot8();
    int j0 = 2 * s.jj;
    float ge0 = ln[32 + j0], ge1 = ln[33 + j0], be0 = ln[48 + j0], be1 = ln[49 + j0];
    for (int ed = s.slot; ed < N_ANG; ed += s.stride) {
        int si = src[ed], di = dst[ed];
        unsigned evu = *(const unsigned*)(&g_h_ang[(size_t)ed * 16 + j0]);
        uint2 pv = *(const uint2*)(g_bps + (size_t)si * 16 + j0);
        unsigned pdu = *(const unsigned*)(&g_bpd[(size_t)di * 16 + j0]);
        float2 pa = h2f2(pv.x), pb = h2f2(pv.y), p1 = h2f2(pdu);
        float z0 = pa.x + p1.x, z1 = pb.x + p1.y;
        #pragma unroll
        for (int t = 0; t < 8; t++) {
            unsigned eu = __shfl_sync(0xffffffffu, evu, s.g8 | t);
            float2 e = h2f2(eu);
            float4 w = sw2q[t * 8 + s.jj];
            z0 += e.x * w.x + e.y * w.z;
            z1 += e.x * w.y + e.y * w.w;
        }
        float sig0 = sigmoidf_(z0), sig1 = sigmoidf_(z1);
        red_pair8(g_accA, di, s.jj,
                  h2bits(__floats2half2_rn(sig0 * pa.y, sig0)),
                  h2bits(__floats2half2_rn(sig1 * pb.y, sig1)));
        if (write_e) {
            float2 evf = h2f2(evu);
            float2 l = ln8pair(z0, z1, ge0, ge1, be0, be1);
            __half2 out = __floats2half2_rn(evf.x + siluf_(l.x), evf.y + siluf_(l.y));
            *(unsigned*)(&g_h_ang[(size_t)ed * 16 + j0]) = h2bits(out);
        }
    }
}

// ---------------- G-graph edge phase with fused A-node update (8-lane) ----------
__global__ void __launch_bounds__(256) k_edge_G(
        const int* __restrict__ src, const int* __restrict__ dst,
        const float* __restrict__ Wg, const float* __restrict__ lnG,
        const float* __restrict__ lnA,
        const float* __restrict__ Wnext, const float* __restrict__ bnext) {
    __shared__ __align__(16) float sw[WPACK];
    __shared__ float4 sw2q[64];
    bool has_next = (Wnext != nullptr);
    load_w2q(sw2q, Wg + 512);
    if (has_next) {
        load_wproj(sw, Wnext, bnext);   // includes __syncthreads()
    } else {
        __syncthreads();
    }
    Slot8 s = make_slot8();
    int j0 = 2 * s.jj;
    float ge0 = lnG[32 + j0], ge1 = lnG[33 + j0], be0 = lnG[48 + j0], be1 = lnG[49 + j0];
    float gn0 = lnA[j0], gn1 = lnA[j0 + 1], bn0 = lnA[16 + j0], bn1 = lnA[17 + j0];
    for (int ed = s.slot; ed < N_BND; ed += s.stride) {
        int si = src[ed], di = dst[ed];
        // --- fused A-node update for bond ed ---
        uint2 au = *(const uint2*)(g_accA + (size_t)ed * 16 + j0);
        float2 a0 = h2f2(au.x), a1 = h2f2(au.y);
        float2 p3 = h2f2(*(const unsigned*)(&g_bp3[(size_t)ed * 16 + j0]));
        float u0 = p3.x + a0.x / (a0.y + 1e-5f);
        float u1 = p3.y + a1.x / (a1.y + 1e-5f);
        float2 xv = *(const float2*)(g_h_bnd + (size_t)ed * 16 + j0);
        float2 l = ln8pair(u0, u1, gn0, gn1, bn0, bn1);
        float ev0 = xv.x + siluf_(l.x), ev1 = xv.y + siluf_(l.y);
        *(uint2*)(g_accA + (size_t)ed * 16 + j0) = make_uint2(0u, 0u);
        // --- G edge ---
        uint2 pv = *(const uint2*)(g_aps + (size_t)si * 16 + j0);
        unsigned pdu = *(const unsigned*)(&g_apd[(size_t)di * 16 + j0]);
        float2 pa = h2f2(pv.x), pb = h2f2(pv.y), p1 = h2f2(pdu);
        float z0 = pa.x + p1.x, z1 = pb.x + p1.y;
        #pragma unroll
        for (int t = 0; t < 8; t++) {
            float e0 = __shfl_sync(0xffffffffu, ev0, s.g8 | t);
            float e1 = __shfl_sync(0xffffffffu, ev1, s.g8 | t);
            float4 w = sw2q[t * 8 + s.jj];
            z0 += e0 * w.x + e1 * w.z;
            z1 += e0 * w.y + e1 * w.w;
        }
        float sig0 = sigmoidf_(z0), sig1 = sigmoidf_(z1);
        red_pair8(g_accG, di, s.jj,
                  h2bits(__floats2half2_rn(sig0 * pa.y, sig0)),
                  h2bits(__floats2half2_rn(sig1 * pb.y, sig1)));
        if (has_next) {
            float2 le = ln8pair(z0, z1, ge0, ge1, be0, be1);
            float en0 = ev0 + siluf_(le.x), en1 = ev1 + siluf_(le.y);
            *(float2*)(g_h_bnd + (size_t)ed * 16 + j0) = make_float2(en0, en1);
            proj_store8(en0, en1, s, sw, g_bps, g_bpd, g_bp3, ed);
        }
    }
}

// ---------------- G-graph node phase (16-lane; zero accG; next-G proj; pool) ----
__global__ void __launch_bounds__(256) k_node_G(
        const float* __restrict__ ln,
        const float* __restrict__ Wnext, const float* __restrict__ bnext,
        const int* __restrict__ batch, int is_last) {
    __shared__ __align__(16) float sw[WPACK];
    bool has_next = (Wnext != nullptr);
    if (has_next) load_wproj(sw, Wnext, bnext);
    Slot s = make_slot();
    float gn = ln[s.j], bn = ln[16 + s.j];
    for (int i = s.slot; i < N_ATM; i += s.stride) {
        float2 ah = h2f2(g_accG[(size_t)i * 16 + s.j]);
        float xv = g_h_atm[(size_t)i * 16 + s.j];
        float u = __half2float(g_ap3[(size_t)i * 16 + s.j]) + ah.x / (ah.y + 1e-5f);
        float xn = xv + siluf_(ln16(u, gn, bn));
        g_accG[(size_t)i * 16 + s.j] = 0u;
        if (is_last) {
            atomicAdd(&g_pooled[batch[i] * 16 + s.j], xn);
        } else {
            g_h_atm[(size_t)i * 16 + s.j] = xn;
            proj_store(xn, s, sw, g_aps, g_apd, g_ap3, i);
        }
    }
}

// ---------------- head (also re-zeroes pooled for next replay) ----------------
__global__ void k_head(const float* __restrict__ fp,
                       const float* __restrict__ l1W, const float* __restrict__ l1b,
                       const float* __restrict__ l2W, const float* __restrict__ l2b,
                       float* __restrict__ out) {
    int g = threadIdx.x;  // one block of 256
    float p[16];
    #pragma unroll
    for (int i = 0; i < 16; i++) p[i] = g_pooled[g * 16 + i];
    float f0 = fp[2 * g], f1 = fp[2 * g + 1];
    float acc = l2b[0];
    #pragma unroll
    for (int jo = 0; jo < 16; jo++) {
        float h = l1b[jo];
        #pragma unroll
        for (int i = 0; i < 16; i++) h += p[i] * l1W[i * 16 + jo];
        h += f0 * l1W[16 * 16 + jo] + f1 * l1W[17 * 16 + jo];
        h = (h > 0.0f) ? h : 0.01f * h;
        acc += h * l2W[jo];
    }
    out[g] = acc;
    #pragma unroll
    for (int i = 0; i < 16; i++) g_pooled[g * 16 + i] = 0.0f;
}

// ---------------- launch ----------------
extern "C" void kernel_launch(void* const* d_in, const int* in_sizes, int n_in,
                              void* d_out, int out_size) {
    const int*   x_atm = (const int*)d_in[0];
    const float* x_bnd = (const float*)d_in[1];
    const float* x_ang = (const float*)d_in[2];
    const int*   mask  = (const int*)d_in[3];
    const int*   eG    = (const int*)d_in[4];
    const int*   eA    = (const int*)d_in[5];
    const int*   batch = (const int*)d_in[6];
    const float* fp    = (const float*)d_in[7];
    const float* W1    = (const float*)d_in[8];
    const float* b1    = (const float*)d_in[9];
    const float* W2    = (const float*)d_in[10];
    const float* b2    = (const float*)d_in[11];
    const float* lg    = (const float*)d_in[12];
    const float* lb    = (const float*)d_in[13];
    const float* cW    = (const float*)d_in[14];  // [3,2,5,16,16]
    const float* cb    = (const float*)d_in[15];  // [3,2,2,16]
    const float* cln   = (const float*)d_in[16];  // [3,2,2,2,16]
    const float* l1W   = (const float*)d_in[17];
    const float* l1b   = (const float*)d_in[18];
    const float* l2W   = (const float*)d_in[19];
    const float* l2b   = (const float*)d_in[20];
    float* out = (float*)d_out;

    #define WA(c)  (cW  + ((c) * 2 + 0) * 5 * 256)
    #define BA(c)  (cb  + ((c) * 2 + 0) * 32)
    #define LNA(c) (cln + ((c) * 2 + 0) * 64)
    #define WG(c)  (cW  + ((c) * 2 + 1) * 5 * 256)
    #define BG(c)  (cb  + ((c) * 2 + 1) * 32)
    #define LNG(c) (cln + ((c) * 2 + 1) * 64)

    k_enc_atm<<<512, 256>>>(x_atm, W1 + 0 * 256, b1 + 0 * 16, W2 + 0 * 256, b2 + 0 * 16,
                            lg + 0 * 16, lb + 0 * 16, WG(0), BG(0));
    k_enc_bnd<<<2048, 256>>>(x_bnd, W1 + 1 * 256, b1 + 1 * 16, W2 + 1 * 256, b2 + 1 * 16,
                             lg + 1 * 16, lb + 1 * 16, WA(0), BA(0));

    for (int c = 0; c < 3; c++) {
        if (c == 0) {
            k_edge_A_first<<<8192, 256>>>(eA, eA + N_ANG, x_ang, mask,
                                          W1, b1, W2, b2, lg, lb, WA(0), LNA(0));
        } else {
            k_edge_A<<<8192, 256>>>(eA, eA + N_ANG, WA(c), LNA(c), (c < 2) ? 1 : 0);
        }

        const float* WnA = (c < 2) ? WA(c + 1) : nullptr;
        const float* bnA = (c < 2) ? BA(c + 1) : nullptr;
        k_edge_G<<<8192, 256>>>(eG, eG + N_BND, WG(c), LNG(c), LNA(c), WnA, bnA);

        const float* WnG = (c < 2) ? WG(c + 1) : nullptr;
        const float* bnG = (c < 2) ? BG(c + 1) : nullptr;
        k_node_G<<<512, 256>>>(LNG(c), WnG, bnG, batch, (c == 2) ? 1 : 0);
    }

    k_head<<<1, 256>>>(fp, l1W, l1b, l2W, l2b, out);
}

// round 12
// speedup vs baseline: 1.1232x; 1.1232x over previous
#include <cuda_runtime.h>
#include <cuda_fp16.h>

#define DIM 16
#define N_ATM 131072
#define N_BND 1048576
#define N_ANG 2097152
#define N_GRAPHS 256
#define PI_F 3.14159265358979323846f

// ---------------- scratch (device globals; zero-init; invariants restored each replay) ----
__device__ float    g_h_atm[N_ATM * DIM];
__device__ float    g_h_bnd[N_BND * DIM];
__device__ __half   g_h_ang[N_ANG * DIM];   // fp16 storage (post-LN, O(1) values)
__device__ unsigned g_accA[N_BND * DIM];    // half2(num,den); zeroed by edge_G
__device__ unsigned g_accG[N_ATM * DIM];    // half2(num,den); zeroed by node_G
__device__ unsigned g_bps[N_BND * DIM];     // bond src-proj half2(p0,p4)
__device__ __half   g_bpd[N_BND * DIM];     // bond dst-proj p1
__device__ __half   g_bp3[N_BND * DIM];     // bond self-proj p3 = x@W3 + b1
__device__ unsigned g_aps[N_ATM * DIM];     // atom src-proj half2(p0,p4)
__device__ __half   g_apd[N_ATM * DIM];     // atom dst-proj p1
__device__ __half   g_ap3[N_ATM * DIM];     // atom self-proj p3
__device__ float    g_pooled[N_GRAPHS * DIM];

// ---------------- helpers ----------------
__device__ __forceinline__ float sigmoidf_(float x) { return 1.0f / (1.0f + __expf(-x)); }
__device__ __forceinline__ float siluf_(float x)    { return x / (1.0f + __expf(-x)); }
__device__ __forceinline__ unsigned h2bits(__half2 h) { return *reinterpret_cast<unsigned*>(&h); }
__device__ __forceinline__ float2 h2f2(unsigned u) {
    return __half22float2(*reinterpret_cast<__half2*>(&u));
}

// ---- 16-lane helpers (encoders / node_G / edge_A_first) ----
__device__ __forceinline__ float ln16(float x, float g, float b) {
    float s = x, q = x * x;
    #pragma unroll
    for (int off = 8; off; off >>= 1) {
        s += __shfl_xor_sync(0xffffffffu, s, off);
        q += __shfl_xor_sync(0xffffffffu, q, off);
    }
    float mu  = s * (1.0f / 16.0f);
    float var = q * (1.0f / 16.0f) - mu * mu;
    return (x - mu) * rsqrtf(var + 1e-5f) * g + b;
}

struct Slot { int j, grp, lane, slot, stride; };
__device__ __forceinline__ Slot make_slot() {
    Slot s;
    int t = blockIdx.x * blockDim.x + threadIdx.x;
    s.lane = t & 31;
    s.j = s.lane & 15;
    s.grp = s.lane & 16;
    s.slot = ((t >> 5) << 1) + (s.grp >> 4);
    s.stride = ((gridDim.x * blockDim.x) >> 5) << 1;
    return s;
}

__device__ __forceinline__ void red_quad(unsigned* base, int node, const Slot& s,
                                         float num, float den) {
    __half2 h = __floats2half2_rn(num, den);
    unsigned v = h2bits(h);
    int b = s.lane & ~3;
    unsigned v0 = __shfl_sync(0xffffffffu, v, b);
    unsigned v1 = __shfl_sync(0xffffffffu, v, b | 1);
    unsigned v2 = __shfl_sync(0xffffffffu, v, b | 2);
    unsigned v3 = __shfl_sync(0xffffffffu, v, b | 3);
    if ((s.lane & 3) == 0) {
        unsigned* p = base + (size_t)node * 16 + s.j;
        asm volatile("red.global.add.noftz.v4.f16x2 [%0], {%1, %2, %3, %4};"
                     :: "l"(p), "r"(v0), "r"(v1), "r"(v2), "r"(v3) : "memory");
    }
}

// ---- 8-lane helpers (edge_A conv1/2, edge_G): 2 channels per lane ----
struct Slot8 { int jj, g8, slot, stride; };
__device__ __forceinline__ Slot8 make_slot8() {
    Slot8 s;
    int t = blockIdx.x * blockDim.x + threadIdx.x;
    int lane = t & 31;
    s.jj = lane & 7;
    s.g8 = lane & 24;
    s.slot = ((t >> 5) << 2) + (lane >> 3);
    s.stride = ((gridDim.x * blockDim.x) >> 5) << 2;
    return s;
}

// LayerNorm over 16 channels held as pairs across 8 lanes
__device__ __forceinline__ float2 ln8pair(float x0, float x1, float g0, float g1,
                                          float b0, float b1) {
    float s = x0 + x1, q = x0 * x0 + x1 * x1;
    #pragma unroll
    for (int off = 4; off; off >>= 1) {
        s += __shfl_xor_sync(0xffffffffu, s, off);
        q += __shfl_xor_sync(0xffffffffu, q, off);
    }
    float mu  = s * (1.0f / 16.0f);
    float var = q * (1.0f / 16.0f) - mu * mu;
    float r = rsqrtf(var + 1e-5f);
    return make_float2((x0 - mu) * r * g0 + b0, (x1 - mu) * r * g1 + b1);
}

// pair-lane vector reduction: lane owns 2 channels (2 words); even jj issues 16B RED
__device__ __forceinline__ void red_pair8(unsigned* base, int node, int jj,
                                          unsigned a0, unsigned a1) {
    unsigned b0 = __shfl_xor_sync(0xffffffffu, a0, 1);
    unsigned b1 = __shfl_xor_sync(0xffffffffu, a1, 1);
    if ((jj & 1) == 0) {
        unsigned* p = base + (size_t)node * 16 + 2 * jj;
        asm volatile("red.global.add.noftz.v4.f16x2 [%0], {%1, %2, %3, %4};"
                     :: "l"(p), "r"(a0), "r"(a1), "r"(b0), "r"(b1) : "memory");
    }
}

// 4-matvec weight pack (planar, as in R10): [0,256)=W0, [256,512)=W1, [512,768)=W4,
// [768,1024)=W3, [1024,1040)=b0, [1040,1056)=b1
#define WPACK 1056
__device__ __forceinline__ void load_wproj(float* sw, const float* W, const float* b) {
    for (int i = threadIdx.x; i < WPACK; i += blockDim.x) {
        if (i < 256)        sw[i] = W[i];
        else if (i < 512)   sw[i] = W[256 + (i - 256)];
        else if (i < 768)   sw[i] = W[4 * 256 + (i - 512)];
        else if (i < 1024)  sw[i] = W[3 * 256 + (i - 768)];
        else if (i < 1040)  sw[i] = b[i - 1024];
        else                sw[i] = b[16 + (i - 1040)];
    }
    __syncthreads();
}

// 16-lane projection (encoders, node_G)
__device__ __forceinline__ void proj_store(float v, const Slot& s, const float* sw,
                                           unsigned* dst_s, __half* dst_d, __half* dst_3,
                                           int i) {
    float p0 = sw[1024 + s.j], p1 = 0.0f, p4 = 0.0f, p3 = sw[1040 + s.j];
    #pragma unroll
    for (int k = 0; k < 16; k++) {
        float a = __shfl_sync(0xffffffffu, v, s.grp | k);
        p0 += a * sw[k * 16 + s.j];
        p1 += a * sw[256 + k * 16 + s.j];
        p4 += a * sw[512 + k * 16 + s.j];
        p3 += a * sw[768 + k * 16 + s.j];
    }
    dst_s[(size_t)i * 16 + s.j] = h2bits(__floats2half2_rn(p0, p4));
    dst_d[(size_t)i * 16 + s.j] = __float2half_rn(p1);
    dst_3[(size_t)i * 16 + s.j] = __float2half_rn(p3);
}

// 8-lane projection (edge_G): float2 smem loads, pairs of channels (R10 layout)
__device__ __forceinline__ void proj_store8(float v0, float v1, const Slot8& s,
                                            const float* sw, unsigned* dst_s,
                                            __half* dst_d, __half* dst_3, int i) {
    int j0 = 2 * s.jj;
    float2 bb0 = *(const float2*)&sw[1024 + j0];
    float2 bb1 = *(const float2*)&sw[1040 + j0];
    float p0a = bb0.x, p0b = bb0.y, p1a = 0.f, p1b = 0.f;
    float p4a = 0.f, p4b = 0.f, p3a = bb1.x, p3b = bb1.y;
    #pragma unroll
    for (int t = 0; t < 8; t++) {
        float e0 = __shfl_sync(0xffffffffu, v0, s.g8 | t);
        float e1 = __shfl_sync(0xffffffffu, v1, s.g8 | t);
        int k0 = 2 * t * 16 + j0, k1 = (2 * t + 1) * 16 + j0;
        float2 wa0 = *(const float2*)&sw[k0],        wa1 = *(const float2*)&sw[k1];
        p0a += e0 * wa0.x + e1 * wa1.x;  p0b += e0 * wa0.y + e1 * wa1.y;
        float2 wb0 = *(const float2*)&sw[256 + k0],  wb1 = *(const float2*)&sw[256 + k1];
        p1a += e0 * wb0.x + e1 * wb1.x;  p1b += e0 * wb0.y + e1 * wb1.y;
        float2 wc0 = *(const float2*)&sw[512 + k0],  wc1 = *(const float2*)&sw[512 + k1];
        p4a += e0 * wc0.x + e1 * wc1.x;  p4b += e0 * wc0.y + e1 * wc1.y;
        float2 wd0 = *(const float2*)&sw[768 + k0],  wd1 = *(const float2*)&sw[768 + k1];
        p3a += e0 * wd0.x + e1 * wd1.x;  p3b += e0 * wd0.y + e1 * wd1.y;
    }
    uint2 ps;
    ps.x = h2bits(__floats2half2_rn(p0a, p4a));
    ps.y = h2bits(__floats2half2_rn(p0b, p4b));
    *(uint2*)(dst_s + (size_t)i * 16 + j0) = ps;
    *(unsigned*)(&dst_d[(size_t)i * 16 + j0]) = h2bits(__floats2half2_rn(p1a, p1b));
    *(unsigned*)(&dst_3[(size_t)i * 16 + j0]) = h2bits(__floats2half2_rn(p3a, p3b));
}

// build 8-lane W2 pack: sw2q[t*8+jj] = (W2[2t][2jj], W2[2t][2jj+1], W2[2t+1][2jj], W2[2t+1][2jj+1])
__device__ __forceinline__ void load_w2q(float4* sw2q, const float* W2) {
    for (int i = threadIdx.x; i < 64; i += blockDim.x) {
        int t = i >> 3, jj = i & 7;
        sw2q[i] = make_float4(W2[(2 * t) * 16 + 2 * jj],     W2[(2 * t) * 16 + 2 * jj + 1],
                              W2[(2 * t + 1) * 16 + 2 * jj], W2[(2 * t + 1) * 16 + 2 * jj + 1]);
    }
}

// 16-lane edge-A body (used only by k_edge_A_first)
__device__ __forceinline__ void edgeA_core(int ed, int si, int di, float ev,
                                           const float* w2c, float ge, float be,
                                           const Slot& s, bool write_e) {
    float2 pf = h2f2(g_bps[(size_t)si * 16 + s.j]);
    float p1 = __half2float(g_bpd[(size_t)di * 16 + s.j]);
    float z = pf.x + p1;
    #pragma unroll
    for (int k = 0; k < 16; k++)
        z += __shfl_sync(0xffffffffu, ev, s.grp | k) * w2c[k];
    float sig = sigmoidf_(z);
    red_quad(g_accA, di, s, sig * pf.y, sig);
    if (write_e)
        g_h_ang[(size_t)ed * 16 + s.j] = __float2half_rn(ev + siluf_(ln16(z, ge, be)));
}

// ---------------- encoders (fused with first-conv projections) ----------------
__global__ void __launch_bounds__(256) k_enc_atm(
        const int* __restrict__ xatm,
        const float* __restrict__ W1, const float* __restrict__ b1,
        const float* __restrict__ W2, const float* __restrict__ b2,
        const float* __restrict__ lg, const float* __restrict__ lb,
        const float* __restrict__ Wg0, const float* __restrict__ bg0) {
    __shared__ float sw[WPACK];
    load_wproj(sw, Wg0, bg0);
    Slot s = make_slot();
    float w2c[16];
    #pragma unroll
    for (int k = 0; k < 16; k++) w2c[k] = W2[k * 16 + s.j];
    float b1j = b1[s.j], b2j = b2[s.j], gj = lg[s.j], bj = lb[s.j];
    for (int a = s.slot; a < N_ATM; a += s.stride) {
        int sp = xatm[a];
        float h = siluf_(W1[sp * 16 + s.j] + b1j);
        float z = b2j;
        #pragma unroll
        for (int k = 0; k < 16; k++)
            z += __shfl_sync(0xffffffffu, h, s.grp | k) * w2c[k];
        float v = ln16(z, gj, bj);
        g_h_atm[a * 16 + s.j] = v;
        proj_store(v, s, sw, g_aps, g_apd, g_ap3, a);
    }
}

__global__ void __launch_bounds__(256) k_enc_bnd(
        const float* __restrict__ xb,
        const float* __restrict__ W1, const float* __restrict__ b1,
        const float* __restrict__ W2, const float* __restrict__ b2,
        const float* __restrict__ lg, const float* __restrict__ lb,
        const float* __restrict__ Wa0, const float* __restrict__ ba0) {
    __shared__ float sw[WPACK];
    load_wproj(sw, Wa0, ba0);
    Slot s = make_slot();
    float w1c[16], w2c[16];
    #pragma unroll
    for (int k = 0; k < 16; k++) { w1c[k] = W1[k * 16 + s.j]; w2c[k] = W2[k * 16 + s.j]; }
    float b1j = b1[s.j], b2j = b2[s.j], gj = lg[s.j], bj = lb[s.j];
    const float nrm = sqrtf(2.0f / 5.0f);
    for (int e = s.slot; e < N_BND; e += s.stride) {
        float xx = xb[e] + 1e-5f;
        float f = nrm * sinf((float)(s.j + 1) * PI_F * xx * (1.0f / 5.0f)) / xx;
        float h = b1j;
        #pragma unroll
        for (int k = 0; k < 16; k++)
            h += __shfl_sync(0xffffffffu, f, s.grp | k) * w1c[k];
        h = siluf_(h);
        float z = b2j;
        #pragma unroll
        for (int k = 0; k < 16; k++)
            z += __shfl_sync(0xffffffffu, h, s.grp | k) * w2c[k];
        float v = ln16(z, gj, bj);
        g_h_bnd[e * 16 + s.j] = v;
        proj_store(v, s, sw, g_bps, g_bpd, g_bp3, e);
    }
}

// ---------------- A-graph edge phase, conv 0: fused angle encoder (16-lane) ----
__global__ void __launch_bounds__(256) k_edge_A_first(
        const int* __restrict__ src, const int* __restrict__ dst,
        const float* __restrict__ xang, const int* __restrict__ mask,
        const float* __restrict__ W1, const float* __restrict__ b1,
        const float* __restrict__ W2, const float* __restrict__ b2,
        const float* __restrict__ lg, const float* __restrict__ lb,
        const float* __restrict__ W, const float* __restrict__ ln) {
    __shared__ float sw[1152];
    for (int i = threadIdx.x; i < 1152; i += blockDim.x) {
        if (i < 512)       sw[i] = W1[512 + i];           // sets 2,3 of W1
        else if (i < 1024) sw[i] = W2[i];                 // sets 2,3 of W2
        else {
            int idx = i - 1024, gsel = idx >> 4, j = idx & 15;
            const float* tbl[8] = { b1 + 32, b1 + 48, b2 + 32, b2 + 48,
                                    lg + 32, lg + 48, lb + 32, lb + 48 };
            sw[i] = tbl[gsel][j];
        }
    }
    __syncthreads();
    Slot s = make_slot();
    float w2c[16];
    #pragma unroll
    for (int k = 0; k < 16; k++) w2c[k] = W[2 * 256 + k * 16 + s.j];
    float ge = ln[32 + s.j], be = ln[48 + s.j];
    const float cb = (float)s.j * (PI_F / 15.0f);
    const float cd = -PI_F + (float)s.j * (2.0f * PI_F / 15.0f);
    const float* sv = sw + 1024;
    for (int ed = s.slot; ed < N_ANG; ed += s.stride) {
        int si = src[ed], di = dst[ed];
        float x = xang[ed];
        bool m = mask[ed] != 0;
        int o = m ? 256 : 0, o16 = m ? 16 : 0;
        float gam = m ? (7.5f / PI_F) : (15.0f / PI_F);
        float t = gam * (x - (m ? cd : cb));
        float f = __expf(-t * t);
        const float* w1p = sw + o;
        const float* w2p = sw + 512 + o;
        float h = sv[o16 + s.j];
        #pragma unroll
        for (int k = 0; k < 16; k++)
            h += __shfl_sync(0xffffffffu, f, s.grp | k) * w1p[k * 16 + s.j];
        h = siluf_(h);
        float z2 = sv[32 + o16 + s.j];
        #pragma unroll
        for (int k = 0; k < 16; k++)
            z2 += __shfl_sync(0xffffffffu, h, s.grp | k) * w2p[k * 16 + s.j];
        float ev = ln16(z2, sv[64 + o16 + s.j], sv[96 + o16 + s.j]);
        edgeA_core(ed, si, di, ev, w2c, ge, be, s, true);
    }
}

// ---------------- A-graph edge phase, conv 1/2 (8-lane; W2 float4 pack) ----------
__global__ void __launch_bounds__(256) k_edge_A(
        const int* __restrict__ src, const int* __restrict__ dst,
        const float* __restrict__ W, const float* __restrict__ ln, int write_e) {
    __shared__ __align__(16) float4 sw2q[64];
    load_w2q(sw2q, W + 512);
    __syncthreads();
    Slot8 s = make_slot8();
    int j0 = 2 * s.jj;
    float ge0 = ln[32 + j0], ge1 = ln[33 + j0], be0 = ln[48 + j0], be1 = ln[49 + j0];
    for (int ed = s.slot; ed < N_ANG; ed += s.stride) {
        int si = src[ed], di = dst[ed];
        unsigned evu = *(const unsigned*)(&g_h_ang[(size_t)ed * 16 + j0]);
        uint2 pv = *(const uint2*)(g_bps + (size_t)si * 16 + j0);
        unsigned pdu = *(const unsigned*)(&g_bpd[(size_t)di * 16 + j0]);
        float2 pa = h2f2(pv.x), pb = h2f2(pv.y), p1 = h2f2(pdu);
        float z0 = pa.x + p1.x, z1 = pb.x + p1.y;
        #pragma unroll
        for (int t = 0; t < 8; t++) {
            unsigned eu = __shfl_sync(0xffffffffu, evu, s.g8 | t);
            float2 e = h2f2(eu);
            float4 w = sw2q[t * 8 + s.jj];
            z0 += e.x * w.x + e.y * w.z;
            z1 += e.x * w.y + e.y * w.w;
        }
        float sig0 = sigmoidf_(z0), sig1 = sigmoidf_(z1);
        red_pair8(g_accA, di, s.jj,
                  h2bits(__floats2half2_rn(sig0 * pa.y, sig0)),
                  h2bits(__floats2half2_rn(sig1 * pb.y, sig1)));
        if (write_e) {
            float2 evf = h2f2(evu);
            float2 l = ln8pair(z0, z1, ge0, ge1, be0, be1);
            __half2 out = __floats2half2_rn(evf.x + siluf_(l.x), evf.y + siluf_(l.y));
            *(unsigned*)(&g_h_ang[(size_t)ed * 16 + j0]) = h2bits(out);
        }
    }
}

// ---------------- G-graph edge phase with fused A-node update (8-lane) ----------
// smem: sw[WPACK] = next-A proj pack (planar); sw2q[64] = Wg's W2 float4 pack
__global__ void __launch_bounds__(256) k_edge_G(
        const int* __restrict__ src, const int* __restrict__ dst,
        const float* __restrict__ Wg, const float* __restrict__ lnG,
        const float* __restrict__ lnA,
        const float* __restrict__ Wnext, const float* __restrict__ bnext) {
    __shared__ float sw[WPACK];
    __shared__ __align__(16) float4 sw2q[64];
    bool has_next = (Wnext != nullptr);
    load_w2q(sw2q, Wg + 512);
    if (has_next) {
        load_wproj(sw, Wnext, bnext);   // includes __syncthreads()
    } else {
        __syncthreads();
    }
    Slot8 s = make_slot8();
    int j0 = 2 * s.jj;
    float ge0 = lnG[32 + j0], ge1 = lnG[33 + j0], be0 = lnG[48 + j0], be1 = lnG[49 + j0];
    float gn0 = lnA[j0], gn1 = lnA[j0 + 1], bn0 = lnA[16 + j0], bn1 = lnA[17 + j0];
    for (int ed = s.slot; ed < N_BND; ed += s.stride) {
        int si = src[ed], di = dst[ed];
        // --- fused A-node update for bond ed ---
        uint2 au = *(const uint2*)(g_accA + (size_t)ed * 16 + j0);
        float2 a0 = h2f2(au.x), a1 = h2f2(au.y);
        float2 p3 = h2f2(*(const unsigned*)(&g_bp3[(size_t)ed * 16 + j0]));
        float u0 = p3.x + a0.x / (a0.y + 1e-5f);
        float u1 = p3.y + a1.x / (a1.y + 1e-5f);
        float2 xv = *(const float2*)(g_h_bnd + (size_t)ed * 16 + j0);
        float2 l = ln8pair(u0, u1, gn0, gn1, bn0, bn1);
        float ev0 = xv.x + siluf_(l.x), ev1 = xv.y + siluf_(l.y);
        *(uint2*)(g_accA + (size_t)ed * 16 + j0) = make_uint2(0u, 0u);
        // --- G edge ---
        uint2 pv = *(const uint2*)(g_aps + (size_t)si * 16 + j0);
        unsigned pdu = *(const unsigned*)(&g_apd[(size_t)di * 16 + j0]);
        float2 pa = h2f2(pv.x), pb = h2f2(pv.y), p1 = h2f2(pdu);
        float z0 = pa.x + p1.x, z1 = pb.x + p1.y;
        #pragma unroll
        for (int t = 0; t < 8; t++) {
            float e0 = __shfl_sync(0xffffffffu, ev0, s.g8 | t);
            float e1 = __shfl_sync(0xffffffffu, ev1, s.g8 | t);
            float4 w = sw2q[t * 8 + s.jj];
            z0 += e0 * w.x + e1 * w.z;
            z1 += e0 * w.y + e1 * w.w;
        }
        float sig0 = sigmoidf_(z0), sig1 = sigmoidf_(z1);
        red_pair8(g_accG, di, s.jj,
                  h2bits(__floats2half2_rn(sig0 * pa.y, sig0)),
                  h2bits(__floats2half2_rn(sig1 * pb.y, sig1)));
        if (has_next) {
            float2 le = ln8pair(z0, z1, ge0, ge1, be0, be1);
            float en0 = ev0 + siluf_(le.x), en1 = ev1 + siluf_(le.y);
            *(float2*)(g_h_bnd + (size_t)ed * 16 + j0) = make_float2(en0, en1);
            proj_store8(en0, en1, s, sw, g_bps, g_bpd, g_bp3, ed);
        }
    }
}

// ---------------- G-graph node phase (16-lane; zero accG; next-G proj; pool) ----
__global__ void __launch_bounds__(256) k_node_G(
        const float* __restrict__ ln,
        const float* __restrict__ Wnext, const float* __restrict__ bnext,
        const int* __restrict__ batch, int is_last) {
    __shared__ float sw[WPACK];
    bool has_next = (Wnext != nullptr);
    if (has_next) load_wproj(sw, Wnext, bnext);
    Slot s = make_slot();
    float gn = ln[s.j], bn = ln[16 + s.j];
    for (int i = s.slot; i < N_ATM; i += s.stride) {
        float2 ah = h2f2(g_accG[(size_t)i * 16 + s.j]);
        float xv = g_h_atm[(size_t)i * 16 + s.j];
        float u = __half2float(g_ap3[(size_t)i * 16 + s.j]) + ah.x / (ah.y + 1e-5f);
        float xn = xv + siluf_(ln16(u, gn, bn));
        g_accG[(size_t)i * 16 + s.j] = 0u;
        if (is_last) {
            atomicAdd(&g_pooled[batch[i] * 16 + s.j], xn);
        } else {
            g_h_atm[(size_t)i * 16 + s.j] = xn;
            proj_store(xn, s, sw, g_aps, g_apd, g_ap3, i);
        }
    }
}

// ---------------- head (also re-zeroes pooled for next replay) ----------------
__global__ void k_head(const float* __restrict__ fp,
                       const float* __restrict__ l1W, const float* __restrict__ l1b,
                       const float* __restrict__ l2W, const float* __restrict__ l2b,
                       float* __restrict__ out) {
    int g = threadIdx.x;  // one block of 256
    float p[16];
    #pragma unroll
    for (int i = 0; i < 16; i++) p[i] = g_pooled[g * 16 + i];
    float f0 = fp[2 * g], f1 = fp[2 * g + 1];
    float acc = l2b[0];
    #pragma unroll
    for (int jo = 0; jo < 16; jo++) {
        float h = l1b[jo];
        #pragma unroll
        for (int i = 0; i < 16; i++) h += p[i] * l1W[i * 16 + jo];
        h += f0 * l1W[16 * 16 + jo] + f1 * l1W[17 * 16 + jo];
        h = (h > 0.0f) ? h : 0.01f * h;
        acc += h * l2W[jo];
    }
    out[g] = acc;
    #pragma unroll
    for (int i = 0; i < 16; i++) g_pooled[g * 16 + i] = 0.0f;
}

// ---------------- launch ----------------
extern "C" void kernel_launch(void* const* d_in, const int* in_sizes, int n_in,
                              void* d_out, int out_size) {
    const int*   x_atm = (const int*)d_in[0];
    const float* x_bnd = (const float*)d_in[1];
    const float* x_ang = (const float*)d_in[2];
    const int*   mask  = (const int*)d_in[3];
    const int*   eG    = (const int*)d_in[4];
    const int*   eA    = (const int*)d_in[5];
    const int*   batch = (const int*)d_in[6];
    const float* fp    = (const float*)d_in[7];
    const float* W1    = (const float*)d_in[8];
    const float* b1    = (const float*)d_in[9];
    const float* W2    = (const float*)d_in[10];
    const float* b2    = (const float*)d_in[11];
    const float* lg    = (const float*)d_in[12];
    const float* lb    = (const float*)d_in[13];
    const float* cW    = (const float*)d_in[14];  // [3,2,5,16,16]
    const float* cb    = (const float*)d_in[15];  // [3,2,2,16]
    const float* cln   = (const float*)d_in[16];  // [3,2,2,2,16]
    const float* l1W   = (const float*)d_in[17];
    const float* l1b   = (const float*)d_in[18];
    const float* l2W   = (const float*)d_in[19];
    const float* l2b   = (const float*)d_in[20];
    float* out = (float*)d_out;

    #define WA(c)  (cW  + ((c) * 2 + 0) * 5 * 256)
    #define BA(c)  (cb  + ((c) * 2 + 0) * 32)
    #define LNA(c) (cln + ((c) * 2 + 0) * 64)
    #define WG(c)  (cW  + ((c) * 2 + 1) * 5 * 256)
    #define BG(c)  (cb  + ((c) * 2 + 1) * 32)
    #define LNG(c) (cln + ((c) * 2 + 1) * 64)

    k_enc_atm<<<512, 256>>>(x_atm, W1 + 0 * 256, b1 + 0 * 16, W2 + 0 * 256, b2 + 0 * 16,
                            lg + 0 * 16, lb + 0 * 16, WG(0), BG(0));
    k_enc_bnd<<<2048, 256>>>(x_bnd, W1 + 1 * 256, b1 + 1 * 16, W2 + 1 * 256, b2 + 1 * 16,
                             lg + 1 * 16, lb + 1 * 16, WA(0), BA(0));

    for (int c = 0; c < 3; c++) {
        if (c == 0) {
            k_edge_A_first<<<8192, 256>>>(eA, eA + N_ANG, x_ang, mask,
                                          W1, b1, W2, b2, lg, lb, WA(0), LNA(0));
        } else {
            k_edge_A<<<8192, 256>>>(eA, eA + N_ANG, WA(c), LNA(c), (c < 2) ? 1 : 0);
        }

        const float* WnA = (c < 2) ? WA(c + 1) : nullptr;
        const float* bnA = (c < 2) ? BA(c + 1) : nullptr;
        k_edge_G<<<8192, 256>>>(eG, eG + N_BND, WG(c), LNG(c), LNA(c), WnA, bnA);

        const float* WnG = (c < 2) ? WG(c + 1) : nullptr;
        const float* bnG = (c < 2) ? BG(c + 1) : nullptr;
        k_node_G<<<512, 256>>>(LNG(c), WnG, bnG, batch, (c == 2) ? 1 : 0);
    }

    k_head<<<1, 256>>>(fp, l1W, l1b, l2W, l2b, out);
}

// round 13
// speedup vs baseline: 1.1575x; 1.0306x over previous
#include <cuda_runtime.h>
#include <cuda_fp16.h>

#define DIM 16
#define N_ATM 131072
#define N_BND 1048576
#define N_ANG 2097152
#define N_GRAPHS 256
#define PI_F 3.14159265358979323846f

// ---------------- scratch (device globals; zero-init; invariants restored each replay) ----
__device__ float    g_h_atm[N_ATM * DIM];
__device__ float    g_h_bnd[N_BND * DIM];
__device__ __half   g_h_ang[N_ANG * DIM];   // fp16 storage (post-LN, O(1) values)
__device__ unsigned g_accA[N_BND * DIM];    // half2(num,den); zeroed by edge_G
__device__ unsigned g_accG[N_ATM * DIM];    // half2(num,den); zeroed by node_G
__device__ unsigned g_bps[N_BND * DIM];     // bond src-proj half2(p0,p4)
__device__ __half   g_bpd[N_BND * DIM];     // bond dst-proj p1
__device__ __half   g_bp3[N_BND * DIM];     // bond self-proj p3 = x@W3 + b1
__device__ unsigned g_aps[N_ATM * DIM];     // atom src-proj half2(p0,p4)
__device__ __half   g_apd[N_ATM * DIM];     // atom dst-proj p1
__device__ __half   g_ap3[N_ATM * DIM];     // atom self-proj p3
__device__ float    g_pooled[N_GRAPHS * DIM];

// ---------------- helpers ----------------
__device__ __forceinline__ float sigmoidf_(float x) { return 1.0f / (1.0f + __expf(-x)); }
__device__ __forceinline__ float siluf_(float x)    { return x / (1.0f + __expf(-x)); }
__device__ __forceinline__ unsigned h2bits(__half2 h) { return *reinterpret_cast<unsigned*>(&h); }
__device__ __forceinline__ float2 h2f2(unsigned u) {
    return __half22float2(*reinterpret_cast<__half2*>(&u));
}
__device__ __forceinline__ unsigned packh2(float a, float b) {
    return h2bits(__floats2half2_rn(a, b));
}

// ---- 16-lane helpers (encoders / node_G / edge_A_first) ----
__device__ __forceinline__ float ln16(float x, float g, float b) {
    float s = x, q = x * x;
    #pragma unroll
    for (int off = 8; off; off >>= 1) {
        s += __shfl_xor_sync(0xffffffffu, s, off);
        q += __shfl_xor_sync(0xffffffffu, q, off);
    }
    float mu  = s * (1.0f / 16.0f);
    float var = q * (1.0f / 16.0f) - mu * mu;
    return (x - mu) * rsqrtf(var + 1e-5f) * g + b;
}

struct Slot { int j, grp, lane, slot, stride; };
__device__ __forceinline__ Slot make_slot() {
    Slot s;
    int t = blockIdx.x * blockDim.x + threadIdx.x;
    s.lane = t & 31;
    s.j = s.lane & 15;
    s.grp = s.lane & 16;
    s.slot = ((t >> 5) << 1) + (s.grp >> 4);
    s.stride = ((gridDim.x * blockDim.x) >> 5) << 1;
    return s;
}

__device__ __forceinline__ void red_quad(unsigned* base, int node, const Slot& s,
                                         float num, float den) {
    unsigned v = packh2(num, den);
    int b = s.lane & ~3;
    unsigned v0 = __shfl_sync(0xffffffffu, v, b);
    unsigned v1 = __shfl_sync(0xffffffffu, v, b | 1);
    unsigned v2 = __shfl_sync(0xffffffffu, v, b | 2);
    unsigned v3 = __shfl_sync(0xffffffffu, v, b | 3);
    if ((s.lane & 3) == 0) {
        unsigned* p = base + (size_t)node * 16 + s.j;
        asm volatile("red.global.add.noftz.v4.f16x2 [%0], {%1, %2, %3, %4};"
                     :: "l"(p), "r"(v0), "r"(v1), "r"(v2), "r"(v3) : "memory");
    }
}

// ---- 8-lane helpers: 2 channels per lane ----
struct Slot8 { int jj, g8, slot, stride; };
__device__ __forceinline__ Slot8 make_slot8() {
    Slot8 s;
    int t = blockIdx.x * blockDim.x + threadIdx.x;
    int lane = t & 31;
    s.jj = lane & 7;
    s.g8 = lane & 24;
    s.slot = ((t >> 5) << 2) + (lane >> 3);
    s.stride = ((gridDim.x * blockDim.x) >> 5) << 2;
    return s;
}

__device__ __forceinline__ float2 ln8pair(float x0, float x1, float g0, float g1,
                                          float b0, float b1) {
    float s = x0 + x1, q = x0 * x0 + x1 * x1;
    #pragma unroll
    for (int off = 4; off; off >>= 1) {
        s += __shfl_xor_sync(0xffffffffu, s, off);
        q += __shfl_xor_sync(0xffffffffu, q, off);
    }
    float mu  = s * (1.0f / 16.0f);
    float var = q * (1.0f / 16.0f) - mu * mu;
    float r = rsqrtf(var + 1e-5f);
    return make_float2((x0 - mu) * r * g0 + b0, (x1 - mu) * r * g1 + b1);
}

__device__ __forceinline__ void red_pair8(unsigned* base, int node, int jj,
                                          unsigned a0, unsigned a1) {
    unsigned b0 = __shfl_xor_sync(0xffffffffu, a0, 1);
    unsigned b1 = __shfl_xor_sync(0xffffffffu, a1, 1);
    if ((jj & 1) == 0) {
        unsigned* p = base + (size_t)node * 16 + 2 * jj;
        asm volatile("red.global.add.noftz.v4.f16x2 [%0], {%1, %2, %3, %4};"
                     :: "l"(p), "r"(a0), "r"(a1), "r"(b0), "r"(b1) : "memory");
    }
}

// ---- fp16 projection weight pack ----
// swh[k*8 + jj] = uint4{ h2(W0[k][j0],W1[k][j0]), h2(W4[k][j0],W3[k][j0]),
//                        h2(W0[k][j1],W1[k][j1]), h2(W4[k][j1],W3[k][j1]) }  (j0=2jj)
// swb[0..15] = b0, swb[16..31] = b1  (fp32)
__device__ __forceinline__ void load_wpack(uint4* swh, float* swb,
                                           const float* W, const float* b) {
    const float* W0 = W;
    const float* W1 = W + 256;
    const float* W4 = W + 4 * 256;
    const float* W3 = W + 3 * 256;
    for (int i = threadIdx.x; i < 160; i += blockDim.x) {
        if (i < 128) {
            int k = i >> 3, j0 = (i & 7) * 2;
            uint4 u;
            u.x = packh2(W0[k * 16 + j0],     W1[k * 16 + j0]);
            u.y = packh2(W4[k * 16 + j0],     W3[k * 16 + j0]);
            u.z = packh2(W0[k * 16 + j0 + 1], W1[k * 16 + j0 + 1]);
            u.w = packh2(W4[k * 16 + j0 + 1], W3[k * 16 + j0 + 1]);
            swh[i] = u;
        } else {
            swb[i - 128] = b[i - 128];
        }
    }
}

// fp16 W2 pack for 8-lane z-matvec:
// sw2h[t*8+jj] = uint2{ h2(W2[2t][j0],W2[2t][j0+1]), h2(W2[2t+1][j0],W2[2t+1][j0+1]) }
__device__ __forceinline__ void load_w2h(uint2* sw2h, const float* W2) {
    for (int i = threadIdx.x; i < 64; i += blockDim.x) {
        int t = i >> 3, j0 = (i & 7) * 2;
        uint2 u;
        u.x = packh2(W2[(2 * t) * 16 + j0],     W2[(2 * t) * 16 + j0 + 1]);
        u.y = packh2(W2[(2 * t + 1) * 16 + j0], W2[(2 * t + 1) * 16 + j0 + 1]);
        sw2h[i] = u;
    }
}

// 16-lane projection (encoders, node_G): one LDS.128 per k (broadcast across j pairs)
__device__ __forceinline__ void proj_store(float v, const Slot& s, const uint4* swh,
                                           const float* swb,
                                           unsigned* dst_s, __half* dst_d, __half* dst_3,
                                           int i) {
    float p0 = swb[s.j], p1 = 0.0f, p4 = 0.0f, p3 = swb[16 + s.j];
    int odd = s.j & 1;
    #pragma unroll
    for (int k = 0; k < 16; k++) {
        float a = __shfl_sync(0xffffffffu, v, s.grp | k);
        uint4 w = swh[k * 8 + (s.j >> 1)];
        float2 f01 = h2f2(odd ? w.z : w.x);
        float2 f43 = h2f2(odd ? w.w : w.y);
        p0 += a * f01.x;
        p1 += a * f01.y;
        p4 += a * f43.x;
        p3 += a * f43.y;
    }
    dst_s[(size_t)i * 16 + s.j] = packh2(p0, p4);
    dst_d[(size_t)i * 16 + s.j] = __float2half_rn(p1);
    dst_3[(size_t)i * 16 + s.j] = __float2half_rn(p3);
}

// 8-lane projection (edge_G): 2 LDS.128 per t
__device__ __forceinline__ void proj_store8(float v0, float v1, const Slot8& s,
                                            const uint4* swh, const float* swb,
                                            unsigned* dst_s, __half* dst_d, __half* dst_3,
                                            int i) {
    int j0 = 2 * s.jj;
    float2 bb0 = *(const float2*)&swb[j0];
    float2 bb1 = *(const float2*)&swb[16 + j0];
    float p0a = bb0.x, p0b = bb0.y, p1a = 0.f, p1b = 0.f;
    float p4a = 0.f, p4b = 0.f, p3a = bb1.x, p3b = bb1.y;
    #pragma unroll
    for (int t = 0; t < 8; t++) {
        float e0 = __shfl_sync(0xffffffffu, v0, s.g8 | t);
        float e1 = __shfl_sync(0xffffffffu, v1, s.g8 | t);
        {
            uint4 w = swh[(2 * t) * 8 + s.jj];
            float2 a01 = h2f2(w.x), a43 = h2f2(w.y);
            float2 b01 = h2f2(w.z), b43 = h2f2(w.w);
            p0a += e0 * a01.x;  p1a += e0 * a01.y;  p4a += e0 * a43.x;  p3a += e0 * a43.y;
            p0b += e0 * b01.x;  p1b += e0 * b01.y;  p4b += e0 * b43.x;  p3b += e0 * b43.y;
        }
        {
            uint4 w = swh[(2 * t + 1) * 8 + s.jj];
            float2 a01 = h2f2(w.x), a43 = h2f2(w.y);
            float2 b01 = h2f2(w.z), b43 = h2f2(w.w);
            p0a += e1 * a01.x;  p1a += e1 * a01.y;  p4a += e1 * a43.x;  p3a += e1 * a43.y;
            p0b += e1 * b01.x;  p1b += e1 * b01.y;  p4b += e1 * b43.x;  p3b += e1 * b43.y;
        }
    }
    uint2 ps;
    ps.x = packh2(p0a, p4a);
    ps.y = packh2(p0b, p4b);
    *(uint2*)(dst_s + (size_t)i * 16 + j0) = ps;
    *(unsigned*)(&dst_d[(size_t)i * 16 + j0]) = packh2(p1a, p1b);
    *(unsigned*)(&dst_3[(size_t)i * 16 + j0]) = packh2(p3a, p3b);
}

// 16-lane edge-A body (used only by k_edge_A_first)
__device__ __forceinline__ void edgeA_core(int ed, int si, int di, float ev,
                                           const float* w2c, float ge, float be,
                                           const Slot& s, bool write_e) {
    float2 pf = h2f2(g_bps[(size_t)si * 16 + s.j]);
    float p1 = __half2float(g_bpd[(size_t)di * 16 + s.j]);
    float z = pf.x + p1;
    #pragma unroll
    for (int k = 0; k < 16; k++)
        z += __shfl_sync(0xffffffffu, ev, s.grp | k) * w2c[k];
    float sig = sigmoidf_(z);
    red_quad(g_accA, di, s, sig * pf.y, sig);
    if (write_e)
        g_h_ang[(size_t)ed * 16 + s.j] = __float2half_rn(ev + siluf_(ln16(z, ge, be)));
}

// ---------------- encoders (fused with first-conv projections) ----------------
__global__ void __launch_bounds__(256) k_enc_atm(
        const int* __restrict__ xatm,
        const float* __restrict__ W1, const float* __restrict__ b1,
        const float* __restrict__ W2, const float* __restrict__ b2,
        const float* __restrict__ lg, const float* __restrict__ lb,
        const float* __restrict__ Wg0, const float* __restrict__ bg0) {
    __shared__ uint4 swh[128];
    __shared__ float swb[32];
    load_wpack(swh, swb, Wg0, bg0);
    __syncthreads();
    Slot s = make_slot();
    float w2c[16];
    #pragma unroll
    for (int k = 0; k < 16; k++) w2c[k] = W2[k * 16 + s.j];
    float b1j = b1[s.j], b2j = b2[s.j], gj = lg[s.j], bj = lb[s.j];
    for (int a = s.slot; a < N_ATM; a += s.stride) {
        int sp = xatm[a];
        float h = siluf_(W1[sp * 16 + s.j] + b1j);
        float z = b2j;
        #pragma unroll
        for (int k = 0; k < 16; k++)
            z += __shfl_sync(0xffffffffu, h, s.grp | k) * w2c[k];
        float v = ln16(z, gj, bj);
        g_h_atm[a * 16 + s.j] = v;
        proj_store(v, s, swh, swb, g_aps, g_apd, g_ap3, a);
    }
}

__global__ void __launch_bounds__(256) k_enc_bnd(
        const float* __restrict__ xb,
        const float* __restrict__ W1, const float* __restrict__ b1,
        const float* __restrict__ W2, const float* __restrict__ b2,
        const float* __restrict__ lg, const float* __restrict__ lb,
        const float* __restrict__ Wa0, const float* __restrict__ ba0) {
    __shared__ uint4 swh[128];
    __shared__ float swb[32];
    load_wpack(swh, swb, Wa0, ba0);
    __syncthreads();
    Slot s = make_slot();
    float w1c[16], w2c[16];
    #pragma unroll
    for (int k = 0; k < 16; k++) { w1c[k] = W1[k * 16 + s.j]; w2c[k] = W2[k * 16 + s.j]; }
    float b1j = b1[s.j], b2j = b2[s.j], gj = lg[s.j], bj = lb[s.j];
    const float nrm = sqrtf(2.0f / 5.0f);
    for (int e = s.slot; e < N_BND; e += s.stride) {
        float xx = xb[e] + 1e-5f;
        float f = nrm * sinf((float)(s.j + 1) * PI_F * xx * (1.0f / 5.0f)) / xx;
        float h = b1j;
        #pragma unroll
        for (int k = 0; k < 16; k++)
            h += __shfl_sync(0xffffffffu, f, s.grp | k) * w1c[k];
        h = siluf_(h);
        float z = b2j;
        #pragma unroll
        for (int k = 0; k < 16; k++)
            z += __shfl_sync(0xffffffffu, h, s.grp | k) * w2c[k];
        float v = ln16(z, gj, bj);
        g_h_bnd[e * 16 + s.j] = v;
        proj_store(v, s, swh, swb, g_bps, g_bpd, g_bp3, e);
    }
}

// ---------------- A-graph edge phase, conv 0: fused angle encoder (16-lane) ----
__global__ void __launch_bounds__(256) k_edge_A_first(
        const int* __restrict__ src, const int* __restrict__ dst,
        const float* __restrict__ xang, const int* __restrict__ mask,
        const float* __restrict__ W1, const float* __restrict__ b1,
        const float* __restrict__ W2, const float* __restrict__ b2,
        const float* __restrict__ lg, const float* __restrict__ lb,
        const float* __restrict__ W, const float* __restrict__ ln) {
    __shared__ float sw[1152];
    for (int i = threadIdx.x; i < 1152; i += blockDim.x) {
        if (i < 512)       sw[i] = W1[512 + i];           // sets 2,3 of W1
        else if (i < 1024) sw[i] = W2[i];                 // sets 2,3 of W2
        else {
            int idx = i - 1024, gsel = idx >> 4, j = idx & 15;
            const float* tbl[8] = { b1 + 32, b1 + 48, b2 + 32, b2 + 48,
                                    lg + 32, lg + 48, lb + 32, lb + 48 };
            sw[i] = tbl[gsel][j];
        }
    }
    __syncthreads();
    Slot s = make_slot();
    float w2c[16];
    #pragma unroll
    for (int k = 0; k < 16; k++) w2c[k] = W[2 * 256 + k * 16 + s.j];
    float ge = ln[32 + s.j], be = ln[48 + s.j];
    const float cb = (float)s.j * (PI_F / 15.0f);
    const float cd = -PI_F + (float)s.j * (2.0f * PI_F / 15.0f);
    const float* sv = sw + 1024;
    for (int ed = s.slot; ed < N_ANG; ed += s.stride) {
        int si = src[ed], di = dst[ed];
        float x = xang[ed];
        bool m = mask[ed] != 0;
        int o = m ? 256 : 0, o16 = m ? 16 : 0;
        float gam = m ? (7.5f / PI_F) : (15.0f / PI_F);
        float t = gam * (x - (m ? cd : cb));
        float f = __expf(-t * t);
        const float* w1p = sw + o;
        const float* w2p = sw + 512 + o;
        float h = sv[o16 + s.j];
        #pragma unroll
        for (int k = 0; k < 16; k++)
            h += __shfl_sync(0xffffffffu, f, s.grp | k) * w1p[k * 16 + s.j];
        h = siluf_(h);
        float z2 = sv[32 + o16 + s.j];
        #pragma unroll
        for (int k = 0; k < 16; k++)
            z2 += __shfl_sync(0xffffffffu, h, s.grp | k) * w2p[k * 16 + s.j];
        float ev = ln16(z2, sv[64 + o16 + s.j], sv[96 + o16 + s.j]);
        edgeA_core(ed, si, di, ev, w2c, ge, be, s, true);
    }
}

// ---------------- A-graph edge phase, conv 1/2 (8-lane; fp16 W2 pack) ----------
__global__ void __launch_bounds__(256) k_edge_A(
        const int* __restrict__ src, const int* __restrict__ dst,
        const float* __restrict__ W, const float* __restrict__ ln, int write_e) {
    __shared__ uint2 sw2h[64];
    load_w2h(sw2h, W + 512);
    __syncthreads();
    Slot8 s = make_slot8();
    int j0 = 2 * s.jj;
    float ge0 = ln[32 + j0], ge1 = ln[33 + j0], be0 = ln[48 + j0], be1 = ln[49 + j0];
    for (int ed = s.slot; ed < N_ANG; ed += s.stride) {
        int si = src[ed], di = dst[ed];
        unsigned evu = *(const unsigned*)(&g_h_ang[(size_t)ed * 16 + j0]);
        uint2 pv = *(const uint2*)(g_bps + (size_t)si * 16 + j0);
        unsigned pdu = *(const unsigned*)(&g_bpd[(size_t)di * 16 + j0]);
        float2 pa = h2f2(pv.x), pb = h2f2(pv.y), p1 = h2f2(pdu);
        float z0 = pa.x + p1.x, z1 = pb.x + p1.y;
        #pragma unroll
        for (int t = 0; t < 8; t++) {
            unsigned eu = __shfl_sync(0xffffffffu, evu, s.g8 | t);
            float2 e = h2f2(eu);
            uint2 w = sw2h[t * 8 + s.jj];
            float2 f0 = h2f2(w.x);  // (W2[k0][j0], W2[k0][j1])
            float2 f1 = h2f2(w.y);  // (W2[k1][j0], W2[k1][j1])
            z0 += e.x * f0.x + e.y * f1.x;
            z1 += e.x * f0.y + e.y * f1.y;
        }
        float sig0 = sigmoidf_(z0), sig1 = sigmoidf_(z1);
        red_pair8(g_accA, di, s.jj,
                  packh2(sig0 * pa.y, sig0), packh2(sig1 * pb.y, sig1));
        if (write_e) {
            float2 evf = h2f2(evu);
            float2 l = ln8pair(z0, z1, ge0, ge1, be0, be1);
            *(unsigned*)(&g_h_ang[(size_t)ed * 16 + j0]) =
                packh2(evf.x + siluf_(l.x), evf.y + siluf_(l.y));
        }
    }
}

// ---------------- G-graph edge phase with fused A-node update (8-lane) ----------
__global__ void __launch_bounds__(256) k_edge_G(
        const int* __restrict__ src, const int* __restrict__ dst,
        const float* __restrict__ Wg, const float* __restrict__ lnG,
        const float* __restrict__ lnA,
        const float* __restrict__ Wnext, const float* __restrict__ bnext) {
    __shared__ uint4 swh[128];
    __shared__ float swb[32];
    __shared__ uint2 sw2h[64];
    bool has_next = (Wnext != nullptr);
    load_w2h(sw2h, Wg + 512);
    if (has_next) load_wpack(swh, swb, Wnext, bnext);
    __syncthreads();
    Slot8 s = make_slot8();
    int j0 = 2 * s.jj;
    float ge0 = lnG[32 + j0], ge1 = lnG[33 + j0], be0 = lnG[48 + j0], be1 = lnG[49 + j0];
    float gn0 = lnA[j0], gn1 = lnA[j0 + 1], bn0 = lnA[16 + j0], bn1 = lnA[17 + j0];
    for (int ed = s.slot; ed < N_BND; ed += s.stride) {
        int si = src[ed], di = dst[ed];
        // --- fused A-node update for bond ed ---
        uint2 au = *(const uint2*)(g_accA + (size_t)ed * 16 + j0);
        float2 a0 = h2f2(au.x), a1 = h2f2(au.y);
        float2 p3 = h2f2(*(const unsigned*)(&g_bp3[(size_t)ed * 16 + j0]));
        float u0 = p3.x + a0.x / (a0.y + 1e-5f);
        float u1 = p3.y + a1.x / (a1.y + 1e-5f);
        float2 xv = *(const float2*)(g_h_bnd + (size_t)ed * 16 + j0);
        float2 l = ln8pair(u0, u1, gn0, gn1, bn0, bn1);
        float ev0 = xv.x + siluf_(l.x), ev1 = xv.y + siluf_(l.y);
        *(uint2*)(g_accA + (size_t)ed * 16 + j0) = make_uint2(0u, 0u);
        // --- G edge ---
        uint2 pv = *(const uint2*)(g_aps + (size_t)si * 16 + j0);
        unsigned pdu = *(const unsigned*)(&g_apd[(size_t)di * 16 + j0]);
        float2 pa = h2f2(pv.x), pb = h2f2(pv.y), p1 = h2f2(pdu);
        float z0 = pa.x + p1.x, z1 = pb.x + p1.y;
        #pragma unroll
        for (int t = 0; t < 8; t++) {
            float e0 = __shfl_sync(0xffffffffu, ev0, s.g8 | t);
            float e1 = __shfl_sync(0xffffffffu, ev1, s.g8 | t);
            uint2 w = sw2h[t * 8 + s.jj];
            float2 f0 = h2f2(w.x);
            float2 f1 = h2f2(w.y);
            z0 += e0 * f0.x + e1 * f1.x;
            z1 += e0 * f0.y + e1 * f1.y;
        }
        float sig0 = sigmoidf_(z0), sig1 = sigmoidf_(z1);
        red_pair8(g_accG, di, s.jj,
                  packh2(sig0 * pa.y, sig0), packh2(sig1 * pb.y, sig1));
        if (has_next) {
            float2 le = ln8pair(z0, z1, ge0, ge1, be0, be1);
            float en0 = ev0 + siluf_(le.x), en1 = ev1 + siluf_(le.y);
            *(float2*)(g_h_bnd + (size_t)ed * 16 + j0) = make_float2(en0, en1);
            proj_store8(en0, en1, s, swh, swb, g_bps, g_bpd, g_bp3, ed);
        }
    }
}

// ---------------- G-graph node phase (16-lane; zero accG; next-G proj; pool) ----
__global__ void __launch_bounds__(256) k_node_G(
        const float* __restrict__ ln,
        const float* __restrict__ Wnext, const float* __restrict__ bnext,
        const int* __restrict__ batch, int is_last) {
    __shared__ uint4 swh[128];
    __shared__ float swb[32];
    bool has_next = (Wnext != nullptr);
    if (has_next) {
        load_wpack(swh, swb, Wnext, bnext);
        __syncthreads();
    }
    Slot s = make_slot();
    float gn = ln[s.j], bn = ln[16 + s.j];
    for (int i = s.slot; i < N_ATM; i += s.stride) {
        float2 ah = h2f2(g_accG[(size_t)i * 16 + s.j]);
        float xv = g_h_atm[(size_t)i * 16 + s.j];
        float u = __half2float(g_ap3[(size_t)i * 16 + s.j]) + ah.x / (ah.y + 1e-5f);
        float xn = xv + siluf_(ln16(u, gn, bn));
        g_accG[(size_t)i * 16 + s.j] = 0u;
        if (is_last) {
            atomicAdd(&g_pooled[batch[i] * 16 + s.j], xn);
        } else {
            g_h_atm[(size_t)i * 16 + s.j] = xn;
            proj_store(xn, s, swh, swb, g_aps, g_apd, g_ap3, i);
        }
    }
}

// ---------------- head (also re-zeroes pooled for next replay) ----------------
__global__ void k_head(const float* __restrict__ fp,
                       const float* __restrict__ l1W, const float* __restrict__ l1b,
                       const float* __restrict__ l2W, const float* __restrict__ l2b,
                       float* __restrict__ out) {
    int g = threadIdx.x;  // one block of 256
    float p[16];
    #pragma unroll
    for (int i = 0; i < 16; i++) p[i] = g_pooled[g * 16 + i];
    float f0 = fp[2 * g], f1 = fp[2 * g + 1];
    float acc = l2b[0];
    #pragma unroll
    for (int jo = 0; jo < 16; jo++) {
        float h = l1b[jo];
        #pragma unroll
        for (int i = 0; i < 16; i++) h += p[i] * l1W[i * 16 + jo];
        h += f0 * l1W[16 * 16 + jo] + f1 * l1W[17 * 16 + jo];
        h = (h > 0.0f) ? h : 0.01f * h;
        acc += h * l2W[jo];
    }
    out[g] = acc;
    #pragma unroll
    for (int i = 0; i < 16; i++) g_pooled[g * 16 + i] = 0.0f;
}

// ---------------- launch ----------------
extern "C" void kernel_launch(void* const* d_in, const int* in_sizes, int n_in,
                              void* d_out, int out_size) {
    const int*   x_atm = (const int*)d_in[0];
    const float* x_bnd = (const float*)d_in[1];
    const float* x_ang = (const float*)d_in[2];
    const int*   mask  = (const int*)d_in[3];
    const int*   eG    = (const int*)d_in[4];
    const int*   eA    = (const int*)d_in[5];
    const int*   batch = (const int*)d_in[6];
    const float* fp    = (const float*)d_in[7];
    const float* W1    = (const float*)d_in[8];
    const float* b1    = (const float*)d_in[9];
    const float* W2    = (const float*)d_in[10];
    const float* b2    = (const float*)d_in[11];
    const float* lg    = (const float*)d_in[12];
    const float* lb    = (const float*)d_in[13];
    const float* cW    = (const float*)d_in[14];  // [3,2,5,16,16]
    const float* cb    = (const float*)d_in[15];  // [3,2,2,16]
    const float* cln   = (const float*)d_in[16];  // [3,2,2,2,16]
    const float* l1W   = (const float*)d_in[17];
    const float* l1b   = (const float*)d_in[18];
    const float* l2W   = (const float*)d_in[19];
    const float* l2b   = (const float*)d_in[20];
    float* out = (float*)d_out;

    #define WA(c)  (cW  + ((c) * 2 + 0) * 5 * 256)
    #define BA(c)  (cb  + ((c) * 2 + 0) * 32)
    #define LNA(c) (cln + ((c) * 2 + 0) * 64)
    #define WG(c)  (cW  + ((c) * 2 + 1) * 5 * 256)
    #define BG(c)  (cb  + ((c) * 2 + 1) * 32)
    #define LNG(c) (cln + ((c) * 2 + 1) * 64)

    k_enc_atm<<<512, 256>>>(x_atm, W1 + 0 * 256, b1 + 0 * 16, W2 + 0 * 256, b2 + 0 * 16,
                            lg + 0 * 16, lb + 0 * 16, WG(0), BG(0));
    k_enc_bnd<<<2048, 256>>>(x_bnd, W1 + 1 * 256, b1 + 1 * 16, W2 + 1 * 256, b2 + 1 * 16,
                             lg + 1 * 16, lb + 1 * 16, WA(0), BA(0));

    for (int c = 0; c < 3; c++) {
        if (c == 0) {
            k_edge_A_first<<<8192, 256>>>(eA, eA + N_ANG, x_ang, mask,
                                          W1, b1, W2, b2, lg, lb, WA(0), LNA(0));
        } else {
            k_edge_A<<<8192, 256>>>(eA, eA + N_ANG, WA(c), LNA(c), (c < 2) ? 1 : 0);
        }

        const float* WnA = (c < 2) ? WA(c + 1) : nullptr;
        const float* bnA = (c < 2) ? BA(c + 1) : nullptr;
        k_edge_G<<<8192, 256>>>(eG, eG + N_BND, WG(c), LNG(c), LNA(c), WnA, bnA);

        const float* WnG = (c < 2) ? WG(c + 1) : nullptr;
        const float* bnG = (c < 2) ? BG(c + 1) : nullptr;
        k_node_G<<<512, 256>>>(LNG(c), WnG, bnG, batch, (c == 2) ? 1 : 0);
    }

    k_head<<<1, 256>>>(fp, l1W, l1b, l2W, l2b, out);
}

// round 14
// speedup vs baseline: 1.2380x; 1.0695x over previous
#include <cuda_runtime.h>
#include <cuda_fp16.h>

#define DIM 16
#define N_ATM 131072
#define N_BND 1048576
#define N_ANG 2097152
#define N_GRAPHS 256
#define PI_F 3.14159265358979323846f

// ---------------- scratch (device globals; zero-init; invariants restored each replay) ----
__device__ float    g_h_atm[N_ATM * DIM];
__device__ float    g_h_bnd[N_BND * DIM];
__device__ __half   g_h_ang[N_ANG * DIM];   // fp16 storage (post-LN, O(1) values)
__device__ unsigned g_accA[N_BND * DIM];    // half2(num,den); zeroed by edge_G
__device__ unsigned g_accG[N_ATM * DIM];    // half2(num,den); zeroed by node_G
__device__ unsigned g_bps[N_BND * DIM];     // bond src-proj half2(p0,p4)
__device__ __half   g_bpd[N_BND * DIM];     // bond dst-proj p1
__device__ __half   g_bp3[N_BND * DIM];     // bond self-proj p3 = x@W3 + b1
__device__ unsigned g_aps[N_ATM * DIM];     // atom src-proj half2(p0,p4)
__device__ __half   g_apd[N_ATM * DIM];     // atom dst-proj p1
__device__ __half   g_ap3[N_ATM * DIM];     // atom self-proj p3
__device__ float    g_pooled[N_GRAPHS * DIM];

// ---------------- helpers ----------------
__device__ __forceinline__ float sigmoidf_(float x) { return 1.0f / (1.0f + __expf(-x)); }
__device__ __forceinline__ float siluf_(float x)    { return x / (1.0f + __expf(-x)); }
__device__ __forceinline__ unsigned h2bits(__half2 h) { return *reinterpret_cast<unsigned*>(&h); }
__device__ __forceinline__ float2 h2f2(unsigned u) {
    return __half22float2(*reinterpret_cast<__half2*>(&u));
}
__device__ __forceinline__ unsigned packh2(float a, float b) {
    return h2bits(__floats2half2_rn(a, b));
}

// ---- 16-lane helpers (encoders / node_G / edge_A_first) ----
__device__ __forceinline__ float ln16(float x, float g, float b) {
    float s = x, q = x * x;
    #pragma unroll
    for (int off = 8; off; off >>= 1) {
        s += __shfl_xor_sync(0xffffffffu, s, off);
        q += __shfl_xor_sync(0xffffffffu, q, off);
    }
    float mu  = s * (1.0f / 16.0f);
    float var = q * (1.0f / 16.0f) - mu * mu;
    return (x - mu) * rsqrtf(var + 1e-5f) * g + b;
}

struct Slot { int j, grp, lane, slot, stride; };
__device__ __forceinline__ Slot make_slot() {
    Slot s;
    int t = blockIdx.x * blockDim.x + threadIdx.x;
    s.lane = t & 31;
    s.j = s.lane & 15;
    s.grp = s.lane & 16;
    s.slot = ((t >> 5) << 1) + (s.grp >> 4);
    s.stride = ((gridDim.x * blockDim.x) >> 5) << 1;
    return s;
}

__device__ __forceinline__ void red_quad(unsigned* base, int node, const Slot& s,
                                         float num, float den) {
    unsigned v = packh2(num, den);
    int b = s.lane & ~3;
    unsigned v0 = __shfl_sync(0xffffffffu, v, b);
    unsigned v1 = __shfl_sync(0xffffffffu, v, b | 1);
    unsigned v2 = __shfl_sync(0xffffffffu, v, b | 2);
    unsigned v3 = __shfl_sync(0xffffffffu, v, b | 3);
    if ((s.lane & 3) == 0) {
        unsigned* p = base + (size_t)node * 16 + s.j;
        asm volatile("red.global.add.noftz.v4.f16x2 [%0], {%1, %2, %3, %4};"
                     :: "l"(p), "r"(v0), "r"(v1), "r"(v2), "r"(v3) : "memory");
    }
}

// ---- 8-lane helpers: 2 channels per lane ----
struct Slot8 { int jj, g8, slot, stride; };
__device__ __forceinline__ Slot8 make_slot8() {
    Slot8 s;
    int t = blockIdx.x * blockDim.x + threadIdx.x;
    int lane = t & 31;
    s.jj = lane & 7;
    s.g8 = lane & 24;
    s.slot = ((t >> 5) << 2) + (lane >> 3);
    s.stride = ((gridDim.x * blockDim.x) >> 5) << 2;
    return s;
}

__device__ __forceinline__ float2 ln8pair(float x0, float x1, float g0, float g1,
                                          float b0, float b1) {
    float s = x0 + x1, q = x0 * x0 + x1 * x1;
    #pragma unroll
    for (int off = 4; off; off >>= 1) {
        s += __shfl_xor_sync(0xffffffffu, s, off);
        q += __shfl_xor_sync(0xffffffffu, q, off);
    }
    float mu  = s * (1.0f / 16.0f);
    float var = q * (1.0f / 16.0f) - mu * mu;
    float r = rsqrtf(var + 1e-5f);
    return make_float2((x0 - mu) * r * g0 + b0, (x1 - mu) * r * g1 + b1);
}

__device__ __forceinline__ void red_pair8(unsigned* base, int node, int jj,
                                          unsigned a0, unsigned a1) {
    unsigned b0 = __shfl_xor_sync(0xffffffffu, a0, 1);
    unsigned b1 = __shfl_xor_sync(0xffffffffu, a1, 1);
    if ((jj & 1) == 0) {
        unsigned* p = base + (size_t)node * 16 + 2 * jj;
        asm volatile("red.global.add.noftz.v4.f16x2 [%0], {%1, %2, %3, %4};"
                     :: "l"(p), "r"(a0), "r"(a1), "r"(b0), "r"(b1) : "memory");
    }
}

// ---- fp16 projection weight pack ----
// swh[k*8 + jj] = uint4{ h2(W0[k][j0],W1[k][j0]), h2(W4[k][j0],W3[k][j0]),
//                        h2(W0[k][j1],W1[k][j1]), h2(W4[k][j1],W3[k][j1]) }  (j0=2jj)
// swb[0..15] = b0, swb[16..31] = b1  (fp32)
__device__ __forceinline__ void load_wpack(uint4* swh, float* swb,
                                           const float* W, const float* b) {
    const float* W0 = W;
    const float* W1 = W + 256;
    const float* W4 = W + 4 * 256;
    const float* W3 = W + 3 * 256;
    for (int i = threadIdx.x; i < 160; i += blockDim.x) {
        if (i < 128) {
            int k = i >> 3, j0 = (i & 7) * 2;
            uint4 u;
            u.x = packh2(W0[k * 16 + j0],     W1[k * 16 + j0]);
            u.y = packh2(W4[k * 16 + j0],     W3[k * 16 + j0]);
            u.z = packh2(W0[k * 16 + j0 + 1], W1[k * 16 + j0 + 1]);
            u.w = packh2(W4[k * 16 + j0 + 1], W3[k * 16 + j0 + 1]);
            swh[i] = u;
        } else {
            swb[i - 128] = b[i - 128];
        }
    }
}

// fp16 W2 pack for 8-lane z-matvec:
// sw2h[t*8+jj] = uint2{ h2(W2[2t][j0],W2[2t][j0+1]), h2(W2[2t+1][j0],W2[2t+1][j0+1]) }
__device__ __forceinline__ void load_w2h(uint2* sw2h, const float* W2) {
    for (int i = threadIdx.x; i < 64; i += blockDim.x) {
        int t = i >> 3, j0 = (i & 7) * 2;
        uint2 u;
        u.x = packh2(W2[(2 * t) * 16 + j0],     W2[(2 * t) * 16 + j0 + 1]);
        u.y = packh2(W2[(2 * t + 1) * 16 + j0], W2[(2 * t + 1) * 16 + j0 + 1]);
        sw2h[i] = u;
    }
}

// 16-lane projection: HFMA2 accumulation (2 HFMA2 + 1 CVT per k)
__device__ __forceinline__ void proj_store(float v, const Slot& s, const uint4* swh,
                                           const float* swb,
                                           unsigned* dst_s, __half* dst_d, __half* dst_3,
                                           int i) {
    __half2 a01 = __floats2half2_rn(swb[s.j], 0.0f);        // (p0, p1)
    __half2 a43 = __floats2half2_rn(0.0f, swb[16 + s.j]);   // (p4, p3)
    int odd = s.j & 1;
    #pragma unroll
    for (int k = 0; k < 16; k++) {
        float a = __shfl_sync(0xffffffffu, v, s.grp | k);
        __half2 ah = __float2half2_rn(a);
        uint4 w = swh[k * 8 + (s.j >> 1)];
        unsigned w01 = odd ? w.z : w.x;
        unsigned w43 = odd ? w.w : w.y;
        a01 = __hfma2(ah, *reinterpret_cast<__half2*>(&w01), a01);
        a43 = __hfma2(ah, *reinterpret_cast<__half2*>(&w43), a43);
    }
    __half2 s04 = __halves2half2(__low2half(a01), __low2half(a43));  // (p0, p4)
    dst_s[(size_t)i * 16 + s.j] = h2bits(s04);
    dst_d[(size_t)i * 16 + s.j] = __high2half(a01);   // p1
    dst_3[(size_t)i * 16 + s.j] = __high2half(a43);   // p3
}

// 8-lane projection (edge_G): 2 LDS.128 + 8 HFMA2 + 2 CVT per t
__device__ __forceinline__ void proj_store8(float v0, float v1, const Slot8& s,
                                            const uint4* swh, const float* swb,
                                            unsigned* dst_s, __half* dst_d, __half* dst_3,
                                            int i) {
    int j0 = 2 * s.jj;
    __half2 a01_0 = __floats2half2_rn(swb[j0], 0.0f);
    __half2 a43_0 = __floats2half2_rn(0.0f, swb[16 + j0]);
    __half2 a01_1 = __floats2half2_rn(swb[j0 + 1], 0.0f);
    __half2 a43_1 = __floats2half2_rn(0.0f, swb[17 + j0]);
    #pragma unroll
    for (int t = 0; t < 8; t++) {
        float e0 = __shfl_sync(0xffffffffu, v0, s.g8 | t);
        float e1 = __shfl_sync(0xffffffffu, v1, s.g8 | t);
        __half2 e0h = __float2half2_rn(e0);
        __half2 e1h = __float2half2_rn(e1);
        uint4 wA = swh[(2 * t) * 8 + s.jj];
        uint4 wB = swh[(2 * t + 1) * 8 + s.jj];
        a01_0 = __hfma2(e0h, *reinterpret_cast<__half2*>(&wA.x), a01_0);
        a43_0 = __hfma2(e0h, *reinterpret_cast<__half2*>(&wA.y), a43_0);
        a01_1 = __hfma2(e0h, *reinterpret_cast<__half2*>(&wA.z), a01_1);
        a43_1 = __hfma2(e0h, *reinterpret_cast<__half2*>(&wA.w), a43_1);
        a01_0 = __hfma2(e1h, *reinterpret_cast<__half2*>(&wB.x), a01_0);
        a43_0 = __hfma2(e1h, *reinterpret_cast<__half2*>(&wB.y), a43_0);
        a01_1 = __hfma2(e1h, *reinterpret_cast<__half2*>(&wB.z), a01_1);
        a43_1 = __hfma2(e1h, *reinterpret_cast<__half2*>(&wB.w), a43_1);
    }
    uint2 ps;
    ps.x = h2bits(__halves2half2(__low2half(a01_0), __low2half(a43_0)));
    ps.y = h2bits(__halves2half2(__low2half(a01_1), __low2half(a43_1)));
    *(uint2*)(dst_s + (size_t)i * 16 + j0) = ps;
    *(unsigned*)(&dst_d[(size_t)i * 16 + j0]) =
        h2bits(__halves2half2(__high2half(a01_0), __high2half(a01_1)));
    *(unsigned*)(&dst_3[(size_t)i * 16 + j0]) =
        h2bits(__halves2half2(__high2half(a43_0), __high2half(a43_1)));
}

// 16-lane edge-A body (used only by k_edge_A_first)
__device__ __forceinline__ void edgeA_core(int ed, int si, int di, float ev,
                                           const float* w2c, float ge, float be,
                                           const Slot& s, bool write_e) {
    float2 pf = h2f2(g_bps[(size_t)si * 16 + s.j]);
    float p1 = __half2float(g_bpd[(size_t)di * 16 + s.j]);
    float z = pf.x + p1;
    #pragma unroll
    for (int k = 0; k < 16; k++)
        z += __shfl_sync(0xffffffffu, ev, s.grp | k) * w2c[k];
    float sig = sigmoidf_(z);
    red_quad(g_accA, di, s, sig * pf.y, sig);
    if (write_e)
        g_h_ang[(size_t)ed * 16 + s.j] = __float2half_rn(ev + siluf_(ln16(z, ge, be)));
}

// ---------------- encoders (fused with first-conv projections) ----------------
__global__ void __launch_bounds__(256) k_enc_atm(
        const int* __restrict__ xatm,
        const float* __restrict__ W1, const float* __restrict__ b1,
        const float* __restrict__ W2, const float* __restrict__ b2,
        const float* __restrict__ lg, const float* __restrict__ lb,
        const float* __restrict__ Wg0, const float* __restrict__ bg0) {
    __shared__ uint4 swh[128];
    __shared__ float swb[32];
    load_wpack(swh, swb, Wg0, bg0);
    __syncthreads();
    Slot s = make_slot();
    float w2c[16];
    #pragma unroll
    for (int k = 0; k < 16; k++) w2c[k] = W2[k * 16 + s.j];
    float b1j = b1[s.j], b2j = b2[s.j], gj = lg[s.j], bj = lb[s.j];
    for (int a = s.slot; a < N_ATM; a += s.stride) {
        int sp = xatm[a];
        float h = siluf_(W1[sp * 16 + s.j] + b1j);
        float z = b2j;
        #pragma unroll
        for (int k = 0; k < 16; k++)
            z += __shfl_sync(0xffffffffu, h, s.grp | k) * w2c[k];
        float v = ln16(z, gj, bj);
        g_h_atm[a * 16 + s.j] = v;
        proj_store(v, s, swh, swb, g_aps, g_apd, g_ap3, a);
    }
}

__global__ void __launch_bounds__(256) k_enc_bnd(
        const float* __restrict__ xb,
        const float* __restrict__ W1, const float* __restrict__ b1,
        const float* __restrict__ W2, const float* __restrict__ b2,
        const float* __restrict__ lg, const float* __restrict__ lb,
        const float* __restrict__ Wa0, const float* __restrict__ ba0) {
    __shared__ uint4 swh[128];
    __shared__ float swb[32];
    load_wpack(swh, swb, Wa0, ba0);
    __syncthreads();
    Slot s = make_slot();
    float w1c[16], w2c[16];
    #pragma unroll
    for (int k = 0; k < 16; k++) { w1c[k] = W1[k * 16 + s.j]; w2c[k] = W2[k * 16 + s.j]; }
    float b1j = b1[s.j], b2j = b2[s.j], gj = lg[s.j], bj = lb[s.j];
    const float nrm = sqrtf(2.0f / 5.0f);
    for (int e = s.slot; e < N_BND; e += s.stride) {
        float xx = xb[e] + 1e-5f;
        float f = nrm * sinf((float)(s.j + 1) * PI_F * xx * (1.0f / 5.0f)) / xx;
        float h = b1j;
        #pragma unroll
        for (int k = 0; k < 16; k++)
            h += __shfl_sync(0xffffffffu, f, s.grp | k) * w1c[k];
        h = siluf_(h);
        float z = b2j;
        #pragma unroll
        for (int k = 0; k < 16; k++)
            z += __shfl_sync(0xffffffffu, h, s.grp | k) * w2c[k];
        float v = ln16(z, gj, bj);
        g_h_bnd[e * 16 + s.j] = v;
        proj_store(v, s, swh, swb, g_bps, g_bpd, g_bp3, e);
    }
}

// ---------------- A-graph edge phase, conv 0: fused angle encoder (16-lane) ----
__global__ void __launch_bounds__(256) k_edge_A_first(
        const int* __restrict__ src, const int* __restrict__ dst,
        const float* __restrict__ xang, const int* __restrict__ mask,
        const float* __restrict__ W1, const float* __restrict__ b1,
        const float* __restrict__ W2, const float* __restrict__ b2,
        const float* __restrict__ lg, const float* __restrict__ lb,
        const float* __restrict__ W, const float* __restrict__ ln) {
    __shared__ float sw[1152];
    for (int i = threadIdx.x; i < 1152; i += blockDim.x) {
        if (i < 512)       sw[i] = W1[512 + i];           // sets 2,3 of W1
        else if (i < 1024) sw[i] = W2[i];                 // sets 2,3 of W2
        else {
            int idx = i - 1024, gsel = idx >> 4, j = idx & 15;
            const float* tbl[8] = { b1 + 32, b1 + 48, b2 + 32, b2 + 48,
                                    lg + 32, lg + 48, lb + 32, lb + 48 };
            sw[i] = tbl[gsel][j];
        }
    }
    __syncthreads();
    Slot s = make_slot();
    float w2c[16];
    #pragma unroll
    for (int k = 0; k < 16; k++) w2c[k] = W[2 * 256 + k * 16 + s.j];
    float ge = ln[32 + s.j], be = ln[48 + s.j];
    const float cb = (float)s.j * (PI_F / 15.0f);
    const float cd = -PI_F + (float)s.j * (2.0f * PI_F / 15.0f);
    const float* sv = sw + 1024;
    for (int ed = s.slot; ed < N_ANG; ed += s.stride) {
        int si = src[ed], di = dst[ed];
        float x = xang[ed];
        bool m = mask[ed] != 0;
        int o = m ? 256 : 0, o16 = m ? 16 : 0;
        float gam = m ? (7.5f / PI_F) : (15.0f / PI_F);
        float t = gam * (x - (m ? cd : cb));
        float f = __expf(-t * t);
        const float* w1p = sw + o;
        const float* w2p = sw + 512 + o;
        float h = sv[o16 + s.j];
        #pragma unroll
        for (int k = 0; k < 16; k++)
            h += __shfl_sync(0xffffffffu, f, s.grp | k) * w1p[k * 16 + s.j];
        h = siluf_(h);
        float z2 = sv[32 + o16 + s.j];
        #pragma unroll
        for (int k = 0; k < 16; k++)
            z2 += __shfl_sync(0xffffffffu, h, s.grp | k) * w2p[k * 16 + s.j];
        float ev = ln16(z2, sv[64 + o16 + s.j], sv[96 + o16 + s.j]);
        edgeA_core(ed, si, di, ev, w2c, ge, be, s, true);
    }
}

// ---------------- A-graph edge phase, conv 1/2 (8-lane; fp16 W2 pack) ----------
__global__ void __launch_bounds__(256) k_edge_A(
        const int* __restrict__ src, const int* __restrict__ dst,
        const float* __restrict__ W, const float* __restrict__ ln, int write_e) {
    __shared__ uint2 sw2h[64];
    load_w2h(sw2h, W + 512);
    __syncthreads();
    Slot8 s = make_slot8();
    int j0 = 2 * s.jj;
    float ge0 = ln[32 + j0], ge1 = ln[33 + j0], be0 = ln[48 + j0], be1 = ln[49 + j0];
    for (int ed = s.slot; ed < N_ANG; ed += s.stride) {
        int si = src[ed], di = dst[ed];
        unsigned evu = *(const unsigned*)(&g_h_ang[(size_t)ed * 16 + j0]);
        uint2 pv = *(const uint2*)(g_bps + (size_t)si * 16 + j0);
        unsigned pdu = *(const unsigned*)(&g_bpd[(size_t)di * 16 + j0]);
        float2 pa = h2f2(pv.x), pb = h2f2(pv.y), p1 = h2f2(pdu);
        float z0 = pa.x + p1.x, z1 = pb.x + p1.y;
        #pragma unroll
        for (int t = 0; t < 8; t++) {
            unsigned eu = __shfl_sync(0xffffffffu, evu, s.g8 | t);
            float2 e = h2f2(eu);
            uint2 w = sw2h[t * 8 + s.jj];
            float2 f0 = h2f2(w.x);
            float2 f1 = h2f2(w.y);
            z0 += e.x * f0.x + e.y * f1.x;
            z1 += e.x * f0.y + e.y * f1.y;
        }
        float sig0 = sigmoidf_(z0), sig1 = sigmoidf_(z1);
        red_pair8(g_accA, di, s.jj,
                  packh2(sig0 * pa.y, sig0), packh2(sig1 * pb.y, sig1));
        if (write_e) {
            float2 evf = h2f2(evu);
            float2 l = ln8pair(z0, z1, ge0, ge1, be0, be1);
            *(unsigned*)(&g_h_ang[(size_t)ed * 16 + j0]) =
                packh2(evf.x + siluf_(l.x), evf.y + siluf_(l.y));
        }
    }
}

// ---------------- G-graph edge phase with fused A-node update (8-lane) ----------
__global__ void __launch_bounds__(256) k_edge_G(
        const int* __restrict__ src, const int* __restrict__ dst,
        const float* __restrict__ Wg, const float* __restrict__ lnG,
        const float* __restrict__ lnA,
        const float* __restrict__ Wnext, const float* __restrict__ bnext) {
    __shared__ uint4 swh[128];
    __shared__ float swb[32];
    __shared__ uint2 sw2h[64];
    bool has_next = (Wnext != nullptr);
    load_w2h(sw2h, Wg + 512);
    if (has_next) load_wpack(swh, swb, Wnext, bnext);
    __syncthreads();
    Slot8 s = make_slot8();
    int j0 = 2 * s.jj;
    float ge0 = lnG[32 + j0], ge1 = lnG[33 + j0], be0 = lnG[48 + j0], be1 = lnG[49 + j0];
    float gn0 = lnA[j0], gn1 = lnA[j0 + 1], bn0 = lnA[16 + j0], bn1 = lnA[17 + j0];
    for (int ed = s.slot; ed < N_BND; ed += s.stride) {
        int si = src[ed], di = dst[ed];
        // --- fused A-node update for bond ed ---
        uint2 au = *(const uint2*)(g_accA + (size_t)ed * 16 + j0);
        float2 a0 = h2f2(au.x), a1 = h2f2(au.y);
        float2 p3 = h2f2(*(const unsigned*)(&g_bp3[(size_t)ed * 16 + j0]));
        float u0 = p3.x + a0.x / (a0.y + 1e-5f);
        float u1 = p3.y + a1.x / (a1.y + 1e-5f);
        float2 xv = *(const float2*)(g_h_bnd + (size_t)ed * 16 + j0);
        float2 l = ln8pair(u0, u1, gn0, gn1, bn0, bn1);
        float ev0 = xv.x + siluf_(l.x), ev1 = xv.y + siluf_(l.y);
        *(uint2*)(g_accA + (size_t)ed * 16 + j0) = make_uint2(0u, 0u);
        // --- G edge ---
        uint2 pv = *(const uint2*)(g_aps + (size_t)si * 16 + j0);
        unsigned pdu = *(const unsigned*)(&g_apd[(size_t)di * 16 + j0]);
        float2 pa = h2f2(pv.x), pb = h2f2(pv.y), p1 = h2f2(pdu);
        float z0 = pa.x + p1.x, z1 = pb.x + p1.y;
        #pragma unroll
        for (int t = 0; t < 8; t++) {
            float e0 = __shfl_sync(0xffffffffu, ev0, s.g8 | t);
            float e1 = __shfl_sync(0xffffffffu, ev1, s.g8 | t);
            uint2 w = sw2h[t * 8 + s.jj];
            float2 f0 = h2f2(w.x);
            float2 f1 = h2f2(w.y);
            z0 += e0 * f0.x + e1 * f1.x;
            z1 += e0 * f0.y + e1 * f1.y;
        }
        float sig0 = sigmoidf_(z0), sig1 = sigmoidf_(z1);
        red_pair8(g_accG, di, s.jj,
                  packh2(sig0 * pa.y, sig0), packh2(sig1 * pb.y, sig1));
        if (has_next) {
            float2 le = ln8pair(z0, z1, ge0, ge1, be0, be1);
            float en0 = ev0 + siluf_(le.x), en1 = ev1 + siluf_(le.y);
            *(float2*)(g_h_bnd + (size_t)ed * 16 + j0) = make_float2(en0, en1);
            proj_store8(en0, en1, s, swh, swb, g_bps, g_bpd, g_bp3, ed);
        }
    }
}

// ---------------- G-graph node phase (16-lane; zero accG; next-G proj; pool) ----
__global__ void __launch_bounds__(256) k_node_G(
        const float* __restrict__ ln,
        const float* __restrict__ Wnext, const float* __restrict__ bnext,
        const int* __restrict__ batch, int is_last) {
    __shared__ uint4 swh[128];
    __shared__ float swb[32];
    bool has_next = (Wnext != nullptr);
    if (has_next) {
        load_wpack(swh, swb, Wnext, bnext);
        __syncthreads();
    }
    Slot s = make_slot();
    float gn = ln[s.j], bn = ln[16 + s.j];
    for (int i = s.slot; i < N_ATM; i += s.stride) {
        float2 ah = h2f2(g_accG[(size_t)i * 16 + s.j]);
        float xv = g_h_atm[(size_t)i * 16 + s.j];
        float u = __half2float(g_ap3[(size_t)i * 16 + s.j]) + ah.x / (ah.y + 1e-5f);
        float xn = xv + siluf_(ln16(u, gn, bn));
        g_accG[(size_t)i * 16 + s.j] = 0u;
        if (is_last) {
            atomicAdd(&g_pooled[batch[i] * 16 + s.j], xn);
        } else {
            g_h_atm[(size_t)i * 16 + s.j] = xn;
            proj_store(xn, s, swh, swb, g_aps, g_apd, g_ap3, i);
        }
    }
}

// ---------------- head (also re-zeroes pooled for next replay) ----------------
__global__ void k_head(const float* __restrict__ fp,
                       const float* __restrict__ l1W, const float* __restrict__ l1b,
                       const float* __restrict__ l2W, const float* __restrict__ l2b,
                       float* __restrict__ out) {
    int g = threadIdx.x;  // one block of 256
    float p[16];
    #pragma unroll
    for (int i = 0; i < 16; i++) p[i] = g_pooled[g * 16 + i];
    float f0 = fp[2 * g], f1 = fp[2 * g + 1];
    float acc = l2b[0];
    #pragma unroll
    for (int jo = 0; jo < 16; jo++) {
        float h = l1b[jo];
        #pragma unroll
        for (int i = 0; i < 16; i++) h += p[i] * l1W[i * 16 + jo];
        h += f0 * l1W[16 * 16 + jo] + f1 * l1W[17 * 16 + jo];
        h = (h > 0.0f) ? h : 0.01f * h;
        acc += h * l2W[jo];
    }
    out[g] = acc;
    #pragma unroll
    for (int i = 0; i < 16; i++) g_pooled[g * 16 + i] = 0.0f;
}

// ---------------- launch ----------------
extern "C" void kernel_launch(void* const* d_in, const int* in_sizes, int n_in,
                              void* d_out, int out_size) {
    const int*   x_atm = (const int*)d_in[0];
    const float* x_bnd = (const float*)d_in[1];
    const float* x_ang = (const float*)d_in[2];
    const int*   mask  = (const int*)d_in[3];
    const int*   eG    = (const int*)d_in[4];
    const int*   eA    = (const int*)d_in[5];
    const int*   batch = (const int*)d_in[6];
    const float* fp    = (const float*)d_in[7];
    const float* W1    = (const float*)d_in[8];
    const float* b1    = (const float*)d_in[9];
    const float* W2    = (const float*)d_in[10];
    const float* b2    = (const float*)d_in[11];
    const float* lg    = (const float*)d_in[12];
    const float* lb    = (const float*)d_in[13];
    const float* cW    = (const float*)d_in[14];  // [3,2,5,16,16]
    const float* cb    = (const float*)d_in[15];  // [3,2,2,16]
    const float* cln   = (const float*)d_in[16];  // [3,2,2,2,16]
    const float* l1W   = (const float*)d_in[17];
    const float* l1b   = (const float*)d_in[18];
    const float* l2W   = (const float*)d_in[19];
    const float* l2b   = (const float*)d_in[20];
    float* out = (float*)d_out;

    #define WA(c)  (cW  + ((c) * 2 + 0) * 5 * 256)
    #define BA(c)  (cb  + ((c) * 2 + 0) * 32)
    #define LNA(c) (cln + ((c) * 2 + 0) * 64)
    #define WG(c)  (cW  + ((c) * 2 + 1) * 5 * 256)
    #define BG(c)  (cb  + ((c) * 2 + 1) * 32)
    #define LNG(c) (cln + ((c) * 2 + 1) * 64)

    k_enc_atm<<<512, 256>>>(x_atm, W1 + 0 * 256, b1 + 0 * 16, W2 + 0 * 256, b2 + 0 * 16,
                            lg + 0 * 16, lb + 0 * 16, WG(0), BG(0));
    k_enc_bnd<<<2048, 256>>>(x_bnd, W1 + 1 * 256, b1 + 1 * 16, W2 + 1 * 256, b2 + 1 * 16,
                             lg + 1 * 16, lb + 1 * 16, WA(0), BA(0));

    for (int c = 0; c < 3; c++) {
        if (c == 0) {
            k_edge_A_first<<<8192, 256>>>(eA, eA + N_ANG, x_ang, mask,
                                          W1, b1, W2, b2, lg, lb, WA(0), LNA(0));
        } else {
            k_edge_A<<<8192, 256>>>(eA, eA + N_ANG, WA(c), LNA(c), (c < 2) ? 1 : 0);
        }

        const float* WnA = (c < 2) ? WA(c + 1) : nullptr;
        const float* bnA = (c < 2) ? BA(c + 1) : nullptr;
        k_edge_G<<<8192, 256>>>(eG, eG + N_BND, WG(c), LNG(c), LNA(c), WnA, bnA);

        const float* WnG = (c < 2) ? WG(c + 1) : nullptr;
        const float* bnG = (c < 2) ? BG(c + 1) : nullptr;
        k_node_G<<<512, 256>>>(LNG(c), WnG, bnG, batch, (c == 2) ? 1 : 0);
    }

    k_head<<<1, 256>>>(fp, l1W, l1b, l2W, l2b, out);
}

// round 15
// speedup vs baseline: 1.3941x; 1.1262x over previous
#include <cuda_runtime.h>
#include <cuda_fp16.h>

#define DIM 16
#define N_ATM 131072
#define N_BND 1048576
#define N_ANG 2097152
#define N_GRAPHS 256
#define PI_F 3.14159265358979323846f

// ---------------- scratch (device globals; zero-init; invariants restored each replay) ----
__device__ float    g_h_atm[N_ATM * DIM];
__device__ float    g_h_bnd[N_BND * DIM];
__device__ __half   g_h_ang[N_ANG * DIM];   // fp16 storage (post-LN, O(1) values)
__device__ unsigned g_accA[N_BND * DIM];    // half2(num,den); zeroed by edge_G
__device__ unsigned g_accG[N_ATM * DIM];    // half2(num,den); zeroed by node_G
__device__ unsigned g_bps[N_BND * DIM];     // bond src-proj half2(p0,p4)
__device__ __half   g_bpd[N_BND * DIM];     // bond dst-proj p1
__device__ __half   g_bp3[N_BND * DIM];     // bond self-proj p3 = x@W3 + b1
__device__ unsigned g_aps[N_ATM * DIM];     // atom src-proj half2(p0,p4)
__device__ __half   g_apd[N_ATM * DIM];     // atom dst-proj p1
__device__ __half   g_ap3[N_ATM * DIM];     // atom self-proj p3
__device__ float    g_pooled[N_GRAPHS * DIM];

// ---------------- helpers ----------------
__device__ __forceinline__ float sigmoidf_(float x) { return 1.0f / (1.0f + __expf(-x)); }
__device__ __forceinline__ float siluf_(float x)    { return x / (1.0f + __expf(-x)); }
__device__ __forceinline__ unsigned h2bits(__half2 h) { return *reinterpret_cast<unsigned*>(&h); }
__device__ __forceinline__ float2 h2f2(unsigned u) {
    return __half22float2(*reinterpret_cast<__half2*>(&u));
}
__device__ __forceinline__ unsigned packh2(float a, float b) {
    return h2bits(__floats2half2_rn(a, b));
}

// ---- 16-lane helpers (encoders / node_G) ----
__device__ __forceinline__ float ln16(float x, float g, float b) {
    float s = x, q = x * x;
    #pragma unroll
    for (int off = 8; off; off >>= 1) {
        s += __shfl_xor_sync(0xffffffffu, s, off);
        q += __shfl_xor_sync(0xffffffffu, q, off);
    }
    float mu  = s * (1.0f / 16.0f);
    float var = q * (1.0f / 16.0f) - mu * mu;
    return (x - mu) * rsqrtf(var + 1e-5f) * g + b;
}

struct Slot { int j, grp, lane, slot, stride; };
__device__ __forceinline__ Slot make_slot() {
    Slot s;
    int t = blockIdx.x * blockDim.x + threadIdx.x;
    s.lane = t & 31;
    s.j = s.lane & 15;
    s.grp = s.lane & 16;
    s.slot = ((t >> 5) << 1) + (s.grp >> 4);
    s.stride = ((gridDim.x * blockDim.x) >> 5) << 1;
    return s;
}

// ---- 8-lane helpers: 2 channels per lane ----
struct Slot8 { int jj, g8, slot, stride; };
__device__ __forceinline__ Slot8 make_slot8() {
    Slot8 s;
    int t = blockIdx.x * blockDim.x + threadIdx.x;
    int lane = t & 31;
    s.jj = lane & 7;
    s.g8 = lane & 24;
    s.slot = ((t >> 5) << 2) + (lane >> 3);
    s.stride = ((gridDim.x * blockDim.x) >> 5) << 2;
    return s;
}

__device__ __forceinline__ float2 ln8pair(float x0, float x1, float g0, float g1,
                                          float b0, float b1) {
    float s = x0 + x1, q = x0 * x0 + x1 * x1;
    #pragma unroll
    for (int off = 4; off; off >>= 1) {
        s += __shfl_xor_sync(0xffffffffu, s, off);
        q += __shfl_xor_sync(0xffffffffu, q, off);
    }
    float mu  = s * (1.0f / 16.0f);
    float var = q * (1.0f / 16.0f) - mu * mu;
    float r = rsqrtf(var + 1e-5f);
    return make_float2((x0 - mu) * r * g0 + b0, (x1 - mu) * r * g1 + b1);
}

__device__ __forceinline__ void red_pair8(unsigned* base, int node, int jj,
                                          unsigned a0, unsigned a1) {
    unsigned b0 = __shfl_xor_sync(0xffffffffu, a0, 1);
    unsigned b1 = __shfl_xor_sync(0xffffffffu, a1, 1);
    if ((jj & 1) == 0) {
        unsigned* p = base + (size_t)node * 16 + 2 * jj;
        asm volatile("red.global.add.noftz.v4.f16x2 [%0], {%1, %2, %3, %4};"
                     :: "l"(p), "r"(a0), "r"(a1), "r"(b0), "r"(b1) : "memory");
    }
}

// ---- fp16 projection weight pack ----
// swh[k*8 + jj] = uint4{ h2(W0[k][j0],W1[k][j0]), h2(W4[k][j0],W3[k][j0]),
//                        h2(W0[k][j1],W1[k][j1]), h2(W4[k][j1],W3[k][j1]) }  (j0=2jj)
// swb[0..15] = b0, swb[16..31] = b1  (fp32)
__device__ __forceinline__ void load_wpack(uint4* swh, float* swb,
                                           const float* W, const float* b) {
    const float* W0 = W;
    const float* W1 = W + 256;
    const float* W4 = W + 4 * 256;
    const float* W3 = W + 3 * 256;
    for (int i = threadIdx.x; i < 160; i += blockDim.x) {
        if (i < 128) {
            int k = i >> 3, j0 = (i & 7) * 2;
            uint4 u;
            u.x = packh2(W0[k * 16 + j0],     W1[k * 16 + j0]);
            u.y = packh2(W4[k * 16 + j0],     W3[k * 16 + j0]);
            u.z = packh2(W0[k * 16 + j0 + 1], W1[k * 16 + j0 + 1]);
            u.w = packh2(W4[k * 16 + j0 + 1], W3[k * 16 + j0 + 1]);
            swh[i] = u;
        } else {
            swb[i - 128] = b[i - 128];
        }
    }
}

// fp16 16x16 matvec pack (8-lane): p[t*8+jj] = uint2{ h2(M[2t][j0],M[2t][j0+1]),
//                                                     h2(M[2t+1][j0],M[2t+1][j0+1]) }
__device__ __forceinline__ void load_w2h_at(uint2* p, const float* M, int base_i) {
    for (int i = threadIdx.x; i < 64; i += blockDim.x) {
        int t = i >> 3, j0 = (i & 7) * 2;
        uint2 u;
        u.x = packh2(M[(2 * t) * 16 + j0],     M[(2 * t) * 16 + j0 + 1]);
        u.y = packh2(M[(2 * t + 1) * 16 + j0], M[(2 * t + 1) * 16 + j0 + 1]);
        p[base_i + i] = u;
    }
}
__device__ __forceinline__ void load_w2h(uint2* p, const float* M) { load_w2h_at(p, M, 0); }

// 8-lane 16x16 matvec step: acc += shuffled-pair @ packed weights
__device__ __forceinline__ void mv8(float& z0, float& z1, unsigned vu, const uint2* p,
                                    int g8, int jj) {
    #pragma unroll
    for (int t = 0; t < 8; t++) {
        unsigned eu = __shfl_sync(0xffffffffu, vu, g8 | t);
        float2 e = h2f2(eu);
        uint2 w = p[t * 8 + jj];
        float2 f0 = h2f2(w.x);
        float2 f1 = h2f2(w.y);
        z0 += e.x * f0.x + e.y * f1.x;
        z1 += e.x * f0.y + e.y * f1.y;
    }
}

// 16-lane projection: HFMA2 accumulation
__device__ __forceinline__ void proj_store(float v, const Slot& s, const uint4* swh,
                                           const float* swb,
                                           unsigned* dst_s, __half* dst_d, __half* dst_3,
                                           int i) {
    __half2 a01 = __floats2half2_rn(swb[s.j], 0.0f);
    __half2 a43 = __floats2half2_rn(0.0f, swb[16 + s.j]);
    int odd = s.j & 1;
    #pragma unroll
    for (int k = 0; k < 16; k++) {
        float a = __shfl_sync(0xffffffffu, v, s.grp | k);
        __half2 ah = __float2half2_rn(a);
        uint4 w = swh[k * 8 + (s.j >> 1)];
        unsigned w01 = odd ? w.z : w.x;
        unsigned w43 = odd ? w.w : w.y;
        a01 = __hfma2(ah, *reinterpret_cast<__half2*>(&w01), a01);
        a43 = __hfma2(ah, *reinterpret_cast<__half2*>(&w43), a43);
    }
    dst_s[(size_t)i * 16 + s.j] = h2bits(__halves2half2(__low2half(a01), __low2half(a43)));
    dst_d[(size_t)i * 16 + s.j] = __high2half(a01);
    dst_3[(size_t)i * 16 + s.j] = __high2half(a43);
}

// 8-lane projection (edge_G)
__device__ __forceinline__ void proj_store8(float v0, float v1, const Slot8& s,
                                            const uint4* swh, const float* swb,
                                            unsigned* dst_s, __half* dst_d, __half* dst_3,
                                            int i) {
    int j0 = 2 * s.jj;
    __half2 a01_0 = __floats2half2_rn(swb[j0], 0.0f);
    __half2 a43_0 = __floats2half2_rn(0.0f, swb[16 + j0]);
    __half2 a01_1 = __floats2half2_rn(swb[j0 + 1], 0.0f);
    __half2 a43_1 = __floats2half2_rn(0.0f, swb[17 + j0]);
    #pragma unroll
    for (int t = 0; t < 8; t++) {
        float e0 = __shfl_sync(0xffffffffu, v0, s.g8 | t);
        float e1 = __shfl_sync(0xffffffffu, v1, s.g8 | t);
        __half2 e0h = __float2half2_rn(e0);
        __half2 e1h = __float2half2_rn(e1);
        uint4 wA = swh[(2 * t) * 8 + s.jj];
        uint4 wB = swh[(2 * t + 1) * 8 + s.jj];
        a01_0 = __hfma2(e0h, *reinterpret_cast<__half2*>(&wA.x), a01_0);
        a43_0 = __hfma2(e0h, *reinterpret_cast<__half2*>(&wA.y), a43_0);
        a01_1 = __hfma2(e0h, *reinterpret_cast<__half2*>(&wA.z), a01_1);
        a43_1 = __hfma2(e0h, *reinterpret_cast<__half2*>(&wA.w), a43_1);
        a01_0 = __hfma2(e1h, *reinterpret_cast<__half2*>(&wB.x), a01_0);
        a43_0 = __hfma2(e1h, *reinterpret_cast<__half2*>(&wB.y), a43_0);
        a01_1 = __hfma2(e1h, *reinterpret_cast<__half2*>(&wB.z), a01_1);
        a43_1 = __hfma2(e1h, *reinterpret_cast<__half2*>(&wB.w), a43_1);
    }
    uint2 ps;
    ps.x = h2bits(__halves2half2(__low2half(a01_0), __low2half(a43_0)));
    ps.y = h2bits(__halves2half2(__low2half(a01_1), __low2half(a43_1)));
    *(uint2*)(dst_s + (size_t)i * 16 + j0) = ps;
    *(unsigned*)(&dst_d[(size_t)i * 16 + j0]) =
        h2bits(__halves2half2(__high2half(a01_0), __high2half(a01_1)));
    *(unsigned*)(&dst_3[(size_t)i * 16 + j0]) =
        h2bits(__halves2half2(__high2half(a43_0), __high2half(a43_1)));
}

// ---------------- encoders (fused with first-conv projections) ----------------
__global__ void __launch_bounds__(256) k_enc_atm(
        const int* __restrict__ xatm,
        const float* __restrict__ W1, const float* __restrict__ b1,
        const float* __restrict__ W2, const float* __restrict__ b2,
        const float* __restrict__ lg, const float* __restrict__ lb,
        const float* __restrict__ Wg0, const float* __restrict__ bg0) {
    __shared__ uint4 swh[128];
    __shared__ float swb[32];
    load_wpack(swh, swb, Wg0, bg0);
    __syncthreads();
    Slot s = make_slot();
    float w2c[16];
    #pragma unroll
    for (int k = 0; k < 16; k++) w2c[k] = W2[k * 16 + s.j];
    float b1j = b1[s.j], b2j = b2[s.j], gj = lg[s.j], bj = lb[s.j];
    for (int a = s.slot; a < N_ATM; a += s.stride) {
        int sp = xatm[a];
        float h = siluf_(W1[sp * 16 + s.j] + b1j);
        float z = b2j;
        #pragma unroll
        for (int k = 0; k < 16; k++)
            z += __shfl_sync(0xffffffffu, h, s.grp | k) * w2c[k];
        float v = ln16(z, gj, bj);
        g_h_atm[a * 16 + s.j] = v;
        proj_store(v, s, swh, swb, g_aps, g_apd, g_ap3, a);
    }
}

__global__ void __launch_bounds__(256) k_enc_bnd(
        const float* __restrict__ xb,
        const float* __restrict__ W1, const float* __restrict__ b1,
        const float* __restrict__ W2, const float* __restrict__ b2,
        const float* __restrict__ lg, const float* __restrict__ lb,
        const float* __restrict__ Wa0, const float* __restrict__ ba0) {
    __shared__ uint4 swh[128];
    __shared__ float swb[32];
    load_wpack(swh, swb, Wa0, ba0);
    __syncthreads();
    Slot s = make_slot();
    float w1c[16], w2c[16];
    #pragma unroll
    for (int k = 0; k < 16; k++) { w1c[k] = W1[k * 16 + s.j]; w2c[k] = W2[k * 16 + s.j]; }
    float b1j = b1[s.j], b2j = b2[s.j], gj = lg[s.j], bj = lb[s.j];
    const float nrm = sqrtf(2.0f / 5.0f);
    for (int e = s.slot; e < N_BND; e += s.stride) {
        float xx = xb[e] + 1e-5f;
        float f = nrm * sinf((float)(s.j + 1) * PI_F * xx * (1.0f / 5.0f)) / xx;
        float h = b1j;
        #pragma unroll
        for (int k = 0; k < 16; k++)
            h += __shfl_sync(0xffffffffu, f, s.grp | k) * w1c[k];
        h = siluf_(h);
        float z = b2j;
        #pragma unroll
        for (int k = 0; k < 16; k++)
            z += __shfl_sync(0xffffffffu, h, s.grp | k) * w2c[k];
        float v = ln16(z, gj, bj);
        g_h_bnd[e * 16 + s.j] = v;
        proj_store(v, s, swh, swb, g_bps, g_bpd, g_bp3, e);
    }
}

// ---------------- A-graph edge phase, conv 0: fused angle encoder (8-lane) ----
// smem: swe1[m*64+..] fp16 W1 sets 2/3; swe2 same for W2; sw2h conv W2 pack
__global__ void __launch_bounds__(256) k_edge_A_first(
        const int* __restrict__ src, const int* __restrict__ dst,
        const float* __restrict__ xang, const int* __restrict__ mask,
        const float* __restrict__ W1, const float* __restrict__ b1,
        const float* __restrict__ W2, const float* __restrict__ b2,
        const float* __restrict__ lg, const float* __restrict__ lb,
        const float* __restrict__ W, const float* __restrict__ ln) {
    __shared__ uint2 swe1[128];
    __shared__ uint2 swe2[128];
    __shared__ uint2 sw2h[64];
    load_w2h_at(swe1, W1 + 2 * 256, 0);
    load_w2h_at(swe1, W1 + 3 * 256, 64);
    load_w2h_at(swe2, W2 + 2 * 256, 0);
    load_w2h_at(swe2, W2 + 3 * 256, 64);
    load_w2h(sw2h, W + 2 * 256);
    __syncthreads();
    Slot8 s = make_slot8();
    int j0 = 2 * s.jj;
    // encoder per-channel params for both branches
    float b1b0 = b1[32 + j0], b1b1 = b1[33 + j0], b1d0 = b1[48 + j0], b1d1 = b1[49 + j0];
    float b2b0 = b2[32 + j0], b2b1 = b2[33 + j0], b2d0 = b2[48 + j0], b2d1 = b2[49 + j0];
    float lgb0 = lg[32 + j0], lgb1 = lg[33 + j0], lgd0 = lg[48 + j0], lgd1 = lg[49 + j0];
    float lbb0 = lb[32 + j0], lbb1 = lb[33 + j0], lbd0 = lb[48 + j0], lbd1 = lb[49 + j0];
    const float cb0 = (float)j0 * (PI_F / 15.0f), cb1 = (float)(j0 + 1) * (PI_F / 15.0f);
    const float cd0 = -PI_F + (float)j0 * (2.0f * PI_F / 15.0f);
    const float cd1 = -PI_F + (float)(j0 + 1) * (2.0f * PI_F / 15.0f);
    const float gamb = 15.0f / PI_F, gamd = 7.5f / PI_F;
    // conv LN params
    float ge0 = ln[32 + j0], ge1 = ln[33 + j0], be0 = ln[48 + j0], be1 = ln[49 + j0];
    for (int ed = s.slot; ed < N_ANG; ed += s.stride) {
        int si = src[ed], di = dst[ed];
        float x = xang[ed];
        bool m = mask[ed] != 0;
        int mo = m ? 64 : 0;
        float t0 = m ? gamd * (x - cd0) : gamb * (x - cb0);
        float t1 = m ? gamd * (x - cd1) : gamb * (x - cb1);
        unsigned fu = packh2(__expf(-t0 * t0), __expf(-t1 * t1));
        float h0 = m ? b1d0 : b1b0, h1 = m ? b1d1 : b1b1;
        mv8(h0, h1, fu, swe1 + mo, s.g8, s.jj);
        unsigned hu = packh2(siluf_(h0), siluf_(h1));
        float z20 = m ? b2d0 : b2b0, z21 = m ? b2d1 : b2b1;
        mv8(z20, z21, hu, swe2 + mo, s.g8, s.jj);
        float2 evl = ln8pair(z20, z21, m ? lgd0 : lgb0, m ? lgd1 : lgb1,
                             m ? lbd0 : lbb0, m ? lbd1 : lbb1);
        unsigned evu = packh2(evl.x, evl.y);
        // --- conv edge ---
        uint2 pv = *(const uint2*)(g_bps + (size_t)si * 16 + j0);
        unsigned pdu = *(const unsigned*)(&g_bpd[(size_t)di * 16 + j0]);
        float2 pa = h2f2(pv.x), pb = h2f2(pv.y), p1 = h2f2(pdu);
        float z0 = pa.x + p1.x, z1 = pb.x + p1.y;
        mv8(z0, z1, evu, sw2h, s.g8, s.jj);
        float sig0 = sigmoidf_(z0), sig1 = sigmoidf_(z1);
        red_pair8(g_accA, di, s.jj,
                  packh2(sig0 * pa.y, sig0), packh2(sig1 * pb.y, sig1));
        float2 evf = h2f2(evu);
        float2 l = ln8pair(z0, z1, ge0, ge1, be0, be1);
        *(unsigned*)(&g_h_ang[(size_t)ed * 16 + j0]) =
            packh2(evf.x + siluf_(l.x), evf.y + siluf_(l.y));
    }
}

// ---------------- A-graph edge phase, conv 1/2 (8-lane; fp16 W2 pack) ----------
__global__ void __launch_bounds__(256) k_edge_A(
        const int* __restrict__ src, const int* __restrict__ dst,
        const float* __restrict__ W, const float* __restrict__ ln, int write_e) {
    __shared__ uint2 sw2h[64];
    load_w2h(sw2h, W + 512);
    __syncthreads();
    Slot8 s = make_slot8();
    int j0 = 2 * s.jj;
    float ge0 = ln[32 + j0], ge1 = ln[33 + j0], be0 = ln[48 + j0], be1 = ln[49 + j0];
    for (int ed = s.slot; ed < N_ANG; ed += s.stride) {
        int si = src[ed], di = dst[ed];
        unsigned evu = *(const unsigned*)(&g_h_ang[(size_t)ed * 16 + j0]);
        uint2 pv = *(const uint2*)(g_bps + (size_t)si * 16 + j0);
        unsigned pdu = *(const unsigned*)(&g_bpd[(size_t)di * 16 + j0]);
        float2 pa = h2f2(pv.x), pb = h2f2(pv.y), p1 = h2f2(pdu);
        float z0 = pa.x + p1.x, z1 = pb.x + p1.y;
        mv8(z0, z1, evu, sw2h, s.g8, s.jj);
        float sig0 = sigmoidf_(z0), sig1 = sigmoidf_(z1);
        red_pair8(g_accA, di, s.jj,
                  packh2(sig0 * pa.y, sig0), packh2(sig1 * pb.y, sig1));
        if (write_e) {
            float2 evf = h2f2(evu);
            float2 l = ln8pair(z0, z1, ge0, ge1, be0, be1);
            *(unsigned*)(&g_h_ang[(size_t)ed * 16 + j0]) =
                packh2(evf.x + siluf_(l.x), evf.y + siluf_(l.y));
        }
    }
}

// ---------------- G-graph edge phase with fused A-node update (8-lane) ----------
__global__ void __launch_bounds__(256) k_edge_G(
        const int* __restrict__ src, const int* __restrict__ dst,
        const float* __restrict__ Wg, const float* __restrict__ lnG,
        const float* __restrict__ lnA,
        const float* __restrict__ Wnext, const float* __restrict__ bnext) {
    __shared__ uint4 swh[128];
    __shared__ float swb[32];
    __shared__ uint2 sw2h[64];
    bool has_next = (Wnext != nullptr);
    load_w2h(sw2h, Wg + 512);
    if (has_next) load_wpack(swh, swb, Wnext, bnext);
    __syncthreads();
    Slot8 s = make_slot8();
    int j0 = 2 * s.jj;
    float ge0 = lnG[32 + j0], ge1 = lnG[33 + j0], be0 = lnG[48 + j0], be1 = lnG[49 + j0];
    float gn0 = lnA[j0], gn1 = lnA[j0 + 1], bn0 = lnA[16 + j0], bn1 = lnA[17 + j0];
    for (int ed = s.slot; ed < N_BND; ed += s.stride) {
        int si = src[ed], di = dst[ed];
        // --- fused A-node update for bond ed ---
        uint2 au = *(const uint2*)(g_accA + (size_t)ed * 16 + j0);
        float2 a0 = h2f2(au.x), a1 = h2f2(au.y);
        float2 p3 = h2f2(*(const unsigned*)(&g_bp3[(size_t)ed * 16 + j0]));
        float u0 = p3.x + a0.x / (a0.y + 1e-5f);
        float u1 = p3.y + a1.x / (a1.y + 1e-5f);
        float2 xv = *(const float2*)(g_h_bnd + (size_t)ed * 16 + j0);
        float2 l = ln8pair(u0, u1, gn0, gn1, bn0, bn1);
        float ev0 = xv.x + siluf_(l.x), ev1 = xv.y + siluf_(l.y);
        *(uint2*)(g_accA + (size_t)ed * 16 + j0) = make_uint2(0u, 0u);
        // --- G edge ---
        uint2 pv = *(const uint2*)(g_aps + (size_t)si * 16 + j0);
        unsigned pdu = *(const unsigned*)(&g_apd[(size_t)di * 16 + j0]);
        float2 pa = h2f2(pv.x), pb = h2f2(pv.y), p1 = h2f2(pdu);
        float z0 = pa.x + p1.x, z1 = pb.x + p1.y;
        #pragma unroll
        for (int t = 0; t < 8; t++) {
            float e0 = __shfl_sync(0xffffffffu, ev0, s.g8 | t);
            float e1 = __shfl_sync(0xffffffffu, ev1, s.g8 | t);
            uint2 w = sw2h[t * 8 + s.jj];
            float2 f0 = h2f2(w.x);
            float2 f1 = h2f2(w.y);
            z0 += e0 * f0.x + e1 * f1.x;
            z1 += e0 * f0.y + e1 * f1.y;
        }
        float sig0 = sigmoidf_(z0), sig1 = sigmoidf_(z1);
        red_pair8(g_accG, di, s.jj,
                  packh2(sig0 * pa.y, sig0), packh2(sig1 * pb.y, sig1));
        if (has_next) {
            float2 le = ln8pair(z0, z1, ge0, ge1, be0, be1);
            float en0 = ev0 + siluf_(le.x), en1 = ev1 + siluf_(le.y);
            *(float2*)(g_h_bnd + (size_t)ed * 16 + j0) = make_float2(en0, en1);
            proj_store8(en0, en1, s, swh, swb, g_bps, g_bpd, g_bp3, ed);
        }
    }
}

// ---------------- G-graph node phase (16-lane; zero accG; next-G proj; pool) ----
__global__ void __launch_bounds__(256) k_node_G(
        const float* __restrict__ ln,
        const float* __restrict__ Wnext, const float* __restrict__ bnext,
        const int* __restrict__ batch, int is_last) {
    __shared__ uint4 swh[128];
    __shared__ float swb[32];
    bool has_next = (Wnext != nullptr);
    if (has_next) {
        load_wpack(swh, swb, Wnext, bnext);
        __syncthreads();
    }
    Slot s = make_slot();
    float gn = ln[s.j], bn = ln[16 + s.j];
    for (int i = s.slot; i < N_ATM; i += s.stride) {
        float2 ah = h2f2(g_accG[(size_t)i * 16 + s.j]);
        float xv = g_h_atm[(size_t)i * 16 + s.j];
        float u = __half2float(g_ap3[(size_t)i * 16 + s.j]) + ah.x / (ah.y + 1e-5f);
        float xn = xv + siluf_(ln16(u, gn, bn));
        g_accG[(size_t)i * 16 + s.j] = 0u;
        if (is_last) {
            atomicAdd(&g_pooled[batch[i] * 16 + s.j], xn);
        } else {
            g_h_atm[(size_t)i * 16 + s.j] = xn;
            proj_store(xn, s, swh, swb, g_aps, g_apd, g_ap3, i);
        }
    }
}

// ---------------- head (also re-zeroes pooled for next replay) ----------------
__global__ void k_head(const float* __restrict__ fp,
                       const float* __restrict__ l1W, const float* __restrict__ l1b,
                       const float* __restrict__ l2W, const float* __restrict__ l2b,
                       float* __restrict__ out) {
    int g = threadIdx.x;  // one block of 256
    float p[16];
    #pragma unroll
    for (int i = 0; i < 16; i++) p[i] = g_pooled[g * 16 + i];
    float f0 = fp[2 * g], f1 = fp[2 * g + 1];
    float acc = l2b[0];
    #pragma unroll
    for (int jo = 0; jo < 16; jo++) {
        float h = l1b[jo];
        #pragma unroll
        for (int i = 0; i < 16; i++) h += p[i] * l1W[i * 16 + jo];
        h += f0 * l1W[16 * 16 + jo] + f1 * l1W[17 * 16 + jo];
        h = (h > 0.0f) ? h : 0.01f * h;
        acc += h * l2W[jo];
    }
    out[g] = acc;
    #pragma unroll
    for (int i = 0; i < 16; i++) g_pooled[g * 16 + i] = 0.0f;
}

// ---------------- launch ----------------
extern "C" void kernel_launch(void* const* d_in, const int* in_sizes, int n_in,
                              void* d_out, int out_size) {
    const int*   x_atm = (const int*)d_in[0];
    const float* x_bnd = (const float*)d_in[1];
    const float* x_ang = (const float*)d_in[2];
    const int*   mask  = (const int*)d_in[3];
    const int*   eG    = (const int*)d_in[4];
    const int*   eA    = (const int*)d_in[5];
    const int*   batch = (const int*)d_in[6];
    const float* fp    = (const float*)d_in[7];
    const float* W1    = (const float*)d_in[8];
    const float* b1    = (const float*)d_in[9];
    const float* W2    = (const float*)d_in[10];
    const float* b2    = (const float*)d_in[11];
    const float* lg    = (const float*)d_in[12];
    const float* lb    = (const float*)d_in[13];
    const float* cW    = (const float*)d_in[14];  // [3,2,5,16,16]
    const float* cb    = (const float*)d_in[15];  // [3,2,2,16]
    const float* cln   = (const float*)d_in[16];  // [3,2,2,2,16]
    const float* l1W   = (const float*)d_in[17];
    const float* l1b   = (const float*)d_in[18];
    const float* l2W   = (const float*)d_in[19];
    const float* l2b   = (const float*)d_in[20];
    float* out = (float*)d_out;

    #define WA(c)  (cW  + ((c) * 2 + 0) * 5 * 256)
    #define BA(c)  (cb  + ((c) * 2 + 0) * 32)
    #define LNA(c) (cln + ((c) * 2 + 0) * 64)
    #define WG(c)  (cW  + ((c) * 2 + 1) * 5 * 256)
    #define BG(c)  (cb  + ((c) * 2 + 1) * 32)
    #define LNG(c) (cln + ((c) * 2 + 1) * 64)

    k_enc_atm<<<512, 256>>>(x_atm, W1 + 0 * 256, b1 + 0 * 16, W2 + 0 * 256, b2 + 0 * 16,
                            lg + 0 * 16, lb + 0 * 16, WG(0), BG(0));
    k_enc_bnd<<<2048, 256>>>(x_bnd, W1 + 1 * 256, b1 + 1 * 16, W2 + 1 * 256, b2 + 1 * 16,
                             lg + 1 * 16, lb + 1 * 16, WA(0), BA(0));

    for (int c = 0; c < 3; c++) {
        if (c == 0) {
            k_edge_A_first<<<8192, 256>>>(eA, eA + N_ANG, x_ang, mask,
                                          W1, b1, W2, b2, lg, lb, WA(0), LNA(0));
        } else {
            k_edge_A<<<8192, 256>>>(eA, eA + N_ANG, WA(c), LNA(c), (c < 2) ? 1 : 0);
        }

        const float* WnA = (c < 2) ? WA(c + 1) : nullptr;
        const float* bnA = (c < 2) ? BA(c + 1) : nullptr;
        k_edge_G<<<8192, 256>>>(eG, eG + N_BND, WG(c), LNG(c), LNA(c), WnA, bnA);

        const float* WnG = (c < 2) ? WG(c + 1) : nullptr;
        const float* bnG = (c < 2) ? BG(c + 1) : nullptr;
        k_node_G<<<512, 256>>>(LNG(c), WnG, bnG, batch, (c == 2) ? 1 : 0);
    }

    k_head<<<1, 256>>>(fp, l1W, l1b, l2W, l2b, out);
}

// round 16
// speedup vs baseline: 1.3998x; 1.0041x over previous
#include <cuda_runtime.h>
#include <cuda_fp16.h>

#define DIM 16
#define N_ATM 131072
#define N_BND 1048576
#define N_ANG 2097152
#define N_GRAPHS 256
#define PI_F 3.14159265358979323846f

// ---------------- scratch (device globals; zero-init; invariants restored each replay) ----
__device__ float    g_h_atm[N_ATM * DIM];
__device__ float    g_h_bnd[N_BND * DIM];
__device__ __half   g_h_ang[N_ANG * DIM];   // fp16 storage (post-LN, O(1) values)
__device__ unsigned g_accA[N_BND * DIM];    // half2(num,den); zeroed by edge_G
__device__ unsigned g_accG[N_ATM * DIM];    // half2(num,den); zeroed by node_G
__device__ unsigned g_bps[N_BND * DIM];     // bond src-proj half2(p0,p4)
__device__ __half   g_bpd[N_BND * DIM];     // bond dst-proj p1
__device__ __half   g_bp3[N_BND * DIM];     // bond self-proj p3 = x@W3 + b1
__device__ unsigned g_aps[N_ATM * DIM];     // atom src-proj half2(p0,p4)
__device__ __half   g_apd[N_ATM * DIM];     // atom dst-proj p1
__device__ __half   g_ap3[N_ATM * DIM];     // atom self-proj p3
__device__ float    g_pooled[N_GRAPHS * DIM];

// ---------------- helpers ----------------
__device__ __forceinline__ float sigmoidf_(float x) { return 1.0f / (1.0f + __expf(-x)); }
__device__ __forceinline__ float siluf_(float x)    { return x / (1.0f + __expf(-x)); }
__device__ __forceinline__ unsigned h2bits(__half2 h) { return *reinterpret_cast<unsigned*>(&h); }
__device__ __forceinline__ float2 h2f2(unsigned u) {
    return __half22float2(*reinterpret_cast<__half2*>(&u));
}
__device__ __forceinline__ unsigned packh2(float a, float b) {
    return h2bits(__floats2half2_rn(a, b));
}
__device__ __forceinline__ __half2 dup_lo(unsigned u) {
    return __low2half2(*reinterpret_cast<__half2*>(&u));
}
__device__ __forceinline__ __half2 dup_hi(unsigned u) {
    return __high2half2(*reinterpret_cast<__half2*>(&u));
}

// ---- 16-lane helpers (encoders / node_G) ----
__device__ __forceinline__ float ln16(float x, float g, float b) {
    float s = x, q = x * x;
    #pragma unroll
    for (int off = 8; off; off >>= 1) {
        s += __shfl_xor_sync(0xffffffffu, s, off);
        q += __shfl_xor_sync(0xffffffffu, q, off);
    }
    float mu  = s * (1.0f / 16.0f);
    float var = q * (1.0f / 16.0f) - mu * mu;
    return (x - mu) * rsqrtf(var + 1e-5f) * g + b;
}

struct Slot { int j, grp, lane, slot, stride; };
__device__ __forceinline__ Slot make_slot() {
    Slot s;
    int t = blockIdx.x * blockDim.x + threadIdx.x;
    s.lane = t & 31;
    s.j = s.lane & 15;
    s.grp = s.lane & 16;
    s.slot = ((t >> 5) << 1) + (s.grp >> 4);
    s.stride = ((gridDim.x * blockDim.x) >> 5) << 1;
    return s;
}

// ---- 8-lane helpers: 2 channels per lane ----
struct Slot8 { int jj, g8, slot, stride; };
__device__ __forceinline__ Slot8 make_slot8() {
    Slot8 s;
    int t = blockIdx.x * blockDim.x + threadIdx.x;
    int lane = t & 31;
    s.jj = lane & 7;
    s.g8 = lane & 24;
    s.slot = ((t >> 5) << 2) + (lane >> 3);
    s.stride = ((gridDim.x * blockDim.x) >> 5) << 2;
    return s;
}

__device__ __forceinline__ float2 ln8pair(float x0, float x1, float g0, float g1,
                                          float b0, float b1) {
    float s = x0 + x1, q = x0 * x0 + x1 * x1;
    #pragma unroll
    for (int off = 4; off; off >>= 1) {
        s += __shfl_xor_sync(0xffffffffu, s, off);
        q += __shfl_xor_sync(0xffffffffu, q, off);
    }
    float mu  = s * (1.0f / 16.0f);
    float var = q * (1.0f / 16.0f) - mu * mu;
    float r = rsqrtf(var + 1e-5f);
    return make_float2((x0 - mu) * r * g0 + b0, (x1 - mu) * r * g1 + b1);
}

__device__ __forceinline__ void red_pair8(unsigned* base, int node, int jj,
                                          unsigned a0, unsigned a1) {
    unsigned b0 = __shfl_xor_sync(0xffffffffu, a0, 1);
    unsigned b1 = __shfl_xor_sync(0xffffffffu, a1, 1);
    if ((jj & 1) == 0) {
        unsigned* p = base + (size_t)node * 16 + 2 * jj;
        asm volatile("red.global.add.noftz.v4.f16x2 [%0], {%1, %2, %3, %4};"
                     :: "l"(p), "r"(a0), "r"(a1), "r"(b0), "r"(b1) : "memory");
    }
}

// ---- fp16 projection weight pack ----
// swh[k*8 + jj] = uint4{ h2(W0[k][j0],W1[k][j0]), h2(W4[k][j0],W3[k][j0]),
//                        h2(W0[k][j1],W1[k][j1]), h2(W4[k][j1],W3[k][j1]) }
__device__ __forceinline__ void load_wpack(uint4* swh, float* swb,
                                           const float* W, const float* b) {
    const float* W0 = W;
    const float* W1 = W + 256;
    const float* W4 = W + 4 * 256;
    const float* W3 = W + 3 * 256;
    for (int i = threadIdx.x; i < 160; i += blockDim.x) {
        if (i < 128) {
            int k = i >> 3, j0 = (i & 7) * 2;
            uint4 u;
            u.x = packh2(W0[k * 16 + j0],     W1[k * 16 + j0]);
            u.y = packh2(W4[k * 16 + j0],     W3[k * 16 + j0]);
            u.z = packh2(W0[k * 16 + j0 + 1], W1[k * 16 + j0 + 1]);
            u.w = packh2(W4[k * 16 + j0 + 1], W3[k * 16 + j0 + 1]);
            swh[i] = u;
        } else {
            swb[i - 128] = b[i - 128];
        }
    }
}

// fp16 16x16 matvec pack (8-lane)
__device__ __forceinline__ void load_w2h_at(uint2* p, const float* M, int base_i) {
    for (int i = threadIdx.x; i < 64; i += blockDim.x) {
        int t = i >> 3, j0 = (i & 7) * 2;
        uint2 u;
        u.x = packh2(M[(2 * t) * 16 + j0],     M[(2 * t) * 16 + j0 + 1]);
        u.y = packh2(M[(2 * t + 1) * 16 + j0], M[(2 * t + 1) * 16 + j0 + 1]);
        p[base_i + i] = u;
    }
}
__device__ __forceinline__ void load_w2h(uint2* p, const float* M) { load_w2h_at(p, M, 0); }

// 8-lane 16x16 matvec step: acc += shuffled-pair @ packed weights (1 SHFL/t)
__device__ __forceinline__ void mv8(float& z0, float& z1, unsigned vu, const uint2* p,
                                    int g8, int jj) {
    #pragma unroll
    for (int t = 0; t < 8; t++) {
        unsigned eu = __shfl_sync(0xffffffffu, vu, g8 | t);
        float2 e = h2f2(eu);
        uint2 w = p[t * 8 + jj];
        float2 f0 = h2f2(w.x);
        float2 f1 = h2f2(w.y);
        z0 += e.x * f0.x + e.y * f1.x;
        z1 += e.x * f0.y + e.y * f1.y;
    }
}

// 16-lane projection: HFMA2 accumulation
__device__ __forceinline__ void proj_store(float v, const Slot& s, const uint4* swh,
                                           const float* swb,
                                           unsigned* dst_s, __half* dst_d, __half* dst_3,
                                           int i) {
    __half2 a01 = __floats2half2_rn(swb[s.j], 0.0f);
    __half2 a43 = __floats2half2_rn(0.0f, swb[16 + s.j]);
    int odd = s.j & 1;
    #pragma unroll
    for (int k = 0; k < 16; k++) {
        float a = __shfl_sync(0xffffffffu, v, s.grp | k);
        __half2 ah = __float2half2_rn(a);
        uint4 w = swh[k * 8 + (s.j >> 1)];
        unsigned w01 = odd ? w.z : w.x;
        unsigned w43 = odd ? w.w : w.y;
        a01 = __hfma2(ah, *reinterpret_cast<__half2*>(&w01), a01);
        a43 = __hfma2(ah, *reinterpret_cast<__half2*>(&w43), a43);
    }
    dst_s[(size_t)i * 16 + s.j] = h2bits(__halves2half2(__low2half(a01), __low2half(a43)));
    dst_d[(size_t)i * 16 + s.j] = __high2half(a01);
    dst_3[(size_t)i * 16 + s.j] = __high2half(a43);
}

// 8-lane projection: packed-shuffle (1 SHFL + 2 dup per t) + HFMA2
__device__ __forceinline__ void proj_store8(unsigned vu, const Slot8& s,
                                            const uint4* swh, const float* swb,
                                            unsigned* dst_s, __half* dst_d, __half* dst_3,
                                            int i) {
    int j0 = 2 * s.jj;
    __half2 a01_0 = __floats2half2_rn(swb[j0], 0.0f);
    __half2 a43_0 = __floats2half2_rn(0.0f, swb[16 + j0]);
    __half2 a01_1 = __floats2half2_rn(swb[j0 + 1], 0.0f);
    __half2 a43_1 = __floats2half2_rn(0.0f, swb[17 + j0]);
    #pragma unroll
    for (int t = 0; t < 8; t++) {
        unsigned eu = __shfl_sync(0xffffffffu, vu, s.g8 | t);
        __half2 e0h = dup_lo(eu);
        __half2 e1h = dup_hi(eu);
        uint4 wA = swh[(2 * t) * 8 + s.jj];
        uint4 wB = swh[(2 * t + 1) * 8 + s.jj];
        a01_0 = __hfma2(e0h, *reinterpret_cast<__half2*>(&wA.x), a01_0);
        a43_0 = __hfma2(e0h, *reinterpret_cast<__half2*>(&wA.y), a43_0);
        a01_1 = __hfma2(e0h, *reinterpret_cast<__half2*>(&wA.z), a01_1);
        a43_1 = __hfma2(e0h, *reinterpret_cast<__half2*>(&wA.w), a43_1);
        a01_0 = __hfma2(e1h, *reinterpret_cast<__half2*>(&wB.x), a01_0);
        a43_0 = __hfma2(e1h, *reinterpret_cast<__half2*>(&wB.y), a43_0);
        a01_1 = __hfma2(e1h, *reinterpret_cast<__half2*>(&wB.z), a01_1);
        a43_1 = __hfma2(e1h, *reinterpret_cast<__half2*>(&wB.w), a43_1);
    }
    uint2 ps;
    ps.x = h2bits(__halves2half2(__low2half(a01_0), __low2half(a43_0)));
    ps.y = h2bits(__halves2half2(__low2half(a01_1), __low2half(a43_1)));
    *(uint2*)(dst_s + (size_t)i * 16 + j0) = ps;
    *(unsigned*)(&dst_d[(size_t)i * 16 + j0]) =
        h2bits(__halves2half2(__high2half(a01_0), __high2half(a01_1)));
    *(unsigned*)(&dst_3[(size_t)i * 16 + j0]) =
        h2bits(__halves2half2(__high2half(a43_0), __high2half(a43_1)));
}

// ---------------- encoders (fused with first-conv projections) ----------------
__global__ void __launch_bounds__(256) k_enc_atm(
        const int* __restrict__ xatm,
        const float* __restrict__ W1, const float* __restrict__ b1,
        const float* __restrict__ W2, const float* __restrict__ b2,
        const float* __restrict__ lg, const float* __restrict__ lb,
        const float* __restrict__ Wg0, const float* __restrict__ bg0) {
    __shared__ uint4 swh[128];
    __shared__ float swb[32];
    load_wpack(swh, swb, Wg0, bg0);
    __syncthreads();
    Slot s = make_slot();
    float w2c[16];
    #pragma unroll
    for (int k = 0; k < 16; k++) w2c[k] = W2[k * 16 + s.j];
    float b1j = b1[s.j], b2j = b2[s.j], gj = lg[s.j], bj = lb[s.j];
    for (int a = s.slot; a < N_ATM; a += s.stride) {
        int sp = xatm[a];
        float h = siluf_(W1[sp * 16 + s.j] + b1j);
        float z = b2j;
        #pragma unroll
        for (int k = 0; k < 16; k++)
            z += __shfl_sync(0xffffffffu, h, s.grp | k) * w2c[k];
        float v = ln16(z, gj, bj);
        g_h_atm[a * 16 + s.j] = v;
        proj_store(v, s, swh, swb, g_aps, g_apd, g_ap3, a);
    }
}

__global__ void __launch_bounds__(256) k_enc_bnd(
        const float* __restrict__ xb,
        const float* __restrict__ W1, const float* __restrict__ b1,
        const float* __restrict__ W2, const float* __restrict__ b2,
        const float* __restrict__ lg, const float* __restrict__ lb,
        const float* __restrict__ Wa0, const float* __restrict__ ba0) {
    __shared__ uint4 swh[128];
    __shared__ float swb[32];
    load_wpack(swh, swb, Wa0, ba0);
    __syncthreads();
    Slot s = make_slot();
    float w1c[16], w2c[16];
    #pragma unroll
    for (int k = 0; k < 16; k++) { w1c[k] = W1[k * 16 + s.j]; w2c[k] = W2[k * 16 + s.j]; }
    float b1j = b1[s.j], b2j = b2[s.j], gj = lg[s.j], bj = lb[s.j];
    const float nrm = sqrtf(2.0f / 5.0f);
    for (int e = s.slot; e < N_BND; e += s.stride) {
        float xx = xb[e] + 1e-5f;
        float f = nrm * sinf((float)(s.j + 1) * PI_F * xx * (1.0f / 5.0f)) / xx;
        float h = b1j;
        #pragma unroll
        for (int k = 0; k < 16; k++)
            h += __shfl_sync(0xffffffffu, f, s.grp | k) * w1c[k];
        h = siluf_(h);
        float z = b2j;
        #pragma unroll
        for (int k = 0; k < 16; k++)
            z += __shfl_sync(0xffffffffu, h, s.grp | k) * w2c[k];
        float v = ln16(z, gj, bj);
        g_h_bnd[e * 16 + s.j] = v;
        proj_store(v, s, swh, swb, g_bps, g_bpd, g_bp3, e);
    }
}

// ---------------- A-graph edge phase, conv 0: fused angle encoder (8-lane) ----
__global__ void __launch_bounds__(256) k_edge_A_first(
        const int* __restrict__ src, const int* __restrict__ dst,
        const float* __restrict__ xang, const int* __restrict__ mask,
        const float* __restrict__ W1, const float* __restrict__ b1,
        const float* __restrict__ W2, const float* __restrict__ b2,
        const float* __restrict__ lg, const float* __restrict__ lb,
        const float* __restrict__ W, const float* __restrict__ ln) {
    __shared__ uint2 swe1[128];
    __shared__ uint2 swe2[128];
    __shared__ uint2 sw2h[64];
    load_w2h_at(swe1, W1 + 2 * 256, 0);
    load_w2h_at(swe1, W1 + 3 * 256, 64);
    load_w2h_at(swe2, W2 + 2 * 256, 0);
    load_w2h_at(swe2, W2 + 3 * 256, 64);
    load_w2h(sw2h, W + 2 * 256);
    __syncthreads();
    Slot8 s = make_slot8();
    int j0 = 2 * s.jj;
    float b1b0 = b1[32 + j0], b1b1 = b1[33 + j0], b1d0 = b1[48 + j0], b1d1 = b1[49 + j0];
    float b2b0 = b2[32 + j0], b2b1 = b2[33 + j0], b2d0 = b2[48 + j0], b2d1 = b2[49 + j0];
    float lgb0 = lg[32 + j0], lgb1 = lg[33 + j0], lgd0 = lg[48 + j0], lgd1 = lg[49 + j0];
    float lbb0 = lb[32 + j0], lbb1 = lb[33 + j0], lbd0 = lb[48 + j0], lbd1 = lb[49 + j0];
    const float cb0 = (float)j0 * (PI_F / 15.0f), cb1 = (float)(j0 + 1) * (PI_F / 15.0f);
    const float cd0 = -PI_F + (float)j0 * (2.0f * PI_F / 15.0f);
    const float cd1 = -PI_F + (float)(j0 + 1) * (2.0f * PI_F / 15.0f);
    const float gamb = 15.0f / PI_F, gamd = 7.5f / PI_F;
    float ge0 = ln[32 + j0], ge1 = ln[33 + j0], be0 = ln[48 + j0], be1 = ln[49 + j0];
    for (int ed = s.slot; ed < N_ANG; ed += s.stride) {
        int si = src[ed], di = dst[ed];
        float x = xang[ed];
        bool m = mask[ed] != 0;
        int mo = m ? 64 : 0;
        float t0 = m ? gamd * (x - cd0) : gamb * (x - cb0);
        float t1 = m ? gamd * (x - cd1) : gamb * (x - cb1);
        unsigned fu = packh2(__expf(-t0 * t0), __expf(-t1 * t1));
        float h0 = m ? b1d0 : b1b0, h1 = m ? b1d1 : b1b1;
        mv8(h0, h1, fu, swe1 + mo, s.g8, s.jj);
        unsigned hu = packh2(siluf_(h0), siluf_(h1));
        float z20 = m ? b2d0 : b2b0, z21 = m ? b2d1 : b2b1;
        mv8(z20, z21, hu, swe2 + mo, s.g8, s.jj);
        float2 evl = ln8pair(z20, z21, m ? lgd0 : lgb0, m ? lgd1 : lgb1,
                             m ? lbd0 : lbb0, m ? lbd1 : lbb1);
        unsigned evu = packh2(evl.x, evl.y);
        uint2 pv = *(const uint2*)(g_bps + (size_t)si * 16 + j0);
        unsigned pdu = *(const unsigned*)(&g_bpd[(size_t)di * 16 + j0]);
        float2 pa = h2f2(pv.x), pb = h2f2(pv.y), p1 = h2f2(pdu);
        float z0 = pa.x + p1.x, z1 = pb.x + p1.y;
        mv8(z0, z1, evu, sw2h, s.g8, s.jj);
        float sig0 = sigmoidf_(z0), sig1 = sigmoidf_(z1);
        red_pair8(g_accA, di, s.jj,
                  packh2(sig0 * pa.y, sig0), packh2(sig1 * pb.y, sig1));
        float2 evf = h2f2(evu);
        float2 l = ln8pair(z0, z1, ge0, ge1, be0, be1);
        *(unsigned*)(&g_h_ang[(size_t)ed * 16 + j0]) =
            packh2(evf.x + siluf_(l.x), evf.y + siluf_(l.y));
    }
}

// ---------------- A-graph edge phase, conv 1/2 (8-lane; fp16 W2 pack) ----------
__global__ void __launch_bounds__(256) k_edge_A(
        const int* __restrict__ src, const int* __restrict__ dst,
        const float* __restrict__ W, const float* __restrict__ ln, int write_e) {
    __shared__ uint2 sw2h[64];
    load_w2h(sw2h, W + 512);
    __syncthreads();
    Slot8 s = make_slot8();
    int j0 = 2 * s.jj;
    float ge0 = ln[32 + j0], ge1 = ln[33 + j0], be0 = ln[48 + j0], be1 = ln[49 + j0];
    for (int ed = s.slot; ed < N_ANG; ed += s.stride) {
        int si = src[ed], di = dst[ed];
        unsigned evu = *(const unsigned*)(&g_h_ang[(size_t)ed * 16 + j0]);
        uint2 pv = *(const uint2*)(g_bps + (size_t)si * 16 + j0);
        unsigned pdu = *(const unsigned*)(&g_bpd[(size_t)di * 16 + j0]);
        float2 pa = h2f2(pv.x), pb = h2f2(pv.y), p1 = h2f2(pdu);
        float z0 = pa.x + p1.x, z1 = pb.x + p1.y;
        mv8(z0, z1, evu, sw2h, s.g8, s.jj);
        float sig0 = sigmoidf_(z0), sig1 = sigmoidf_(z1);
        red_pair8(g_accA, di, s.jj,
                  packh2(sig0 * pa.y, sig0), packh2(sig1 * pb.y, sig1));
        if (write_e) {
            float2 evf = h2f2(evu);
            float2 l = ln8pair(z0, z1, ge0, ge1, be0, be1);
            *(unsigned*)(&g_h_ang[(size_t)ed * 16 + j0]) =
                packh2(evf.x + siluf_(l.x), evf.y + siluf_(l.y));
        }
    }
}

// ---------------- G-graph edge phase with fused A-node update (8-lane, packed shuffles) ----
__global__ void __launch_bounds__(256) k_edge_G(
        const int* __restrict__ src, const int* __restrict__ dst,
        const float* __restrict__ Wg, const float* __restrict__ lnG,
        const float* __restrict__ lnA,
        const float* __restrict__ Wnext, const float* __restrict__ bnext) {
    __shared__ uint4 swh[128];
    __shared__ float swb[32];
    __shared__ uint2 sw2h[64];
    bool has_next = (Wnext != nullptr);
    load_w2h(sw2h, Wg + 512);
    if (has_next) load_wpack(swh, swb, Wnext, bnext);
    __syncthreads();
    Slot8 s = make_slot8();
    int j0 = 2 * s.jj;
    float ge0 = lnG[32 + j0], ge1 = lnG[33 + j0], be0 = lnG[48 + j0], be1 = lnG[49 + j0];
    float gn0 = lnA[j0], gn1 = lnA[j0 + 1], bn0 = lnA[16 + j0], bn1 = lnA[17 + j0];
    for (int ed = s.slot; ed < N_BND; ed += s.stride) {
        int si = src[ed], di = dst[ed];
        // --- fused A-node update for bond ed ---
        uint2 au = *(const uint2*)(g_accA + (size_t)ed * 16 + j0);
        float2 a0 = h2f2(au.x), a1 = h2f2(au.y);
        float2 p3 = h2f2(*(const unsigned*)(&g_bp3[(size_t)ed * 16 + j0]));
        float u0 = p3.x + a0.x / (a0.y + 1e-5f);
        float u1 = p3.y + a1.x / (a1.y + 1e-5f);
        float2 xv = *(const float2*)(g_h_bnd + (size_t)ed * 16 + j0);
        float2 l = ln8pair(u0, u1, gn0, gn1, bn0, bn1);
        float ev0 = xv.x + siluf_(l.x), ev1 = xv.y + siluf_(l.y);
        unsigned evu = packh2(ev0, ev1);
        *(uint2*)(g_accA + (size_t)ed * 16 + j0) = make_uint2(0u, 0u);
        // --- G edge (packed-shuffle matvec) ---
        uint2 pv = *(const uint2*)(g_aps + (size_t)si * 16 + j0);
        unsigned pdu = *(const unsigned*)(&g_apd[(size_t)di * 16 + j0]);
        float2 pa = h2f2(pv.x), pb = h2f2(pv.y), p1 = h2f2(pdu);
        float z0 = pa.x + p1.x, z1 = pb.x + p1.y;
        mv8(z0, z1, evu, sw2h, s.g8, s.jj);
        float sig0 = sigmoidf_(z0), sig1 = sigmoidf_(z1);
        red_pair8(g_accG, di, s.jj,
                  packh2(sig0 * pa.y, sig0), packh2(sig1 * pb.y, sig1));
        if (has_next) {
            float2 le = ln8pair(z0, z1, ge0, ge1, be0, be1);
            float en0 = ev0 + siluf_(le.x), en1 = ev1 + siluf_(le.y);
            *(float2*)(g_h_bnd + (size_t)ed * 16 + j0) = make_float2(en0, en1);
            proj_store8(packh2(en0, en1), s, swh, swb, g_bps, g_bpd, g_bp3, ed);
        }
    }
}

// ---------------- G-graph node phase (16-lane; zero accG; next-G proj; pool) ----
__global__ void __launch_bounds__(256) k_node_G(
        const float* __restrict__ ln,
        const float* __restrict__ Wnext, const float* __restrict__ bnext,
        const int* __restrict__ batch, int is_last) {
    __shared__ uint4 swh[128];
    __shared__ float swb[32];
    bool has_next = (Wnext != nullptr);
    if (has_next) {
        load_wpack(swh, swb, Wnext, bnext);
        __syncthreads();
    }
    Slot s = make_slot();
    float gn = ln[s.j], bn = ln[16 + s.j];
    for (int i = s.slot; i < N_ATM; i += s.stride) {
        float2 ah = h2f2(g_accG[(size_t)i * 16 + s.j]);
        float xv = g_h_atm[(size_t)i * 16 + s.j];
        float u = __half2float(g_ap3[(size_t)i * 16 + s.j]) + ah.x / (ah.y + 1e-5f);
        float xn = xv + siluf_(ln16(u, gn, bn));
        g_accG[(size_t)i * 16 + s.j] = 0u;
        if (is_last) {
            atomicAdd(&g_pooled[batch[i] * 16 + s.j], xn);
        } else {
            g_h_atm[(size_t)i * 16 + s.j] = xn;
            proj_store(xn, s, swh, swb, g_aps, g_apd, g_ap3, i);
        }
    }
}

// ---------------- head (also re-zeroes pooled for next replay) ----------------
__global__ void k_head(const float* __restrict__ fp,
                       const float* __restrict__ l1W, const float* __restrict__ l1b,
                       const float* __restrict__ l2W, const float* __restrict__ l2b,
                       float* __restrict__ out) {
    int g = threadIdx.x;  // one block of 256
    float p[16];
    #pragma unroll
    for (int i = 0; i < 16; i++) p[i] = g_pooled[g * 16 + i];
    float f0 = fp[2 * g], f1 = fp[2 * g + 1];
    float acc = l2b[0];
    #pragma unroll
    for (int jo = 0; jo < 16; jo++) {
        float h = l1b[jo];
        #pragma unroll
        for (int i = 0; i < 16; i++) h += p[i] * l1W[i * 16 + jo];
        h += f0 * l1W[16 * 16 + jo] + f1 * l1W[17 * 16 + jo];
        h = (h > 0.0f) ? h : 0.01f * h;
        acc += h * l2W[jo];
    }
    out[g] = acc;
    #pragma unroll
    for (int i = 0; i < 16; i++) g_pooled[g * 16 + i] = 0.0f;
}

// ---------------- launch ----------------
extern "C" void kernel_launch(void* const* d_in, const int* in_sizes, int n_in,
                              void* d_out, int out_size) {
    const int*   x_atm = (const int*)d_in[0];
    const float* x_bnd = (const float*)d_in[1];
    const float* x_ang = (const float*)d_in[2];
    const int*   mask  = (const int*)d_in[3];
    const int*   eG    = (const int*)d_in[4];
    const int*   eA    = (const int*)d_in[5];
    const int*   batch = (const int*)d_in[6];
    const float* fp    = (const float*)d_in[7];
    const float* W1    = (const float*)d_in[8];
    const float* b1    = (const float*)d_in[9];
    const float* W2    = (const float*)d_in[10];
    const float* b2    = (const float*)d_in[11];
    const float* lg    = (const float*)d_in[12];
    const float* lb    = (const float*)d_in[13];
    const float* cW    = (const float*)d_in[14];  // [3,2,5,16,16]
    const float* cb    = (const float*)d_in[15];  // [3,2,2,16]
    const float* cln   = (const float*)d_in[16];  // [3,2,2,2,16]
    const float* l1W   = (const float*)d_in[17];
    const float* l1b   = (const float*)d_in[18];
    const float* l2W   = (const float*)d_in[19];
    const float* l2b   = (const float*)d_in[20];
    float* out = (float*)d_out;

    #define WA(c)  (cW  + ((c) * 2 + 0) * 5 * 256)
    #define BA(c)  (cb  + ((c) * 2 + 0) * 32)
    #define LNA(c) (cln + ((c) * 2 + 0) * 64)
    #define WG(c)  (cW  + ((c) * 2 + 1) * 5 * 256)
    #define BG(c)  (cb  + ((c) * 2 + 1) * 32)
    #define LNG(c) (cln + ((c) * 2 + 1) * 64)

    k_enc_atm<<<512, 256>>>(x_atm, W1 + 0 * 256, b1 + 0 * 16, W2 + 0 * 256, b2 + 0 * 16,
                            lg + 0 * 16, lb + 0 * 16, WG(0), BG(0));
    k_enc_bnd<<<2048, 256>>>(x_bnd, W1 + 1 * 256, b1 + 1 * 16, W2 + 1 * 256, b2 + 1 * 16,
                             lg + 1 * 16, lb + 1 * 16, WA(0), BA(0));

    for (int c = 0; c < 3; c++) {
        if (c == 0) {
            k_edge_A_first<<<8192, 256>>>(eA, eA + N_ANG, x_ang, mask,
                                          W1, b1, W2, b2, lg, lb, WA(0), LNA(0));
        } else {
            k_edge_A<<<8192, 256>>>(eA, eA + N_ANG, WA(c), LNA(c), (c < 2) ? 1 : 0);
        }

        const float* WnA = (c < 2) ? WA(c + 1) : nullptr;
        const float* bnA = (c < 2) ? BA(c + 1) : nullptr;
        k_edge_G<<<8192, 256>>>(eG, eG + N_BND, WG(c), LNG(c), LNA(c), WnA, bnA);

        const float* WnG = (c < 2) ? WG(c + 1) : nullptr;
        const float* bnG = (c < 2) ? BG(c + 1) : nullptr;
        k_node_G<<<512, 256>>>(LNG(c), WnG, bnG, batch, (c == 2) ? 1 : 0);
    }

    k_head<<<1, 256>>>(fp, l1W, l1b, l2W, l2b, out);
}

// round 17
// speedup vs baseline: 1.4220x; 1.0158x over previous
#include <cuda_runtime.h>
#include <cuda_fp16.h>

#define DIM 16
#define N_ATM 131072
#define N_BND 1048576
#define N_ANG 2097152
#define N_GRAPHS 256
#define PI_F 3.14159265358979323846f

// ---------------- scratch (device globals; zero-init; invariants restored each replay) ----
__device__ float    g_h_atm[N_ATM * DIM];
__device__ float    g_h_bnd[N_BND * DIM];
__device__ __half   g_h_ang[N_ANG * DIM];   // fp16 storage (post-LN, O(1) values)
__device__ unsigned g_accA[N_BND * DIM];    // half2(num,den); zeroed by edge_G
__device__ unsigned g_accG[N_ATM * DIM];    // half2(num,den); zeroed by node_G
__device__ unsigned g_bps[N_BND * DIM];     // bond src-proj half2(p0,p4)
__device__ __half   g_bpd[N_BND * DIM];     // bond dst-proj p1
__device__ __half   g_bp3[N_BND * DIM];     // bond self-proj p3 = x@W3 + b1
__device__ unsigned g_aps[N_ATM * DIM];     // atom src-proj half2(p0,p4)
__device__ __half   g_apd[N_ATM * DIM];     // atom dst-proj p1
__device__ __half   g_ap3[N_ATM * DIM];     // atom self-proj p3
__device__ float    g_pooled[N_GRAPHS * DIM];

// ---------------- helpers ----------------
__device__ __forceinline__ float sigmoidf_(float x) { return 1.0f / (1.0f + __expf(-x)); }
__device__ __forceinline__ float siluf_(float x)    { return x / (1.0f + __expf(-x)); }
__device__ __forceinline__ unsigned h2bits(__half2 h) { return *reinterpret_cast<unsigned*>(&h); }
__device__ __forceinline__ float2 h2f2(unsigned u) {
    return __half22float2(*reinterpret_cast<__half2*>(&u));
}
__device__ __forceinline__ unsigned packh2(float a, float b) {
    return h2bits(__floats2half2_rn(a, b));
}
__device__ __forceinline__ __half2 dup_lo(unsigned u) {
    return __low2half2(*reinterpret_cast<__half2*>(&u));
}
__device__ __forceinline__ __half2 dup_hi(unsigned u) {
    return __high2half2(*reinterpret_cast<__half2*>(&u));
}

// ---- 16-lane helpers (encoders / node_G) ----
__device__ __forceinline__ float ln16(float x, float g, float b) {
    float s = x, q = x * x;
    #pragma unroll
    for (int off = 8; off; off >>= 1) {
        s += __shfl_xor_sync(0xffffffffu, s, off);
        q += __shfl_xor_sync(0xffffffffu, q, off);
    }
    float mu  = s * (1.0f / 16.0f);
    float var = q * (1.0f / 16.0f) - mu * mu;
    return (x - mu) * rsqrtf(var + 1e-5f) * g + b;
}

struct Slot { int j, grp, lane, slot, stride; };
__device__ __forceinline__ Slot make_slot() {
    Slot s;
    int t = blockIdx.x * blockDim.x + threadIdx.x;
    s.lane = t & 31;
    s.j = s.lane & 15;
    s.grp = s.lane & 16;
    s.slot = ((t >> 5) << 1) + (s.grp >> 4);
    s.stride = ((gridDim.x * blockDim.x) >> 5) << 1;
    return s;
}

// ---- 8-lane helpers: 2 channels per lane ----
struct Slot8 { int jj, g8, slot, stride; };
__device__ __forceinline__ Slot8 make_slot8() {
    Slot8 s;
    int t = blockIdx.x * blockDim.x + threadIdx.x;
    int lane = t & 31;
    s.jj = lane & 7;
    s.g8 = lane & 24;
    s.slot = ((t >> 5) << 2) + (lane >> 3);
    s.stride = ((gridDim.x * blockDim.x) >> 5) << 2;
    return s;
}

__device__ __forceinline__ float2 ln8pair(float x0, float x1, float g0, float g1,
                                          float b0, float b1) {
    float s = x0 + x1, q = x0 * x0 + x1 * x1;
    #pragma unroll
    for (int off = 4; off; off >>= 1) {
        s += __shfl_xor_sync(0xffffffffu, s, off);
        q += __shfl_xor_sync(0xffffffffu, q, off);
    }
    float mu  = s * (1.0f / 16.0f);
    float var = q * (1.0f / 16.0f) - mu * mu;
    float r = rsqrtf(var + 1e-5f);
    return make_float2((x0 - mu) * r * g0 + b0, (x1 - mu) * r * g1 + b1);
}

__device__ __forceinline__ void red_pair8(unsigned* base, int node, int jj,
                                          unsigned a0, unsigned a1) {
    unsigned b0 = __shfl_xor_sync(0xffffffffu, a0, 1);
    unsigned b1 = __shfl_xor_sync(0xffffffffu, a1, 1);
    if ((jj & 1) == 0) {
        unsigned* p = base + (size_t)node * 16 + 2 * jj;
        asm volatile("red.global.add.noftz.v4.f16x2 [%0], {%1, %2, %3, %4};"
                     :: "l"(p), "r"(a0), "r"(a1), "r"(b0), "r"(b1) : "memory");
    }
}

// ---- fp16 projection weight pack ----
__device__ __forceinline__ void load_wpack(uint4* swh, float* swb,
                                           const float* W, const float* b) {
    const float* W0 = W;
    const float* W1 = W + 256;
    const float* W4 = W + 4 * 256;
    const float* W3 = W + 3 * 256;
    for (int i = threadIdx.x; i < 160; i += blockDim.x) {
        if (i < 128) {
            int k = i >> 3, j0 = (i & 7) * 2;
            uint4 u;
            u.x = packh2(W0[k * 16 + j0],     W1[k * 16 + j0]);
            u.y = packh2(W4[k * 16 + j0],     W3[k * 16 + j0]);
            u.z = packh2(W0[k * 16 + j0 + 1], W1[k * 16 + j0 + 1]);
            u.w = packh2(W4[k * 16 + j0 + 1], W3[k * 16 + j0 + 1]);
            swh[i] = u;
        } else {
            swb[i - 128] = b[i - 128];
        }
    }
}

// fp16 16x16 matvec pack (8-lane)
__device__ __forceinline__ void load_w2h_at(uint2* p, const float* M, int base_i) {
    for (int i = threadIdx.x; i < 64; i += blockDim.x) {
        int t = i >> 3, j0 = (i & 7) * 2;
        uint2 u;
        u.x = packh2(M[(2 * t) * 16 + j0],     M[(2 * t) * 16 + j0 + 1]);
        u.y = packh2(M[(2 * t + 1) * 16 + j0], M[(2 * t + 1) * 16 + j0 + 1]);
        p[base_i + i] = u;
    }
}
__device__ __forceinline__ void load_w2h(uint2* p, const float* M) { load_w2h_at(p, M, 0); }

// 8-lane 16x16 matvec step (1 SHFL/t)
__device__ __forceinline__ void mv8(float& z0, float& z1, unsigned vu, const uint2* p,
                                    int g8, int jj) {
    #pragma unroll
    for (int t = 0; t < 8; t++) {
        unsigned eu = __shfl_sync(0xffffffffu, vu, g8 | t);
        float2 e = h2f2(eu);
        uint2 w = p[t * 8 + jj];
        float2 f0 = h2f2(w.x);
        float2 f1 = h2f2(w.y);
        z0 += e.x * f0.x + e.y * f1.x;
        z1 += e.x * f0.y + e.y * f1.y;
    }
}

// 16-lane projection: HFMA2 accumulation
__device__ __forceinline__ void proj_store(float v, const Slot& s, const uint4* swh,
                                           const float* swb,
                                           unsigned* dst_s, __half* dst_d, __half* dst_3,
                                           int i) {
    __half2 a01 = __floats2half2_rn(swb[s.j], 0.0f);
    __half2 a43 = __floats2half2_rn(0.0f, swb[16 + s.j]);
    int odd = s.j & 1;
    #pragma unroll
    for (int k = 0; k < 16; k++) {
        float a = __shfl_sync(0xffffffffu, v, s.grp | k);
        __half2 ah = __float2half2_rn(a);
        uint4 w = swh[k * 8 + (s.j >> 1)];
        unsigned w01 = odd ? w.z : w.x;
        unsigned w43 = odd ? w.w : w.y;
        a01 = __hfma2(ah, *reinterpret_cast<__half2*>(&w01), a01);
        a43 = __hfma2(ah, *reinterpret_cast<__half2*>(&w43), a43);
    }
    dst_s[(size_t)i * 16 + s.j] = h2bits(__halves2half2(__low2half(a01), __low2half(a43)));
    dst_d[(size_t)i * 16 + s.j] = __high2half(a01);
    dst_3[(size_t)i * 16 + s.j] = __high2half(a43);
}

// 8-lane projection: packed-shuffle + HFMA2
__device__ __forceinline__ void proj_store8(unsigned vu, const Slot8& s,
                                            const uint4* swh, const float* swb,
                                            unsigned* dst_s, __half* dst_d, __half* dst_3,
                                            int i) {
    int j0 = 2 * s.jj;
    __half2 a01_0 = __floats2half2_rn(swb[j0], 0.0f);
    __half2 a43_0 = __floats2half2_rn(0.0f, swb[16 + j0]);
    __half2 a01_1 = __floats2half2_rn(swb[j0 + 1], 0.0f);
    __half2 a43_1 = __floats2half2_rn(0.0f, swb[17 + j0]);
    #pragma unroll
    for (int t = 0; t < 8; t++) {
        unsigned eu = __shfl_sync(0xffffffffu, vu, s.g8 | t);
        __half2 e0h = dup_lo(eu);
        __half2 e1h = dup_hi(eu);
        uint4 wA = swh[(2 * t) * 8 + s.jj];
        uint4 wB = swh[(2 * t + 1) * 8 + s.jj];
        a01_0 = __hfma2(e0h, *reinterpret_cast<__half2*>(&wA.x), a01_0);
        a43_0 = __hfma2(e0h, *reinterpret_cast<__half2*>(&wA.y), a43_0);
        a01_1 = __hfma2(e0h, *reinterpret_cast<__half2*>(&wA.z), a01_1);
        a43_1 = __hfma2(e0h, *reinterpret_cast<__half2*>(&wA.w), a43_1);
        a01_0 = __hfma2(e1h, *reinterpret_cast<__half2*>(&wB.x), a01_0);
        a43_0 = __hfma2(e1h, *reinterpret_cast<__half2*>(&wB.y), a43_0);
        a01_1 = __hfma2(e1h, *reinterpret_cast<__half2*>(&wB.z), a01_1);
        a43_1 = __hfma2(e1h, *reinterpret_cast<__half2*>(&wB.w), a43_1);
    }
    uint2 ps;
    ps.x = h2bits(__halves2half2(__low2half(a01_0), __low2half(a43_0)));
    ps.y = h2bits(__halves2half2(__low2half(a01_1), __low2half(a43_1)));
    *(uint2*)(dst_s + (size_t)i * 16 + j0) = ps;
    *(unsigned*)(&dst_d[(size_t)i * 16 + j0]) =
        h2bits(__halves2half2(__high2half(a01_0), __high2half(a01_1)));
    *(unsigned*)(&dst_3[(size_t)i * 16 + j0]) =
        h2bits(__halves2half2(__high2half(a43_0), __high2half(a43_1)));
}

// ---------------- encoders (fused with first-conv projections) ----------------
__global__ void __launch_bounds__(256) k_enc_atm(
        const int* __restrict__ xatm,
        const float* __restrict__ W1, const float* __restrict__ b1,
        const float* __restrict__ W2, const float* __restrict__ b2,
        const float* __restrict__ lg, const float* __restrict__ lb,
        const float* __restrict__ Wg0, const float* __restrict__ bg0) {
    __shared__ uint4 swh[128];
    __shared__ float swb[32];
    load_wpack(swh, swb, Wg0, bg0);
    __syncthreads();
    Slot s = make_slot();
    float w2c[16];
    #pragma unroll
    for (int k = 0; k < 16; k++) w2c[k] = W2[k * 16 + s.j];
    float b1j = b1[s.j], b2j = b2[s.j], gj = lg[s.j], bj = lb[s.j];
    for (int a = s.slot; a < N_ATM; a += s.stride) {
        int sp = xatm[a];
        float h = siluf_(W1[sp * 16 + s.j] + b1j);
        float z = b2j;
        #pragma unroll
        for (int k = 0; k < 16; k++)
            z += __shfl_sync(0xffffffffu, h, s.grp | k) * w2c[k];
        float v = ln16(z, gj, bj);
        g_h_atm[a * 16 + s.j] = v;
        proj_store(v, s, swh, swb, g_aps, g_apd, g_ap3, a);
    }
}

__global__ void __launch_bounds__(256) k_enc_bnd(
        const float* __restrict__ xb,
        const float* __restrict__ W1, const float* __restrict__ b1,
        const float* __restrict__ W2, const float* __restrict__ b2,
        const float* __restrict__ lg, const float* __restrict__ lb,
        const float* __restrict__ Wa0, const float* __restrict__ ba0) {
    __shared__ uint4 swh[128];
    __shared__ float swb[32];
    load_wpack(swh, swb, Wa0, ba0);
    __syncthreads();
    Slot s = make_slot();
    float w1c[16], w2c[16];
    #pragma unroll
    for (int k = 0; k < 16; k++) { w1c[k] = W1[k * 16 + s.j]; w2c[k] = W2[k * 16 + s.j]; }
    float b1j = b1[s.j], b2j = b2[s.j], gj = lg[s.j], bj = lb[s.j];
    const float nrm = sqrtf(2.0f / 5.0f);
    for (int e = s.slot; e < N_BND; e += s.stride) {
        float xx = xb[e] + 1e-5f;
        float f = nrm * sinf((float)(s.j + 1) * PI_F * xx * (1.0f / 5.0f)) / xx;
        float h = b1j;
        #pragma unroll
        for (int k = 0; k < 16; k++)
            h += __shfl_sync(0xffffffffu, f, s.grp | k) * w1c[k];
        h = siluf_(h);
        float z = b2j;
        #pragma unroll
        for (int k = 0; k < 16; k++)
            z += __shfl_sync(0xffffffffu, h, s.grp | k) * w2c[k];
        float v = ln16(z, gj, bj);
        g_h_bnd[e * 16 + s.j] = v;
        proj_store(v, s, swh, swb, g_bps, g_bpd, g_bp3, e);
    }
}

// ---------------- A-graph edge phase, conv 0: fused angle encoder (8-lane) ----
__global__ void __launch_bounds__(256) k_edge_A_first(
        const int* __restrict__ src, const int* __restrict__ dst,
        const float* __restrict__ xang, const int* __restrict__ mask,
        const float* __restrict__ W1, const float* __restrict__ b1,
        const float* __restrict__ W2, const float* __restrict__ b2,
        const float* __restrict__ lg, const float* __restrict__ lb,
        const float* __restrict__ W, const float* __restrict__ ln) {
    __shared__ uint2 swe1[128];
    __shared__ uint2 swe2[128];
    __shared__ uint2 sw2h[64];
    load_w2h_at(swe1, W1 + 2 * 256, 0);
    load_w2h_at(swe1, W1 + 3 * 256, 64);
    load_w2h_at(swe2, W2 + 2 * 256, 0);
    load_w2h_at(swe2, W2 + 3 * 256, 64);
    load_w2h(sw2h, W + 2 * 256);
    __syncthreads();
    Slot8 s = make_slot8();
    int j0 = 2 * s.jj;
    float b1b0 = b1[32 + j0], b1b1 = b1[33 + j0], b1d0 = b1[48 + j0], b1d1 = b1[49 + j0];
    float b2b0 = b2[32 + j0], b2b1 = b2[33 + j0], b2d0 = b2[48 + j0], b2d1 = b2[49 + j0];
    float lgb0 = lg[32 + j0], lgb1 = lg[33 + j0], lgd0 = lg[48 + j0], lgd1 = lg[49 + j0];
    float lbb0 = lb[32 + j0], lbb1 = lb[33 + j0], lbd0 = lb[48 + j0], lbd1 = lb[49 + j0];
    const float cb0 = (float)j0 * (PI_F / 15.0f), cb1 = (float)(j0 + 1) * (PI_F / 15.0f);
    const float cd0 = -PI_F + (float)j0 * (2.0f * PI_F / 15.0f);
    const float cd1 = -PI_F + (float)(j0 + 1) * (2.0f * PI_F / 15.0f);
    const float gamb = 15.0f / PI_F, gamd = 7.5f / PI_F;
    float ge0 = ln[32 + j0], ge1 = ln[33 + j0], be0 = ln[48 + j0], be1 = ln[49 + j0];
    for (int ed = s.slot; ed < N_ANG; ed += s.stride) {
        int si = src[ed], di = dst[ed];
        float x = xang[ed];
        bool m = mask[ed] != 0;
        int mo = m ? 64 : 0;
        float t0 = m ? gamd * (x - cd0) : gamb * (x - cb0);
        float t1 = m ? gamd * (x - cd1) : gamb * (x - cb1);
        unsigned fu = packh2(__expf(-t0 * t0), __expf(-t1 * t1));
        float h0 = m ? b1d0 : b1b0, h1 = m ? b1d1 : b1b1;
        mv8(h0, h1, fu, swe1 + mo, s.g8, s.jj);
        unsigned hu = packh2(siluf_(h0), siluf_(h1));
        float z20 = m ? b2d0 : b2b0, z21 = m ? b2d1 : b2b1;
        mv8(z20, z21, hu, swe2 + mo, s.g8, s.jj);
        float2 evl = ln8pair(z20, z21, m ? lgd0 : lgb0, m ? lgd1 : lgb1,
                             m ? lbd0 : lbb0, m ? lbd1 : lbb1);
        unsigned evu = packh2(evl.x, evl.y);
        uint2 pv = *(const uint2*)(g_bps + (size_t)si * 16 + j0);
        unsigned pdu = *(const unsigned*)(&g_bpd[(size_t)di * 16 + j0]);
        float2 pa = h2f2(pv.x), pb = h2f2(pv.y), p1 = h2f2(pdu);
        float z0 = pa.x + p1.x, z1 = pb.x + p1.y;
        mv8(z0, z1, evu, sw2h, s.g8, s.jj);
        float sig0 = sigmoidf_(z0), sig1 = sigmoidf_(z1);
        red_pair8(g_accA, di, s.jj,
                  packh2(sig0 * pa.y, sig0), packh2(sig1 * pb.y, sig1));
        float2 evf = h2f2(evu);
        float2 l = ln8pair(z0, z1, ge0, ge1, be0, be1);
        *(unsigned*)(&g_h_ang[(size_t)ed * 16 + j0]) =
            packh2(evf.x + siluf_(l.x), evf.y + siluf_(l.y));
    }
}

// ---------------- A-graph edge phase, conv 1/2 (8-lane; fp16 W2 pack) ----------
__global__ void __launch_bounds__(256) k_edge_A(
        const int* __restrict__ src, const int* __restrict__ dst,
        const float* __restrict__ W, const float* __restrict__ ln, int write_e) {
    __shared__ uint2 sw2h[64];
    load_w2h(sw2h, W + 512);
    __syncthreads();
    Slot8 s = make_slot8();
    int j0 = 2 * s.jj;
    float ge0 = ln[32 + j0], ge1 = ln[33 + j0], be0 = ln[48 + j0], be1 = ln[49 + j0];
    for (int ed = s.slot; ed < N_ANG; ed += s.stride) {
        int si = src[ed], di = dst[ed];
        unsigned evu = *(const unsigned*)(&g_h_ang[(size_t)ed * 16 + j0]);
        uint2 pv = *(const uint2*)(g_bps + (size_t)si * 16 + j0);
        unsigned pdu = *(const unsigned*)(&g_bpd[(size_t)di * 16 + j0]);
        float2 pa = h2f2(pv.x), pb = h2f2(pv.y), p1 = h2f2(pdu);
        float z0 = pa.x + p1.x, z1 = pb.x + p1.y;
        mv8(z0, z1, evu, sw2h, s.g8, s.jj);
        float sig0 = sigmoidf_(z0), sig1 = sigmoidf_(z1);
        red_pair8(g_accA, di, s.jj,
                  packh2(sig0 * pa.y, sig0), packh2(sig1 * pb.y, sig1));
        if (write_e) {
            float2 evf = h2f2(evu);
            float2 l = ln8pair(z0, z1, ge0, ge1, be0, be1);
            *(unsigned*)(&g_h_ang[(size_t)ed * 16 + j0]) =
                packh2(evf.x + siluf_(l.x), evf.y + siluf_(l.y));
        }
    }
}

// ---------------- G-graph edge phase with fused A-node update (8-lane) ----------
__global__ void __launch_bounds__(256) k_edge_G(
        const int* __restrict__ src, const int* __restrict__ dst,
        const float* __restrict__ Wg, const float* __restrict__ lnG,
        const float* __restrict__ lnA,
        const float* __restrict__ Wnext, const float* __restrict__ bnext) {
    __shared__ uint4 swh[128];
    __shared__ float swb[32];
    __shared__ uint2 sw2h[64];
    bool has_next = (Wnext != nullptr);
    load_w2h(sw2h, Wg + 512);
    if (has_next) load_wpack(swh, swb, Wnext, bnext);
    __syncthreads();
    Slot8 s = make_slot8();
    int j0 = 2 * s.jj;
    float ge0 = lnG[32 + j0], ge1 = lnG[33 + j0], be0 = lnG[48 + j0], be1 = lnG[49 + j0];
    float gn0 = lnA[j0], gn1 = lnA[j0 + 1], bn0 = lnA[16 + j0], bn1 = lnA[17 + j0];
    for (int ed = s.slot; ed < N_BND; ed += s.stride) {
        int si = src[ed], di = dst[ed];
        uint2 au = *(const uint2*)(g_accA + (size_t)ed * 16 + j0);
        float2 a0 = h2f2(au.x), a1 = h2f2(au.y);
        float2 p3 = h2f2(*(const unsigned*)(&g_bp3[(size_t)ed * 16 + j0]));
        float u0 = p3.x + a0.x / (a0.y + 1e-5f);
        float u1 = p3.y + a1.x / (a1.y + 1e-5f);
        float2 xv = *(const float2*)(g_h_bnd + (size_t)ed * 16 + j0);
        float2 l = ln8pair(u0, u1, gn0, gn1, bn0, bn1);
        float ev0 = xv.x + siluf_(l.x), ev1 = xv.y + siluf_(l.y);
        unsigned evu = packh2(ev0, ev1);
        *(uint2*)(g_accA + (size_t)ed * 16 + j0) = make_uint2(0u, 0u);
        uint2 pv = *(const uint2*)(g_aps + (size_t)si * 16 + j0);
        unsigned pdu = *(const unsigned*)(&g_apd[(size_t)di * 16 + j0]);
        float2 pa = h2f2(pv.x), pb = h2f2(pv.y), p1 = h2f2(pdu);
        float z0 = pa.x + p1.x, z1 = pb.x + p1.y;
        mv8(z0, z1, evu, sw2h, s.g8, s.jj);
        float sig0 = sigmoidf_(z0), sig1 = sigmoidf_(z1);
        red_pair8(g_accG, di, s.jj,
                  packh2(sig0 * pa.y, sig0), packh2(sig1 * pb.y, sig1));
        if (has_next) {
            float2 le = ln8pair(z0, z1, ge0, ge1, be0, be1);
            float en0 = ev0 + siluf_(le.x), en1 = ev1 + siluf_(le.y);
            *(float2*)(g_h_bnd + (size_t)ed * 16 + j0) = make_float2(en0, en1);
            proj_store8(packh2(en0, en1), s, swh, swb, g_bps, g_bpd, g_bp3, ed);
        }
    }
}

// ---------------- G-graph node phase (16-lane; zero accG; next-G proj; pool) ----
__global__ void __launch_bounds__(256) k_node_G(
        const float* __restrict__ ln,
        const float* __restrict__ Wnext, const float* __restrict__ bnext,
        const int* __restrict__ batch, int is_last) {
    __shared__ uint4 swh[128];
    __shared__ float swb[32];
    bool has_next = (Wnext != nullptr);
    if (has_next) {
        load_wpack(swh, swb, Wnext, bnext);
        __syncthreads();
    }
    Slot s = make_slot();
    float gn = ln[s.j], bn = ln[16 + s.j];
    for (int i = s.slot; i < N_ATM; i += s.stride) {
        float2 ah = h2f2(g_accG[(size_t)i * 16 + s.j]);
        float xv = g_h_atm[(size_t)i * 16 + s.j];
        float u = __half2float(g_ap3[(size_t)i * 16 + s.j]) + ah.x / (ah.y + 1e-5f);
        float xn = xv + siluf_(ln16(u, gn, bn));
        g_accG[(size_t)i * 16 + s.j] = 0u;
        if (is_last) {
            atomicAdd(&g_pooled[batch[i] * 16 + s.j], xn);
        } else {
            g_h_atm[(size_t)i * 16 + s.j] = xn;
            proj_store(xn, s, swh, swb, g_aps, g_apd, g_ap3, i);
        }
    }
}

// ---------------- head (also re-zeroes pooled for next replay) ----------------
__global__ void k_head(const float* __restrict__ fp,
                       const float* __restrict__ l1W, const float* __restrict__ l1b,
                       const float* __restrict__ l2W, const float* __restrict__ l2b,
                       float* __restrict__ out) {
    int g = threadIdx.x;  // one block of 256
    float p[16];
    #pragma unroll
    for (int i = 0; i < 16; i++) p[i] = g_pooled[g * 16 + i];
    float f0 = fp[2 * g], f1 = fp[2 * g + 1];
    float acc = l2b[0];
    #pragma unroll
    for (int jo = 0; jo < 16; jo++) {
        float h = l1b[jo];
        #pragma unroll
        for (int i = 0; i < 16; i++) h += p[i] * l1W[i * 16 + jo];
        h += f0 * l1W[16 * 16 + jo] + f1 * l1W[17 * 16 + jo];
        h = (h > 0.0f) ? h : 0.01f * h;
        acc += h * l2W[jo];
    }
    out[g] = acc;
    #pragma unroll
    for (int i = 0; i < 16; i++) g_pooled[g * 16 + i] = 0.0f;
}

// ---------------- launch (fork-join overlap: enc_atm / node_G on side stream) ----
extern "C" void kernel_launch(void* const* d_in, const int* in_sizes, int n_in,
                              void* d_out, int out_size) {
    const int*   x_atm = (const int*)d_in[0];
    const float* x_bnd = (const float*)d_in[1];
    const float* x_ang = (const float*)d_in[2];
    const int*   mask  = (const int*)d_in[3];
    const int*   eG    = (const int*)d_in[4];
    const int*   eA    = (const int*)d_in[5];
    const int*   batch = (const int*)d_in[6];
    const float* fp    = (const float*)d_in[7];
    const float* W1    = (const float*)d_in[8];
    const float* b1    = (const float*)d_in[9];
    const float* W2    = (const float*)d_in[10];
    const float* b2    = (const float*)d_in[11];
    const float* lg    = (const float*)d_in[12];
    const float* lb    = (const float*)d_in[13];
    const float* cW    = (const float*)d_in[14];  // [3,2,5,16,16]
    const float* cb    = (const float*)d_in[15];  // [3,2,2,16]
    const float* cln   = (const float*)d_in[16];  // [3,2,2,2,16]
    const float* l1W   = (const float*)d_in[17];
    const float* l1b   = (const float*)d_in[18];
    const float* l2W   = (const float*)d_in[19];
    const float* l2b   = (const float*)d_in[20];
    float* out = (float*)d_out;

    #define WA(c)  (cW  + ((c) * 2 + 0) * 5 * 256)
    #define BA(c)  (cb  + ((c) * 2 + 0) * 32)
    #define LNA(c) (cln + ((c) * 2 + 0) * 64)
    #define WG(c)  (cW  + ((c) * 2 + 1) * 5 * 256)
    #define BG(c)  (cb  + ((c) * 2 + 1) * 32)
    #define LNG(c) (cln + ((c) * 2 + 1) * 64)

    // side stream + events, created per call (kernel_launch runs only a few times;
    // host-side objects only — no device allocations)
    cudaStream_t s2;
    cudaStreamCreateWithFlags(&s2, cudaStreamNonBlocking);
    cudaEvent_t ev[6];
    for (int i = 0; i < 6; i++) cudaEventCreateWithFlags(&ev[i], cudaEventDisableTiming);

    // fork: enc_atm runs on s2, overlapping enc_bnd + edge_A_first on the main stream
    cudaEventRecord(ev[0], 0);
    cudaStreamWaitEvent(s2, ev[0], 0);
    k_enc_atm<<<512, 256, 0, s2>>>(x_atm, W1, b1, W2, b2, lg, lb, WG(0), BG(0));

    k_enc_bnd<<<2048, 256>>>(x_bnd, W1 + 256, b1 + 16, W2 + 256, b2 + 16,
                             lg + 16, lb + 16, WA(0), BA(0));
    k_edge_A_first<<<8192, 256>>>(eA, eA + N_ANG, x_ang, mask,
                                  W1, b1, W2, b2, lg, lb, WA(0), LNA(0));

    // join enc_atm before edge_G(0) (needs h_atm + atom projections)
    cudaEventRecord(ev[1], s2);
    cudaStreamWaitEvent(0, ev[1], 0);

    for (int c = 0; c < 3; c++) {
        const float* WnA = (c < 2) ? WA(c + 1) : nullptr;
        const float* bnA = (c < 2) ? BA(c + 1) : nullptr;
        k_edge_G<<<8192, 256>>>(eG, eG + N_BND, WG(c), LNG(c), LNA(c), WnA, bnA);

        const float* WnG = (c < 2) ? WG(c + 1) : nullptr;
        const float* bnG = (c < 2) ? BG(c + 1) : nullptr;
        if (c < 2) {
            // fork: node_G(c) on s2 (atom arrays) || edge_A(c+1) on main (bond/angle arrays)
            cudaEventRecord(ev[2 + c], 0);
            cudaStreamWaitEvent(s2, ev[2 + c], 0);
            k_node_G<<<512, 256, 0, s2>>>(LNG(c), WnG, bnG, batch, 0);
            k_edge_A<<<8192, 256>>>(eA, eA + N_ANG, WA(c + 1), LNA(c + 1),
                                    (c + 1 < 2) ? 1 : 0);
            // join before edge_G(c+1) (needs atom projections from node_G)
            cudaEventRecord(ev[4 + c], s2);
            cudaStreamWaitEvent(0, ev[4 + c], 0);
        } else {
            k_node_G<<<512, 256>>>(LNG(c), WnG, bnG, batch, 1);
        }
    }

    k_head<<<1, 256>>>(fp, l1W, l1b, l2W, l2b, out);
}